// round 7
// baseline (speedup 1.0000x reference)
#include <cuda_runtime.h>
#include <cuda_bf16.h>
#include <stdint.h>
#include <float.h>

// ---------------- problem constants ----------------
#define NB    4
#define NSEQ  4096
#define DIMX  1024
#define HEADS 16
#define DHEAD 64
#define MAG   128
#define BHN   (NB * HEADS)
#define SCALE 0.125f

// ---------------- scratch (device globals; no allocation) ----------------
__device__ float g_q[NB * HEADS * NSEQ * DHEAD];
__device__ float g_k[NB * HEADS * NSEQ * DHEAD];
__device__ float g_v[NB * HEADS * NSEQ * DHEAD];
__device__ float g_qa[NB * HEADS * NSEQ * MAG];
__device__ float g_ak[NB * HEADS * MAG * NSEQ];
__device__ float g_agent_part[8 * BHN * MAG * DHEAD];
__device__ float g_agent[BHN * MAG * DHEAD];
__device__ float g_maskf[NB * NSEQ];
__device__ float2 g_akstat[BHN * MAG];

__device__ __nv_bfloat16 g_xh[NB * NSEQ * DIMX];
__device__ __nv_bfloat16 g_xl[NB * NSEQ * DIMX];
__device__ __nv_bfloat16 g_wqkvh[3 * DIMX * DIMX];
__device__ __nv_bfloat16 g_wqkvl[3 * DIMX * DIMX];
__device__ __nv_bfloat16 g_wouth[DIMX * DIMX];
__device__ __nv_bfloat16 g_woutl[DIMX * DIMX];
__device__ __nv_bfloat16 g_midh[NB * NSEQ * DIMX];
__device__ __nv_bfloat16 g_midl[NB * NSEQ * DIMX];

// ---------------- PTX helpers ----------------
__device__ __forceinline__ uint32_t smem_u32(const void* p) {
    uint32_t a;
    asm("{ .reg .u64 t; cvta.to.shared.u64 t, %1; cvt.u32.u64 %0, t; }" : "=r"(a) : "l"(p));
    return a;
}
#define SMEM_SWIZZLE_128B(o) ((o) ^ (((o) >> 3) & 0x70))

__device__ __forceinline__ void cp_async16(uint32_t sa, const void* g) {
    asm volatile("cp.async.cg.shared.global [%0], [%1], 16;" :: "r"(sa), "l"(g));
}
#define CP_COMMIT() asm volatile("cp.async.commit_group;" ::: "memory")
#define CP_WAIT(n)  asm volatile("cp.async.wait_group %0;" :: "n"(n) : "memory")

__device__ __forceinline__ void ldsm_x4(uint32_t* r, uint32_t a) {
    asm volatile("ldmatrix.sync.aligned.m8n8.x4.shared.b16 {%0,%1,%2,%3}, [%4];"
                 : "=r"(r[0]), "=r"(r[1]), "=r"(r[2]), "=r"(r[3]) : "r"(a));
}
__device__ __forceinline__ void mma16816(float* c, const uint32_t* a, const uint32_t* b) {
    asm volatile("mma.sync.aligned.m16n8k16.row.col.f32.bf16.bf16.f32 "
                 "{%0,%1,%2,%3}, {%4,%5,%6,%7}, {%8,%9}, {%0,%1,%2,%3};"
                 : "+f"(c[0]), "+f"(c[1]), "+f"(c[2]), "+f"(c[3])
                 : "r"(a[0]), "r"(a[1]), "r"(a[2]), "r"(a[3]), "r"(b[0]), "r"(b[1]));
}

__device__ __forceinline__ float warp_max(float v) {
#pragma unroll
    for (int o = 16; o > 0; o >>= 1) v = fmaxf(v, __shfl_xor_sync(0xffffffffu, v, o));
    return v;
}
__device__ __forceinline__ float warp_sum(float v) {
#pragma unroll
    for (int o = 16; o > 0; o >>= 1) v += __shfl_xor_sync(0xffffffffu, v, o);
    return v;
}
__device__ __forceinline__ void split_hl(float v, __nv_bfloat16& h, __nv_bfloat16& l) {
    h = __float2bfloat16(v);
    l = __float2bfloat16(v - __bfloat162float(h));
}

// ---------------- mask dtype detection + expansion ----------------
__global__ void mask_expand_kernel(const void* __restrict__ mraw) {
    __shared__ int s_weird, s_off;
    const unsigned char* mb = (const unsigned char*)mraw;
    if (threadIdx.x == 0) { s_weird = 0; s_off = 0; }
    __syncthreads();
    int weird = 0, off = 0;
    for (int i = threadIdx.x; i < NB * NSEQ; i += blockDim.x) {
        unsigned char c = mb[i];
        if (c > 1) weird = 1;
        if (c != 0 && (i & 3)) off = 1;
    }
    if (weird) atomicOr(&s_weird, 1);
    if (off)   atomicOr(&s_off, 1);
    __syncthreads();
    int mode = s_weird ? 2 : (s_off ? 0 : 1);
    for (int i = threadIdx.x; i < NB * NSEQ; i += blockDim.x) {
        float v;
        if (mode == 0)      v = mb[i] ? 1.f : 0.f;
        else if (mode == 1) v = ((const int*)mraw)[i] ? 1.f : 0.f;
        else                v = (((const float*)mraw)[i] != 0.f) ? 1.f : 0.f;
        g_maskf[i] = v;
    }
}

// ---------------- fp32 -> bf16 hi/lo split ----------------
__global__ __launch_bounds__(256) void conv_split_kernel(const float* __restrict__ src,
                                                         __nv_bfloat16* __restrict__ h,
                                                         __nv_bfloat16* __restrict__ l, int n4) {
    int i = blockIdx.x * 256 + threadIdx.x;
    if (i >= n4) return;
    float4 v = reinterpret_cast<const float4*>(src)[i];
    __nv_bfloat16 h0, h1, h2, h3, l0, l1, l2, l3;
    split_hl(v.x, h0, l0); split_hl(v.y, h1, l1);
    split_hl(v.z, h2, l2); split_hl(v.w, h3, l3);
    reinterpret_cast<__nv_bfloat162*>(h)[i * 2]     = __nv_bfloat162(h0, h1);
    reinterpret_cast<__nv_bfloat162*>(h)[i * 2 + 1] = __nv_bfloat162(h2, h3);
    reinterpret_cast<__nv_bfloat162*>(l)[i * 2]     = __nv_bfloat162(l0, l1);
    reinterpret_cast<__nv_bfloat162*>(l)[i * 2 + 1] = __nv_bfloat162(l2, l3);
}

// ---------------- W[K,N] -> W^T[N,K] bf16 hi/lo ----------------
__global__ __launch_bounds__(256) void conv_wt_kernel(const float* __restrict__ W,
                                                      __nv_bfloat16* __restrict__ Th,
                                                      __nv_bfloat16* __restrict__ Tl,
                                                      int K, int N) {
    __shared__ float t[32][33];
    int bx = blockIdx.x * 32;
    int by = blockIdx.y * 32;
    int x = threadIdx.x & 31, y0 = threadIdx.x >> 5;
#pragma unroll
    for (int y = y0; y < 32; y += 8) t[y][x] = W[(size_t)(by + y) * N + bx + x];
    __syncthreads();
#pragma unroll
    for (int y = y0; y < 32; y += 8) {
        float v = t[x][y];
        __nv_bfloat16 h, l;
        split_hl(v, h, l);
        size_t o = (size_t)(bx + y) * K + by + x;
        Th[o] = h; Tl[o] = l;
    }
}

// ---------------- mma.sync bf16x3 GEMM, BK=32, 3-stage, 2 CTA/SM ----------------
// Stage layout: A-slab 128 rows x 128B, row r = [Ah[r][k0:k0+32) 64B | Al[...] 64B]; B-slab same.
#define ST_BYTES 32768                      // 2 slabs x 16KB
#define GT_SMEM  (1024 + 3 * ST_BYTES)      // pad + 3 stages = 99328

template <int MODE>
__global__ __launch_bounds__(256, 2) void gemm_mma_kernel(
    const __nv_bfloat16* __restrict__ Ah, const __nv_bfloat16* __restrict__ Al,
    const __nv_bfloat16* __restrict__ Bh, const __nv_bfloat16* __restrict__ Bl,
    float* __restrict__ out, int Kdim, int Nout) {
    extern __shared__ char dsm[];
    uint32_t sraw = smem_u32(dsm);
    uint32_t sbase = (sraw + 1023u) & ~1023u;

    const int tid = threadIdx.x;
    const int lane = tid & 31;
    const int wid = tid >> 5;
    const int wm = wid >> 2;
    const int wn = wid & 3;
    const int bm = blockIdx.y * 128;
    const int bn = blockIdx.x * 128;

    float acc[4][4][4];
#pragma unroll
    for (int i = 0; i < 4; i++)
#pragma unroll
        for (int j = 0; j < 4; j++)
#pragma unroll
            for (int v = 0; v < 4; v++) acc[i][j][v] = 0.f;

    const int nchunk = Kdim >> 5;          // BK = 32

    auto load_stage = [&](int c) {
        const int st = c % 3;
        const int k0 = c << 5;
        const uint32_t sb = sbase + st * ST_BYTES;
#pragma unroll
        for (int i = 0; i < 4; i++) {
            int u = tid + i * 256;          // 0..1023
            int r = u >> 3;
            int cb = (u & 7) << 4;          // 0..112 bytes
            const __nv_bfloat16* asrc = (cb < 64) ? Ah : Al;
            const __nv_bfloat16* bsrc = (cb < 64) ? Bh : Bl;
            int koff = (cb & 63) >> 1;
            uint32_t so = SMEM_SWIZZLE_128B(r * 128 + cb);
            cp_async16(sb + so,         asrc + (size_t)(bm + r) * Kdim + k0 + koff);
            cp_async16(sb + 16384 + so, bsrc + (size_t)(bn + r) * Kdim + k0 + koff);
        }
        CP_COMMIT();
    };

    load_stage(0);
    if (nchunk > 1) load_stage(1);
    if (nchunk > 2) load_stage(2);

    const int lrow = lane & 15;
    const int lksel = (lane >> 4) << 4;

    for (int c = 0; c < nchunk; c++) {
        if (c + 2 < nchunk)      { CP_WAIT(2); }
        else if (c + 1 < nchunk) { CP_WAIT(1); }
        else                     { CP_WAIT(0); }
        __syncthreads();
        const uint32_t sA = sbase + (c % 3) * ST_BYTES;
        const uint32_t sB = sA + 16384;
#pragma unroll
        for (int s = 0; s < 2; s++) {
            const int kb = s * 32 + lksel;       // hi half; lo at +64
            uint32_t af[4][4], bh2[4][2], bl2[4][2];
#pragma unroll
            for (int mf = 0; mf < 4; mf++) {
                int row = wm * 64 + mf * 16 + lrow;
                ldsm_x4(af[mf], sA + SMEM_SWIZZLE_128B(row * 128 + kb));
            }
#pragma unroll
            for (int g = 0; g < 2; g++) {
                int row = wn * 32 + g * 16 + lrow;
                uint32_t r[4];
                ldsm_x4(r, sB + SMEM_SWIZZLE_128B(row * 128 + kb));
                bh2[g * 2][0] = r[0]; bh2[g * 2][1] = r[2];
                bh2[g * 2 + 1][0] = r[1]; bh2[g * 2 + 1][1] = r[3];
                ldsm_x4(r, sB + SMEM_SWIZZLE_128B(row * 128 + kb + 64));
                bl2[g * 2][0] = r[0]; bl2[g * 2][1] = r[2];
                bl2[g * 2 + 1][0] = r[1]; bl2[g * 2 + 1][1] = r[3];
            }
#pragma unroll
            for (int mf = 0; mf < 4; mf++)
#pragma unroll
                for (int nf = 0; nf < 4; nf++) mma16816(acc[mf][nf], af[mf], bh2[nf]);
#pragma unroll
            for (int mf = 0; mf < 4; mf++)
#pragma unroll
                for (int nf = 0; nf < 4; nf++) mma16816(acc[mf][nf], af[mf], bl2[nf]);
            // reload A-lo into af regs
#pragma unroll
            for (int mf = 0; mf < 4; mf++) {
                int row = wm * 64 + mf * 16 + lrow;
                ldsm_x4(af[mf], sA + SMEM_SWIZZLE_128B(row * 128 + kb + 64));
            }
#pragma unroll
            for (int mf = 0; mf < 4; mf++)
#pragma unroll
                for (int nf = 0; nf < 4; nf++) mma16816(acc[mf][nf], af[mf], bh2[nf]);
        }
        __syncthreads();
        if (c + 3 < nchunk) load_stage(c + 3);
    }

#pragma unroll
    for (int mf = 0; mf < 4; mf++) {
        int r0 = bm + wm * 64 + mf * 16 + (lane >> 2);
#pragma unroll
        for (int nf = 0; nf < 4; nf++) {
            int col = bn + wn * 32 + nf * 8 + ((lane & 3) << 1);
            float* p0;
            float* p1;
            if (MODE == 1) {
                const int which = col >> 10;
                const int hh = (col >> 6) & 15;
                const int d0 = col & 63;
                float* dst = which == 0 ? g_q : (which == 1 ? g_k : g_v);
                const int b0 = r0 >> 12, n0 = r0 & 4095;
                const int b1 = (r0 + 8) >> 12, n1 = (r0 + 8) & 4095;
                p0 = &dst[(((size_t)(b0 * 16 + hh)) * 4096 + n0) * 64 + d0];
                p1 = &dst[(((size_t)(b1 * 16 + hh)) * 4096 + n1) * 64 + d0];
            } else {
                p0 = &out[(size_t)r0 * Nout + col];
                p1 = &out[(size_t)(r0 + 8) * Nout + col];
            }
            *reinterpret_cast<float2*>(p0) = make_float2(acc[mf][nf][0], acc[mf][nf][1]);
            *reinterpret_cast<float2*>(p1) = make_float2(acc[mf][nf][2], acc[mf][nf][3]);
        }
    }
}

// ---------------- qa_sim + fused softmax; conflict-free (4,+64) mapping ----------------
#define SIM_SMEM (2 * 64 * 128 * 4)   // 65536
__global__ __launch_bounds__(256) void qa_sim_softmax_kernel(const float* __restrict__ Agt) {
    extern __shared__ float s[];
    float (*Qs)[128] = reinterpret_cast<float(*)[128]>(s);
    float (*As)[128] = reinterpret_cast<float(*)[128]>(s + 64 * 128);
    const int tid = threadIdx.x;
    const int bh = blockIdx.y;
    const int h = bh & 15;
    const int bm = blockIdx.x * 128;
    const float* Q = g_q + (size_t)bh * (NSEQ * DHEAD);
    const float* A = Agt + (size_t)h * (MAG * DHEAD);
    const int tx = tid & 15, ty = tid >> 4;
    const int row = tid >> 2, kv = (tid & 3) << 2;
#pragma unroll
    for (int k0 = 0; k0 < 64; k0 += 16) {
#pragma unroll
        for (int s2 = 0; s2 < 2; s2++) {
            int r = row + s2 * 64;
            float4 a4 = *reinterpret_cast<const float4*>(&Q[(bm + r) * 64 + k0 + kv]);
            Qs[k0 + kv + 0][r] = a4.x; Qs[k0 + kv + 1][r] = a4.y;
            Qs[k0 + kv + 2][r] = a4.z; Qs[k0 + kv + 3][r] = a4.w;
            float4 b4 = *reinterpret_cast<const float4*>(&A[r * 64 + k0 + kv]);
            As[k0 + kv + 0][r] = b4.x * SCALE; As[k0 + kv + 1][r] = b4.y * SCALE;
            As[k0 + kv + 2][r] = b4.z * SCALE; As[k0 + kv + 3][r] = b4.w * SCALE;
        }
    }
    __syncthreads();
    float acc[8][8] = {};
#pragma unroll 8
    for (int kk = 0; kk < 64; kk++) {
        float4 ra0 = *reinterpret_cast<const float4*>(&Qs[kk][ty * 4]);
        float4 ra1 = *reinterpret_cast<const float4*>(&Qs[kk][ty * 4 + 64]);
        float4 rb0 = *reinterpret_cast<const float4*>(&As[kk][tx * 4]);
        float4 rb1 = *reinterpret_cast<const float4*>(&As[kk][tx * 4 + 64]);
        float ra[8] = {ra0.x, ra0.y, ra0.z, ra0.w, ra1.x, ra1.y, ra1.z, ra1.w};
        float rb[8] = {rb0.x, rb0.y, rb0.z, rb0.w, rb1.x, rb1.y, rb1.z, rb1.w};
#pragma unroll
        for (int i = 0; i < 8; i++)
#pragma unroll
            for (int j = 0; j < 8; j++) acc[i][j] = fmaf(ra[i], rb[j], acc[i][j]);
    }
#pragma unroll
    for (int i = 0; i < 8; i++) {
        float mx = acc[i][0];
#pragma unroll
        for (int j = 1; j < 8; j++) mx = fmaxf(mx, acc[i][j]);
#pragma unroll
        for (int o = 8; o > 0; o >>= 1) mx = fmaxf(mx, __shfl_xor_sync(0xffffffffu, mx, o));
        float sm = 0.f;
#pragma unroll
        for (int j = 0; j < 8; j++) { acc[i][j] = __expf(acc[i][j] - mx); sm += acc[i][j]; }
#pragma unroll
        for (int o = 8; o > 0; o >>= 1) sm += __shfl_xor_sync(0xffffffffu, sm, o);
        float inv = 1.f / sm;
        int ii = bm + ty * 4 + (i & 3) + (i >> 2) * 64;
        float* p = &g_qa[((size_t)bh * NSEQ + ii) * MAG + tx * 4];
        *reinterpret_cast<float4*>(p) =
            make_float4(acc[i][0] * inv, acc[i][1] * inv, acc[i][2] * inv, acc[i][3] * inv);
        *reinterpret_cast<float4*>(p + 64) =
            make_float4(acc[i][4] * inv, acc[i][5] * inv, acc[i][6] * inv, acc[i][7] * inv);
    }
}

// ---------------- ak_sim: conflict-free mapping + mask ----------------
__global__ __launch_bounds__(256) void ak_sim_kernel(const float* __restrict__ Agt) {
    extern __shared__ float s[];
    float (*As)[128] = reinterpret_cast<float(*)[128]>(s);
    float (*Ks)[128] = reinterpret_cast<float(*)[128]>(s + 64 * 128);
    const int tid = threadIdx.x;
    const int bh = blockIdx.y;
    const int b = bh >> 4, h = bh & 15;
    const int bn = blockIdx.x * 128;
    const float* A  = Agt + (size_t)h * (MAG * DHEAD);
    const float* Kt = g_k + (size_t)bh * (NSEQ * DHEAD);
    const int tx = tid & 15, ty = tid >> 4;
    const int row = tid >> 2, kv = (tid & 3) << 2;
#pragma unroll
    for (int k0 = 0; k0 < 64; k0 += 16) {
#pragma unroll
        for (int s2 = 0; s2 < 2; s2++) {
            int r = row + s2 * 64;
            float4 a4 = *reinterpret_cast<const float4*>(&A[r * 64 + k0 + kv]);
            As[k0 + kv + 0][r] = a4.x * SCALE; As[k0 + kv + 1][r] = a4.y * SCALE;
            As[k0 + kv + 2][r] = a4.z * SCALE; As[k0 + kv + 3][r] = a4.w * SCALE;
            float4 b4 = *reinterpret_cast<const float4*>(&Kt[(bn + r) * 64 + k0 + kv]);
            Ks[k0 + kv + 0][r] = b4.x; Ks[k0 + kv + 1][r] = b4.y;
            Ks[k0 + kv + 2][r] = b4.z; Ks[k0 + kv + 3][r] = b4.w;
        }
    }
    __syncthreads();
    float acc[8][8] = {};
#pragma unroll 8
    for (int kk = 0; kk < 64; kk++) {
        float4 ra0 = *reinterpret_cast<const float4*>(&As[kk][ty * 4]);
        float4 ra1 = *reinterpret_cast<const float4*>(&As[kk][ty * 4 + 64]);
        float4 rb0 = *reinterpret_cast<const float4*>(&Ks[kk][tx * 4]);
        float4 rb1 = *reinterpret_cast<const float4*>(&Ks[kk][tx * 4 + 64]);
        float ra[8] = {ra0.x, ra0.y, ra0.z, ra0.w, ra1.x, ra1.y, ra1.z, ra1.w};
        float rb[8] = {rb0.x, rb0.y, rb0.z, rb0.w, rb1.x, rb1.y, rb1.z, rb1.w};
#pragma unroll
        for (int i = 0; i < 8; i++)
#pragma unroll
            for (int j = 0; j < 8; j++) acc[i][j] = fmaf(ra[i], rb[j], acc[i][j]);
    }
    float4 mv0 = *reinterpret_cast<const float4*>(&g_maskf[b * NSEQ + bn + tx * 4]);
    float4 mv1 = *reinterpret_cast<const float4*>(&g_maskf[b * NSEQ + bn + tx * 4 + 64]);
    float m0[4] = {mv0.x, mv0.y, mv0.z, mv0.w};
    float m1[4] = {mv1.x, mv1.y, mv1.z, mv1.w};
#pragma unroll
    for (int i = 0; i < 8; i++) {
        int m = ty * 4 + (i & 3) + (i >> 2) * 64;
        float* p = &g_ak[((size_t)bh * MAG + m) * NSEQ + bn + tx * 4];
        float4 o0, o1;
        o0.x = m0[0] != 0.f ? acc[i][0] : -FLT_MAX;
        o0.y = m0[1] != 0.f ? acc[i][1] : -FLT_MAX;
        o0.z = m0[2] != 0.f ? acc[i][2] : -FLT_MAX;
        o0.w = m0[3] != 0.f ? acc[i][3] : -FLT_MAX;
        o1.x = m1[0] != 0.f ? acc[i][4] : -FLT_MAX;
        o1.y = m1[1] != 0.f ? acc[i][5] : -FLT_MAX;
        o1.z = m1[2] != 0.f ? acc[i][6] : -FLT_MAX;
        o1.w = m1[3] != 0.f ? acc[i][7] : -FLT_MAX;
        *reinterpret_cast<float4*>(p)      = o0;
        *reinterpret_cast<float4*>(p + 64) = o1;
    }
}

// ---------------- ak row stats ----------------
__global__ __launch_bounds__(256) void ak_stats_kernel() {
    const int row = blockIdx.x;
    const int t = threadIdx.x;
    const float* p = g_ak + (size_t)row * NSEQ;
    float4 v[4];
    float mx = -FLT_MAX;
#pragma unroll
    for (int i = 0; i < 4; i++) {
        v[i] = *reinterpret_cast<const float4*>(&p[t * 16 + i * 4]);
        mx = fmaxf(mx, fmaxf(fmaxf(v[i].x, v[i].y), fmaxf(v[i].z, v[i].w)));
    }
    __shared__ float red[8];
    int wid = t >> 5, lane = t & 31;
    float wm = warp_max(mx);
    if (lane == 0) red[wid] = wm;
    __syncthreads();
    float m = red[0];
#pragma unroll
    for (int i = 1; i < 8; i++) m = fmaxf(m, red[i]);
    float sacc = 0.f;
#pragma unroll
    for (int i = 0; i < 4; i++)
        sacc += __expf(v[i].x - m) + __expf(v[i].y - m) + __expf(v[i].z - m) + __expf(v[i].w - m);
    float ws = warp_sum(sacc);
    __syncthreads();
    if (lane == 0) red[wid] = ws;
    __syncthreads();
    if (t == 0) {
        float tot = 0.f;
#pragma unroll
        for (int i = 0; i < 8; i++) tot += red[i];
        g_akstat[row] = make_float2(m, 1.f / tot);
    }
}

// ---------------- fused exp-normalize + head mix (ak, in place) ----------------
__global__ __launch_bounds__(256) void mix_ak_exp_kernel(const float* __restrict__ Wm) {
    __shared__ float Ws[256];
    if (threadIdx.x < 256) Ws[threadIdx.x] = Wm[threadIdx.x];
    __syncthreads();
    const size_t R = (size_t)MAG * NSEQ;
    size_t pos = (size_t)blockIdx.x * blockDim.x + threadIdx.x;
    if (pos >= (size_t)NB * R) return;
    size_t b = pos / R, r = pos % R;
    int m = (int)(r >> 12);
    float* p = g_ak + b * 16 * R + r;
    float x[16];
#pragma unroll
    for (int h = 0; h < 16; h++) {
        float2 st = g_akstat[(b * 16 + h) * MAG + m];
        x[h] = __expf(p[h * R] - st.x) * st.y;
    }
#pragma unroll
    for (int g = 0; g < 16; g++) {
        float sacc = 0.f;
#pragma unroll
        for (int h = 0; h < 16; h++) sacc = fmaf(Ws[g * 16 + h], x[h], sacc);
        p[g * R] = sacc;
    }
}

// ---------------- talking heads (qa side) ----------------
__global__ __launch_bounds__(256) void mix_heads_kernel(const float* __restrict__ Wm) {
    __shared__ float Ws[256];
    if (threadIdx.x < 256) Ws[threadIdx.x] = Wm[threadIdx.x];
    __syncthreads();
    const size_t R = (size_t)NSEQ * MAG;
    size_t pos = (size_t)blockIdx.x * blockDim.x + threadIdx.x;
    if (pos >= (size_t)NB * R) return;
    size_t b = pos / R, r = pos % R;
    float* p = g_qa + b * 16 * R + r;
    float x[16];
#pragma unroll
    for (int h = 0; h < 16; h++) x[h] = p[h * R];
#pragma unroll
    for (int g = 0; g < 16; g++) {
        float sacc = 0.f;
#pragma unroll
        for (int h = 0; h < 16; h++) sacc = fmaf(Ws[g * 16 + h], x[h], sacc);
        p[g * R] = sacc;
    }
}

// ---------------- agent_out (split-K=8, K-chunk 32) ----------------
__global__ __launch_bounds__(256) void agent_out_kernel() {
    __shared__ float As[32][128];
    __shared__ float Bs[32][64];
    const int tid = threadIdx.x;
    const int sp = blockIdx.x;
    const int bh = blockIdx.y;
    const float* A = g_ak + (size_t)bh * MAG * NSEQ;
    const float* V = g_v + (size_t)bh * NSEQ * DHEAD;
    const int tx = tid & 15, ty = tid >> 4;
    float acc[8][4] = {};
    const int kend = sp * 512 + 512;
    for (int k0 = sp * 512; k0 < kend; k0 += 32) {
#pragma unroll
        for (int p = 0; p < 4; p++) {
            int id = tid + p * 256;
            int m = id >> 3, kc = (id & 7) << 2;
            float4 a4 = *reinterpret_cast<const float4*>(&A[m * 4096 + k0 + kc]);
            As[kc + 0][m] = a4.x; As[kc + 1][m] = a4.y;
            As[kc + 2][m] = a4.z; As[kc + 3][m] = a4.w;
        }
#pragma unroll
        for (int p = 0; p < 2; p++) {
            int id = tid + p * 256;
            int r = id >> 4, c = (id & 15) << 2;
            *reinterpret_cast<float4*>(&Bs[r][c]) =
                *reinterpret_cast<const float4*>(&V[(k0 + r) * 64 + c]);
        }
        __syncthreads();
#pragma unroll
        for (int kk = 0; kk < 32; kk++) {
            float4 rb4 = *reinterpret_cast<const float4*>(&Bs[kk][tx * 4]);
            float rb[4] = {rb4.x, rb4.y, rb4.z, rb4.w};
            float ra[8];
#pragma unroll
            for (int i = 0; i < 8; i++) ra[i] = As[kk][ty * 8 + i];
#pragma unroll
            for (int i = 0; i < 8; i++)
#pragma unroll
                for (int j = 0; j < 4; j++) acc[i][j] = fmaf(ra[i], rb[j], acc[i][j]);
        }
        __syncthreads();
    }
    float* P = g_agent_part + (size_t)sp * (BHN * MAG * DHEAD) + (size_t)bh * (MAG * DHEAD);
#pragma unroll
    for (int i = 0; i < 8; i++)
        *reinterpret_cast<float4*>(&P[(ty * 8 + i) * 64 + tx * 4]) =
            make_float4(acc[i][0], acc[i][1], acc[i][2], acc[i][3]);
}

__global__ __launch_bounds__(256) void reduce_agent_kernel() {
    int i = blockIdx.x * 256 + threadIdx.x;
    float sacc = 0.f;
#pragma unroll
    for (int k = 0; k < 8; k++) sacc += g_agent_part[(size_t)k * (BHN * MAG * DHEAD) + i];
    g_agent[i] = sacc;
}

// ---------------- out_mid (K-chunk 32): qa2 @ agent, mask, bf16 hi/lo ----------------
__global__ __launch_bounds__(256) void out_mid_kernel() {
    __shared__ float As[32][128];
    __shared__ float Bs[32][64];
    const int tid = threadIdx.x;
    const int bh = blockIdx.y;
    const int b = bh >> 4, h = bh & 15;
    const int bm = blockIdx.x * 128;
    const float* A = g_qa + (size_t)bh * NSEQ * MAG;
    const float* G = g_agent + (size_t)bh * MAG * DHEAD;
    const int tx = tid & 15, ty = tid >> 4;
    float acc[8][4] = {};
    for (int k0 = 0; k0 < 128; k0 += 32) {
#pragma unroll
        for (int p = 0; p < 4; p++) {
            int id = tid + p * 256;
            int r = id >> 3, kc = (id & 7) << 2;
            float4 a4 = *reinterpret_cast<const float4*>(&A[(size_t)(bm + r) * 128 + k0 + kc]);
            As[kc + 0][r] = a4.x; As[kc + 1][r] = a4.y;
            As[kc + 2][r] = a4.z; As[kc + 3][r] = a4.w;
        }
#pragma unroll
        for (int p = 0; p < 2; p++) {
            int id = tid + p * 256;
            int r = id >> 4, c = (id & 15) << 2;
            *reinterpret_cast<float4*>(&Bs[r][c]) =
                *reinterpret_cast<const float4*>(&G[(k0 + r) * 64 + c]);
        }
        __syncthreads();
#pragma unroll
        for (int kk = 0; kk < 32; kk++) {
            float4 rb4 = *reinterpret_cast<const float4*>(&Bs[kk][tx * 4]);
            float rb[4] = {rb4.x, rb4.y, rb4.z, rb4.w};
            float ra[8];
#pragma unroll
            for (int i = 0; i < 8; i++) ra[i] = As[kk][ty * 8 + i];
#pragma unroll
            for (int i = 0; i < 8; i++)
#pragma unroll
                for (int j = 0; j < 4; j++) acc[i][j] = fmaf(ra[i], rb[j], acc[i][j]);
        }
        __syncthreads();
    }
#pragma unroll
    for (int i = 0; i < 8; i++) {
        int r = bm + ty * 8 + i;
        float mv = g_maskf[b * NSEQ + r];
        size_t o = ((size_t)b * NSEQ + r) * DIMX + h * 64 + tx * 4;
        __nv_bfloat16 hh0, ll0, hh1, ll1, hh2, ll2, hh3, ll3;
        split_hl(acc[i][0] * mv, hh0, ll0);
        split_hl(acc[i][1] * mv, hh1, ll1);
        split_hl(acc[i][2] * mv, hh2, ll2);
        split_hl(acc[i][3] * mv, hh3, ll3);
        reinterpret_cast<__nv_bfloat162*>(&g_midh[o])[0] = __nv_bfloat162(hh0, hh1);
        reinterpret_cast<__nv_bfloat162*>(&g_midh[o])[1] = __nv_bfloat162(hh2, hh3);
        reinterpret_cast<__nv_bfloat162*>(&g_midl[o])[0] = __nv_bfloat162(ll0, ll1);
        reinterpret_cast<__nv_bfloat162*>(&g_midl[o])[1] = __nv_bfloat162(ll2, ll3);
    }
}

// ---------------- launcher ----------------
extern "C" void kernel_launch(void* const* d_in, const int* in_sizes, int n_in,
                              void* d_out, int out_size) {
    const float* x     = (const float*)d_in[0];
    const void*  mask  = d_in[1];
    const float* Wqkv  = (const float*)d_in[2];
    const float* agent = (const float*)d_in[3];
    const float* Wqa   = (const float*)d_in[4];
    const float* Wak   = (const float*)d_in[5];
    const float* Wout  = (const float*)d_in[6];
    float* out = (float*)d_out;
    (void)in_sizes; (void)n_in; (void)out_size;

    cudaFuncSetAttribute(gemm_mma_kernel<0>, cudaFuncAttributeMaxDynamicSharedMemorySize, GT_SMEM);
    cudaFuncSetAttribute(gemm_mma_kernel<1>, cudaFuncAttributeMaxDynamicSharedMemorySize, GT_SMEM);
    cudaFuncSetAttribute(qa_sim_softmax_kernel, cudaFuncAttributeMaxDynamicSharedMemorySize, SIM_SMEM);
    cudaFuncSetAttribute(ak_sim_kernel, cudaFuncAttributeMaxDynamicSharedMemorySize, SIM_SMEM);

    __nv_bfloat16 *xh, *xl, *wqh, *wql, *woh, *wol, *mh, *ml;
    cudaGetSymbolAddress((void**)&xh,  g_xh);
    cudaGetSymbolAddress((void**)&xl,  g_xl);
    cudaGetSymbolAddress((void**)&wqh, g_wqkvh);
    cudaGetSymbolAddress((void**)&wql, g_wqkvl);
    cudaGetSymbolAddress((void**)&woh, g_wouth);
    cudaGetSymbolAddress((void**)&wol, g_woutl);
    cudaGetSymbolAddress((void**)&mh,  g_midh);
    cudaGetSymbolAddress((void**)&ml,  g_midl);

    mask_expand_kernel<<<1, 1024>>>(mask);
    conv_split_kernel<<<(NB * NSEQ * DIMX / 4 + 255) / 256, 256>>>(x, xh, xl, NB * NSEQ * DIMX / 4);
    conv_wt_kernel<<<dim3(96, 32), 256>>>(Wqkv, wqh, wql, 1024, 3072);
    conv_wt_kernel<<<dim3(32, 32), 256>>>(Wout, woh, wol, 1024, 1024);

    gemm_mma_kernel<1><<<dim3(24, 128), 256, GT_SMEM>>>(xh, xl, wqh, wql, nullptr, 1024, 3072);

    qa_sim_softmax_kernel<<<dim3(32, 64), 256, SIM_SMEM>>>(agent);
    ak_sim_kernel<<<dim3(32, 64), 256, SIM_SMEM>>>(agent);
    ak_stats_kernel<<<BHN * MAG, 256>>>();
    mix_heads_kernel<<<8192, 256>>>(Wqa);
    mix_ak_exp_kernel<<<8192, 256>>>(Wak);
    agent_out_kernel<<<dim3(8, 64), 256>>>();
    reduce_agent_kernel<<<(BHN * MAG * DHEAD) / 256, 256>>>();
    out_mid_kernel<<<dim3(32, 64), 256>>>();

    gemm_mma_kernel<0><<<dim3(8, 128), 256, GT_SMEM>>>(mh, ml, woh, wol, out, 1024, 1024);
}

// round 8
// speedup vs baseline: 1.4694x; 1.4694x over previous
#include <cuda_runtime.h>
#include <cuda_bf16.h>
#include <stdint.h>
#include <float.h>

// ---------------- problem constants ----------------
#define NB    4
#define NSEQ  4096
#define DIMX  1024
#define HEADS 16
#define DHEAD 64
#define MAG   128
#define BHN   (NB * HEADS)
#define SCALE 0.125f

// ---------------- scratch (device globals; no allocation) ----------------
__device__ float g_q[NB * HEADS * NSEQ * DHEAD];
__device__ float g_k[NB * HEADS * NSEQ * DHEAD];
__device__ float g_v[NB * HEADS * NSEQ * DHEAD];
__device__ float g_qa[NB * HEADS * NSEQ * MAG];
__device__ float g_ak[NB * HEADS * MAG * NSEQ];
__device__ float g_agent_part[8 * BHN * MAG * DHEAD];
__device__ float g_agent[BHN * MAG * DHEAD];
__device__ float g_maskf[NB * NSEQ];
__device__ float2 g_akstat[BHN * MAG];

__device__ __nv_bfloat16 g_xh[NB * NSEQ * DIMX];
__device__ __nv_bfloat16 g_xl[NB * NSEQ * DIMX];
__device__ __nv_bfloat16 g_wqkvh[3 * DIMX * DIMX];
__device__ __nv_bfloat16 g_wqkvl[3 * DIMX * DIMX];
__device__ __nv_bfloat16 g_wouth[DIMX * DIMX];
__device__ __nv_bfloat16 g_woutl[DIMX * DIMX];
__device__ __nv_bfloat16 g_midh[NB * NSEQ * DIMX];
__device__ __nv_bfloat16 g_midl[NB * NSEQ * DIMX];

// ---------------- PTX helpers ----------------
__device__ __forceinline__ uint32_t smem_u32(const void* p) {
    uint32_t a;
    asm("{ .reg .u64 t; cvta.to.shared.u64 t, %1; cvt.u32.u64 %0, t; }" : "=r"(a) : "l"(p));
    return a;
}
#define SMEM_SWIZZLE_128B(o) ((o) ^ (((o) >> 3) & 0x70))

__device__ __forceinline__ void cp_async16(uint32_t sa, const void* g) {
    asm volatile("cp.async.cg.shared.global [%0], [%1], 16;" :: "r"(sa), "l"(g));
}
#define CP_COMMIT() asm volatile("cp.async.commit_group;" ::: "memory")
#define CP_WAIT(n)  asm volatile("cp.async.wait_group %0;" :: "n"(n) : "memory")

__device__ __forceinline__ void ldsm_x4(uint32_t* r, uint32_t a) {
    asm volatile("ldmatrix.sync.aligned.m8n8.x4.shared.b16 {%0,%1,%2,%3}, [%4];"
                 : "=r"(r[0]), "=r"(r[1]), "=r"(r[2]), "=r"(r[3]) : "r"(a));
}
__device__ __forceinline__ void mma16816(float* c, const uint32_t* a, const uint32_t* b) {
    asm volatile("mma.sync.aligned.m16n8k16.row.col.f32.bf16.bf16.f32 "
                 "{%0,%1,%2,%3}, {%4,%5,%6,%7}, {%8,%9}, {%0,%1,%2,%3};"
                 : "+f"(c[0]), "+f"(c[1]), "+f"(c[2]), "+f"(c[3])
                 : "r"(a[0]), "r"(a[1]), "r"(a[2]), "r"(a[3]), "r"(b[0]), "r"(b[1]));
}

__device__ __forceinline__ float warp_max(float v) {
#pragma unroll
    for (int o = 16; o > 0; o >>= 1) v = fmaxf(v, __shfl_xor_sync(0xffffffffu, v, o));
    return v;
}
__device__ __forceinline__ float warp_sum(float v) {
#pragma unroll
    for (int o = 16; o > 0; o >>= 1) v += __shfl_xor_sync(0xffffffffu, v, o);
    return v;
}
__device__ __forceinline__ void split_hl(float v, __nv_bfloat16& h, __nv_bfloat16& l) {
    h = __float2bfloat16(v);
    l = __float2bfloat16(v - __bfloat162float(h));
}

// ---------------- mask dtype detection + expansion ----------------
__global__ void mask_expand_kernel(const void* __restrict__ mraw) {
    __shared__ int s_weird, s_off;
    const unsigned char* mb = (const unsigned char*)mraw;
    if (threadIdx.x == 0) { s_weird = 0; s_off = 0; }
    __syncthreads();
    int weird = 0, off = 0;
    for (int i = threadIdx.x; i < NB * NSEQ; i += blockDim.x) {
        unsigned char c = mb[i];
        if (c > 1) weird = 1;
        if (c != 0 && (i & 3)) off = 1;
    }
    if (weird) atomicOr(&s_weird, 1);
    if (off)   atomicOr(&s_off, 1);
    __syncthreads();
    int mode = s_weird ? 2 : (s_off ? 0 : 1);
    for (int i = threadIdx.x; i < NB * NSEQ; i += blockDim.x) {
        float v;
        if (mode == 0)      v = mb[i] ? 1.f : 0.f;
        else if (mode == 1) v = ((const int*)mraw)[i] ? 1.f : 0.f;
        else                v = (((const float*)mraw)[i] != 0.f) ? 1.f : 0.f;
        g_maskf[i] = v;
    }
}

// ---------------- fp32 -> bf16 hi/lo split ----------------
__global__ __launch_bounds__(256) void conv_split_kernel(const float* __restrict__ src,
                                                         __nv_bfloat16* __restrict__ h,
                                                         __nv_bfloat16* __restrict__ l, int n4) {
    int i = blockIdx.x * 256 + threadIdx.x;
    if (i >= n4) return;
    float4 v = reinterpret_cast<const float4*>(src)[i];
    __nv_bfloat16 h0, h1, h2, h3, l0, l1, l2, l3;
    split_hl(v.x, h0, l0); split_hl(v.y, h1, l1);
    split_hl(v.z, h2, l2); split_hl(v.w, h3, l3);
    reinterpret_cast<__nv_bfloat162*>(h)[i * 2]     = __nv_bfloat162(h0, h1);
    reinterpret_cast<__nv_bfloat162*>(h)[i * 2 + 1] = __nv_bfloat162(h2, h3);
    reinterpret_cast<__nv_bfloat162*>(l)[i * 2]     = __nv_bfloat162(l0, l1);
    reinterpret_cast<__nv_bfloat162*>(l)[i * 2 + 1] = __nv_bfloat162(l2, l3);
}

// ---------------- W[K,N] -> W^T[N,K] bf16 hi/lo ----------------
__global__ __launch_bounds__(256) void conv_wt_kernel(const float* __restrict__ W,
                                                      __nv_bfloat16* __restrict__ Th,
                                                      __nv_bfloat16* __restrict__ Tl,
                                                      int K, int N) {
    __shared__ float t[32][33];
    int bx = blockIdx.x * 32;
    int by = blockIdx.y * 32;
    int x = threadIdx.x & 31, y0 = threadIdx.x >> 5;
#pragma unroll
    for (int y = y0; y < 32; y += 8) t[y][x] = W[(size_t)(by + y) * N + bx + x];
    __syncthreads();
#pragma unroll
    for (int y = y0; y < 32; y += 8) {
        float v = t[x][y];
        __nv_bfloat16 h, l;
        split_hl(v, h, l);
        size_t o = (size_t)(bx + y) * K + by + x;
        Th[o] = h; Tl[o] = l;
    }
}

// ---------------- mma.sync bf16x3 GEMM: 128x128 tile, BK=64, 2-stage, 512 threads ----------------
// 16 warps: warp grid 4(m) x 4(n); warp tile 32x32.
#define GT_TILE  16384
#define GT_STAGE (4 * GT_TILE)
#define GT_SMEM  (1024 + 2 * GT_STAGE)   // 132096

template <int MODE>
__global__ __launch_bounds__(512, 1) void gemm_mma_kernel(
    const __nv_bfloat16* __restrict__ Ah, const __nv_bfloat16* __restrict__ Al,
    const __nv_bfloat16* __restrict__ Bh, const __nv_bfloat16* __restrict__ Bl,
    float* __restrict__ out, int Kdim, int Nout) {
    extern __shared__ char dsm[];
    uint32_t sraw = smem_u32(dsm);
    uint32_t sbase = (sraw + 1023u) & ~1023u;

    const int tid = threadIdx.x;
    const int lane = tid & 31;
    const int wid = tid >> 5;          // 0..15
    const int wm = wid >> 2;           // 0..3
    const int wn = wid & 3;            // 0..3
    const int bm = blockIdx.y * 128;
    const int bn = blockIdx.x * 128;

    float acc[2][4][4];
#pragma unroll
    for (int i = 0; i < 2; i++)
#pragma unroll
        for (int j = 0; j < 4; j++)
#pragma unroll
            for (int v = 0; v < 4; v++) acc[i][j][v] = 0.f;

    const int nchunk = Kdim >> 6;      // BK = 64
    const int lr  = tid >> 3;          // 0..63
    const int lc  = (tid & 7) << 4;    // byte col 0..112

    auto load_chunk = [&](int c) {
        const int buf = c & 1;
        const int k0 = c << 6;
        const uint32_t sb = sbase + buf * GT_STAGE;
#pragma unroll
        for (int i = 0; i < 2; i++) {
            int r = lr + i * 64;
            uint32_t so = SMEM_SWIZZLE_128B(r * 128 + lc);
            size_t go = (size_t)(bm + r) * Kdim + k0 + (lc >> 1);
            size_t gb = (size_t)(bn + r) * Kdim + k0 + (lc >> 1);
            cp_async16(sb + 0 * GT_TILE + so, Ah + go);
            cp_async16(sb + 1 * GT_TILE + so, Al + go);
            cp_async16(sb + 2 * GT_TILE + so, Bh + gb);
            cp_async16(sb + 3 * GT_TILE + so, Bl + gb);
        }
        CP_COMMIT();
    };

    load_chunk(0);
    if (nchunk > 1) load_chunk(1);

    const int lrow = lane & 15;
    const int lksel = (lane >> 4) << 4;

    for (int c = 0; c < nchunk; c++) {
        if (c + 1 < nchunk) { CP_WAIT(1); } else { CP_WAIT(0); }
        __syncthreads();
        const uint32_t sb = sbase + (c & 1) * GT_STAGE;
        const uint32_t a_h = sb, a_l = sb + GT_TILE;
        const uint32_t b_h = sb + 2 * GT_TILE, b_l = sb + 3 * GT_TILE;
#pragma unroll
        for (int ks = 0; ks < 4; ks++) {
            const int kb = ks * 32 + lksel;
            uint32_t ah[2][4], al[2][4], bh[4][2], bl[4][2];
#pragma unroll
            for (int mf = 0; mf < 2; mf++) {
                int row = wm * 32 + mf * 16 + lrow;
                uint32_t so = SMEM_SWIZZLE_128B(row * 128 + kb);
                ldsm_x4(ah[mf], a_h + so);
                ldsm_x4(al[mf], a_l + so);
            }
#pragma unroll
            for (int g = 0; g < 2; g++) {
                int row = wn * 32 + g * 16 + lrow;
                uint32_t so = SMEM_SWIZZLE_128B(row * 128 + kb);
                uint32_t r[4];
                ldsm_x4(r, b_h + so);
                bh[g * 2][0] = r[0]; bh[g * 2][1] = r[2];
                bh[g * 2 + 1][0] = r[1]; bh[g * 2 + 1][1] = r[3];
                ldsm_x4(r, b_l + so);
                bl[g * 2][0] = r[0]; bl[g * 2][1] = r[2];
                bl[g * 2 + 1][0] = r[1]; bl[g * 2 + 1][1] = r[3];
            }
#pragma unroll
            for (int mf = 0; mf < 2; mf++)
#pragma unroll
                for (int nf = 0; nf < 4; nf++) mma16816(acc[mf][nf], ah[mf], bh[nf]);
#pragma unroll
            for (int mf = 0; mf < 2; mf++)
#pragma unroll
                for (int nf = 0; nf < 4; nf++) mma16816(acc[mf][nf], ah[mf], bl[nf]);
#pragma unroll
            for (int mf = 0; mf < 2; mf++)
#pragma unroll
                for (int nf = 0; nf < 4; nf++) mma16816(acc[mf][nf], al[mf], bh[nf]);
        }
        __syncthreads();
        if (c + 2 < nchunk) load_chunk(c + 2);
    }

#pragma unroll
    for (int mf = 0; mf < 2; mf++) {
        int r0 = bm + wm * 32 + mf * 16 + (lane >> 2);
#pragma unroll
        for (int nf = 0; nf < 4; nf++) {
            int col = bn + wn * 32 + nf * 8 + ((lane & 3) << 1);
            float* p0;
            float* p1;
            if (MODE == 1) {
                const int which = col >> 10;
                const int hh = (col >> 6) & 15;
                const int d0 = col & 63;
                float* dst = which == 0 ? g_q : (which == 1 ? g_k : g_v);
                const int b0 = r0 >> 12, n0 = r0 & 4095;
                const int b1 = (r0 + 8) >> 12, n1 = (r0 + 8) & 4095;
                p0 = &dst[(((size_t)(b0 * 16 + hh)) * 4096 + n0) * 64 + d0];
                p1 = &dst[(((size_t)(b1 * 16 + hh)) * 4096 + n1) * 64 + d0];
            } else {
                p0 = &out[(size_t)r0 * Nout + col];
                p1 = &out[(size_t)(r0 + 8) * Nout + col];
            }
            *reinterpret_cast<float2*>(p0) = make_float2(acc[mf][nf][0], acc[mf][nf][1]);
            *reinterpret_cast<float2*>(p1) = make_float2(acc[mf][nf][2], acc[mf][nf][3]);
        }
    }
}

// ---------------- qa_sim + fused softmax over m (R4 version) ----------------
#define SIM_SMEM (2 * 64 * 128 * 4)   // 65536
__global__ __launch_bounds__(256) void qa_sim_softmax_kernel(const float* __restrict__ Agt) {
    extern __shared__ float s[];
    float (*Qs)[128] = reinterpret_cast<float(*)[128]>(s);
    float (*As)[128] = reinterpret_cast<float(*)[128]>(s + 64 * 128);
    const int tid = threadIdx.x;
    const int bh = blockIdx.y;
    const int h = bh & 15;
    const int bm = blockIdx.x * 128;
    const float* Q = g_q + (size_t)bh * (NSEQ * DHEAD);
    const float* A = Agt + (size_t)h * (MAG * DHEAD);
    const int tx = tid & 15, ty = tid >> 4;
    const int row = tid >> 2, kv = (tid & 3) << 2;
#pragma unroll
    for (int k0 = 0; k0 < 64; k0 += 16) {
#pragma unroll
        for (int s2 = 0; s2 < 2; s2++) {
            int r = row + s2 * 64;
            float4 a4 = *reinterpret_cast<const float4*>(&Q[(bm + r) * 64 + k0 + kv]);
            Qs[k0 + kv + 0][r] = a4.x; Qs[k0 + kv + 1][r] = a4.y;
            Qs[k0 + kv + 2][r] = a4.z; Qs[k0 + kv + 3][r] = a4.w;
            float4 b4 = *reinterpret_cast<const float4*>(&A[r * 64 + k0 + kv]);
            As[k0 + kv + 0][r] = b4.x * SCALE; As[k0 + kv + 1][r] = b4.y * SCALE;
            As[k0 + kv + 2][r] = b4.z * SCALE; As[k0 + kv + 3][r] = b4.w * SCALE;
        }
    }
    __syncthreads();
    float acc[8][8] = {};
#pragma unroll 8
    for (int kk = 0; kk < 64; kk++) {
        float4 ra0 = *reinterpret_cast<const float4*>(&Qs[kk][ty * 8]);
        float4 ra1 = *reinterpret_cast<const float4*>(&Qs[kk][ty * 8 + 4]);
        float4 rb0 = *reinterpret_cast<const float4*>(&As[kk][tx * 8]);
        float4 rb1 = *reinterpret_cast<const float4*>(&As[kk][tx * 8 + 4]);
        float ra[8] = {ra0.x, ra0.y, ra0.z, ra0.w, ra1.x, ra1.y, ra1.z, ra1.w};
        float rb[8] = {rb0.x, rb0.y, rb0.z, rb0.w, rb1.x, rb1.y, rb1.z, rb1.w};
#pragma unroll
        for (int i = 0; i < 8; i++)
#pragma unroll
            for (int j = 0; j < 8; j++) acc[i][j] = fmaf(ra[i], rb[j], acc[i][j]);
    }
#pragma unroll
    for (int i = 0; i < 8; i++) {
        float mx = acc[i][0];
#pragma unroll
        for (int j = 1; j < 8; j++) mx = fmaxf(mx, acc[i][j]);
#pragma unroll
        for (int o = 8; o > 0; o >>= 1) mx = fmaxf(mx, __shfl_xor_sync(0xffffffffu, mx, o));
        float sm = 0.f;
#pragma unroll
        for (int j = 0; j < 8; j++) { acc[i][j] = __expf(acc[i][j] - mx); sm += acc[i][j]; }
#pragma unroll
        for (int o = 8; o > 0; o >>= 1) sm += __shfl_xor_sync(0xffffffffu, sm, o);
        float inv = 1.f / sm;
        int ii = bm + ty * 8 + i;
        float* p = &g_qa[((size_t)bh * NSEQ + ii) * MAG + tx * 8];
        *reinterpret_cast<float4*>(p) =
            make_float4(acc[i][0] * inv, acc[i][1] * inv, acc[i][2] * inv, acc[i][3] * inv);
        *reinterpret_cast<float4*>(p + 4) =
            make_float4(acc[i][4] * inv, acc[i][5] * inv, acc[i][6] * inv, acc[i][7] * inv);
    }
}

// ---------------- ak_sim (R4 version) ----------------
__global__ __launch_bounds__(256) void ak_sim_kernel(const float* __restrict__ Agt) {
    extern __shared__ float s[];
    float (*As)[128] = reinterpret_cast<float(*)[128]>(s);
    float (*Ks)[128] = reinterpret_cast<float(*)[128]>(s + 64 * 128);
    const int tid = threadIdx.x;
    const int bh = blockIdx.y;
    const int b = bh >> 4, h = bh & 15;
    const int bn = blockIdx.x * 128;
    const float* A  = Agt + (size_t)h * (MAG * DHEAD);
    const float* Kt = g_k + (size_t)bh * (NSEQ * DHEAD);
    const int tx = tid & 15, ty = tid >> 4;
    const int row = tid >> 2, kv = (tid & 3) << 2;
#pragma unroll
    for (int k0 = 0; k0 < 64; k0 += 16) {
#pragma unroll
        for (int s2 = 0; s2 < 2; s2++) {
            int r = row + s2 * 64;
            float4 a4 = *reinterpret_cast<const float4*>(&A[r * 64 + k0 + kv]);
            As[k0 + kv + 0][r] = a4.x * SCALE; As[k0 + kv + 1][r] = a4.y * SCALE;
            As[k0 + kv + 2][r] = a4.z * SCALE; As[k0 + kv + 3][r] = a4.w * SCALE;
            float4 b4 = *reinterpret_cast<const float4*>(&Kt[(bn + r) * 64 + k0 + kv]);
            Ks[k0 + kv + 0][r] = b4.x; Ks[k0 + kv + 1][r] = b4.y;
            Ks[k0 + kv + 2][r] = b4.z; Ks[k0 + kv + 3][r] = b4.w;
        }
    }
    __syncthreads();
    float acc[8][8] = {};
#pragma unroll 8
    for (int kk = 0; kk < 64; kk++) {
        float4 ra0 = *reinterpret_cast<const float4*>(&As[kk][ty * 8]);
        float4 ra1 = *reinterpret_cast<const float4*>(&As[kk][ty * 8 + 4]);
        float4 rb0 = *reinterpret_cast<const float4*>(&Ks[kk][tx * 8]);
        float4 rb1 = *reinterpret_cast<const float4*>(&Ks[kk][tx * 8 + 4]);
        float ra[8] = {ra0.x, ra0.y, ra0.z, ra0.w, ra1.x, ra1.y, ra1.z, ra1.w};
        float rb[8] = {rb0.x, rb0.y, rb0.z, rb0.w, rb1.x, rb1.y, rb1.z, rb1.w};
#pragma unroll
        for (int i = 0; i < 8; i++)
#pragma unroll
            for (int j = 0; j < 8; j++) acc[i][j] = fmaf(ra[i], rb[j], acc[i][j]);
    }
#pragma unroll
    for (int i = 0; i < 8; i++) {
        int m = ty * 8 + i;
        float* p = &g_ak[((size_t)bh * MAG + m) * NSEQ + bn + tx * 8];
#pragma unroll
        for (int j = 0; j < 8; j++) {
            int n = bn + tx * 8 + j;
            float mv = g_maskf[b * NSEQ + n];
            p[j] = (mv != 0.f) ? acc[i][j] : -FLT_MAX;
        }
    }
}

// ---------------- ak row stats ----------------
__global__ __launch_bounds__(256) void ak_stats_kernel() {
    const int row = blockIdx.x;
    const int t = threadIdx.x;
    const float* p = g_ak + (size_t)row * NSEQ;
    float4 v[4];
    float mx = -FLT_MAX;
#pragma unroll
    for (int i = 0; i < 4; i++) {
        v[i] = *reinterpret_cast<const float4*>(&p[t * 16 + i * 4]);
        mx = fmaxf(mx, fmaxf(fmaxf(v[i].x, v[i].y), fmaxf(v[i].z, v[i].w)));
    }
    __shared__ float red[8];
    int wid = t >> 5, lane = t & 31;
    float wm = warp_max(mx);
    if (lane == 0) red[wid] = wm;
    __syncthreads();
    float m = red[0];
#pragma unroll
    for (int i = 1; i < 8; i++) m = fmaxf(m, red[i]);
    float sacc = 0.f;
#pragma unroll
    for (int i = 0; i < 4; i++)
        sacc += __expf(v[i].x - m) + __expf(v[i].y - m) + __expf(v[i].z - m) + __expf(v[i].w - m);
    float ws = warp_sum(sacc);
    __syncthreads();
    if (lane == 0) red[wid] = ws;
    __syncthreads();
    if (t == 0) {
        float tot = 0.f;
#pragma unroll
        for (int i = 0; i < 8; i++) tot += red[i];
        g_akstat[row] = make_float2(m, 1.f / tot);
    }
}

// ---------------- fused exp-normalize + head mix (ak, in place) ----------------
__global__ __launch_bounds__(256) void mix_ak_exp_kernel(const float* __restrict__ Wm) {
    __shared__ float Ws[256];
    if (threadIdx.x < 256) Ws[threadIdx.x] = Wm[threadIdx.x];
    __syncthreads();
    const size_t R = (size_t)MAG * NSEQ;
    size_t pos = (size_t)blockIdx.x * blockDim.x + threadIdx.x;
    if (pos >= (size_t)NB * R) return;
    size_t b = pos / R, r = pos % R;
    int m = (int)(r >> 12);
    float* p = g_ak + b * 16 * R + r;
    float x[16];
#pragma unroll
    for (int h = 0; h < 16; h++) {
        float2 st = g_akstat[(b * 16 + h) * MAG + m];
        x[h] = __expf(p[h * R] - st.x) * st.y;
    }
#pragma unroll
    for (int g = 0; g < 16; g++) {
        float sacc = 0.f;
#pragma unroll
        for (int h = 0; h < 16; h++) sacc = fmaf(Ws[g * 16 + h], x[h], sacc);
        p[g * R] = sacc;
    }
}

// ---------------- talking heads (qa side) ----------------
__global__ __launch_bounds__(256) void mix_heads_kernel(const float* __restrict__ Wm) {
    __shared__ float Ws[256];
    if (threadIdx.x < 256) Ws[threadIdx.x] = Wm[threadIdx.x];
    __syncthreads();
    const size_t R = (size_t)NSEQ * MAG;
    size_t pos = (size_t)blockIdx.x * blockDim.x + threadIdx.x;
    if (pos >= (size_t)NB * R) return;
    size_t b = pos / R, r = pos % R;
    float* p = g_qa + b * 16 * R + r;
    float x[16];
#pragma unroll
    for (int h = 0; h < 16; h++) x[h] = p[h * R];
#pragma unroll
    for (int g = 0; g < 16; g++) {
        float sacc = 0.f;
#pragma unroll
        for (int h = 0; h < 16; h++) sacc = fmaf(Ws[g * 16 + h], x[h], sacc);
        p[g * R] = sacc;
    }
}

// ---------------- agent_out (split-K=8, R4 version) ----------------
__global__ __launch_bounds__(256) void agent_out_kernel() {
    __shared__ float As[16][128];
    __shared__ float Bs[16][64];
    const int tid = threadIdx.x;
    const int sp = blockIdx.x;
    const int bh = blockIdx.y;
    const float* A = g_ak + (size_t)bh * MAG * NSEQ;
    const float* V = g_v + (size_t)bh * NSEQ * DHEAD;
    const int tx = tid & 15, ty = tid >> 4;
    const int arow = tid >> 2, akv = (tid & 3) << 2;
    const int bk = tid >> 4, bn4 = (tid & 15) << 2;
    float acc[8][4] = {};
    const int kend = sp * 512 + 512;
    for (int k0 = sp * 512; k0 < kend; k0 += 16) {
#pragma unroll
        for (int s2 = 0; s2 < 2; s2++) {
            int r = arow + s2 * 64;
            float4 a4 = *reinterpret_cast<const float4*>(&A[r * 4096 + k0 + akv]);
            As[akv + 0][r] = a4.x; As[akv + 1][r] = a4.y;
            As[akv + 2][r] = a4.z; As[akv + 3][r] = a4.w;
        }
        *reinterpret_cast<float4*>(&Bs[bk][bn4]) =
            *reinterpret_cast<const float4*>(&V[(k0 + bk) * 64 + bn4]);
        __syncthreads();
#pragma unroll
        for (int kk = 0; kk < 16; kk++) {
            float ra[8], rb[4];
#pragma unroll
            for (int i = 0; i < 8; i++) ra[i] = As[kk][ty * 8 + i];
#pragma unroll
            for (int j = 0; j < 4; j++) rb[j] = Bs[kk][tx * 4 + j];
#pragma unroll
            for (int i = 0; i < 8; i++)
#pragma unroll
                for (int j = 0; j < 4; j++) acc[i][j] = fmaf(ra[i], rb[j], acc[i][j]);
        }
        __syncthreads();
    }
    float* P = g_agent_part + (size_t)sp * (BHN * MAG * DHEAD) + (size_t)bh * (MAG * DHEAD);
#pragma unroll
    for (int i = 0; i < 8; i++)
        *reinterpret_cast<float4*>(&P[(ty * 8 + i) * 64 + tx * 4]) =
            make_float4(acc[i][0], acc[i][1], acc[i][2], acc[i][3]);
}

__global__ __launch_bounds__(256) void reduce_agent_kernel() {
    int i = blockIdx.x * 256 + threadIdx.x;
    float sacc = 0.f;
#pragma unroll
    for (int k = 0; k < 8; k++) sacc += g_agent_part[(size_t)k * (BHN * MAG * DHEAD) + i];
    g_agent[i] = sacc;
}

// ---------------- out_mid (R4 version) ----------------
__global__ __launch_bounds__(256) void out_mid_kernel() {
    __shared__ float As[16][128];
    __shared__ float Bs[16][64];
    const int tid = threadIdx.x;
    const int bh = blockIdx.y;
    const int b = bh >> 4, h = bh & 15;
    const int bm = blockIdx.x * 128;
    const float* A = g_qa + (size_t)bh * NSEQ * MAG;
    const float* G = g_agent + (size_t)bh * MAG * DHEAD;
    const int tx = tid & 15, ty = tid >> 4;
    const int arow = tid >> 2, akv = (tid & 3) << 2;
    const int bk = tid >> 4, bn4 = (tid & 15) << 2;
    float acc[8][4] = {};
    for (int k0 = 0; k0 < 128; k0 += 16) {
#pragma unroll
        for (int s2 = 0; s2 < 2; s2++) {
            int r = arow + s2 * 64;
            float4 a4 = *reinterpret_cast<const float4*>(&A[(bm + r) * 128 + k0 + akv]);
            As[akv + 0][r] = a4.x; As[akv + 1][r] = a4.y;
            As[akv + 2][r] = a4.z; As[akv + 3][r] = a4.w;
        }
        *reinterpret_cast<float4*>(&Bs[bk][bn4]) =
            *reinterpret_cast<const float4*>(&G[(k0 + bk) * 64 + bn4]);
        __syncthreads();
#pragma unroll
        for (int kk = 0; kk < 16; kk++) {
            float ra[8], rb[4];
#pragma unroll
            for (int i = 0; i < 8; i++) ra[i] = As[kk][ty * 8 + i];
#pragma unroll
            for (int j = 0; j < 4; j++) rb[j] = Bs[kk][tx * 4 + j];
#pragma unroll
            for (int i = 0; i < 8; i++)
#pragma unroll
                for (int j = 0; j < 4; j++) acc[i][j] = fmaf(ra[i], rb[j], acc[i][j]);
        }
        __syncthreads();
    }
#pragma unroll
    for (int i = 0; i < 8; i++) {
        int r = bm + ty * 8 + i;
        float mv = g_maskf[b * NSEQ + r];
        size_t o = ((size_t)b * NSEQ + r) * DIMX + h * 64 + tx * 4;
        __nv_bfloat16 hh0, ll0, hh1, ll1, hh2, ll2, hh3, ll3;
        split_hl(acc[i][0] * mv, hh0, ll0);
        split_hl(acc[i][1] * mv, hh1, ll1);
        split_hl(acc[i][2] * mv, hh2, ll2);
        split_hl(acc[i][3] * mv, hh3, ll3);
        reinterpret_cast<__nv_bfloat162*>(&g_midh[o])[0] = __nv_bfloat162(hh0, hh1);
        reinterpret_cast<__nv_bfloat162*>(&g_midh[o])[1] = __nv_bfloat162(hh2, hh3);
        reinterpret_cast<__nv_bfloat162*>(&g_midl[o])[0] = __nv_bfloat162(ll0, ll1);
        reinterpret_cast<__nv_bfloat162*>(&g_midl[o])[1] = __nv_bfloat162(ll2, ll3);
    }
}

// ---------------- launcher ----------------
extern "C" void kernel_launch(void* const* d_in, const int* in_sizes, int n_in,
                              void* d_out, int out_size) {
    const float* x     = (const float*)d_in[0];
    const void*  mask  = d_in[1];
    const float* Wqkv  = (const float*)d_in[2];
    const float* agent = (const float*)d_in[3];
    const float* Wqa   = (const float*)d_in[4];
    const float* Wak   = (const float*)d_in[5];
    const float* Wout  = (const float*)d_in[6];
    float* out = (float*)d_out;
    (void)in_sizes; (void)n_in; (void)out_size;

    cudaFuncSetAttribute(gemm_mma_kernel<0>, cudaFuncAttributeMaxDynamicSharedMemorySize, GT_SMEM);
    cudaFuncSetAttribute(gemm_mma_kernel<1>, cudaFuncAttributeMaxDynamicSharedMemorySize, GT_SMEM);
    cudaFuncSetAttribute(qa_sim_softmax_kernel, cudaFuncAttributeMaxDynamicSharedMemorySize, SIM_SMEM);
    cudaFuncSetAttribute(ak_sim_kernel, cudaFuncAttributeMaxDynamicSharedMemorySize, SIM_SMEM);

    __nv_bfloat16 *xh, *xl, *wqh, *wql, *woh, *wol, *mh, *ml;
    cudaGetSymbolAddress((void**)&xh,  g_xh);
    cudaGetSymbolAddress((void**)&xl,  g_xl);
    cudaGetSymbolAddress((void**)&wqh, g_wqkvh);
    cudaGetSymbolAddress((void**)&wql, g_wqkvl);
    cudaGetSymbolAddress((void**)&woh, g_wouth);
    cudaGetSymbolAddress((void**)&wol, g_woutl);
    cudaGetSymbolAddress((void**)&mh,  g_midh);
    cudaGetSymbolAddress((void**)&ml,  g_midl);

    mask_expand_kernel<<<1, 1024>>>(mask);
    conv_split_kernel<<<(NB * NSEQ * DIMX / 4 + 255) / 256, 256>>>(x, xh, xl, NB * NSEQ * DIMX / 4);
    conv_wt_kernel<<<dim3(96, 32), 256>>>(Wqkv, wqh, wql, 1024, 3072);
    conv_wt_kernel<<<dim3(32, 32), 256>>>(Wout, woh, wol, 1024, 1024);

    gemm_mma_kernel<1><<<dim3(24, 128), 512, GT_SMEM>>>(xh, xl, wqh, wql, nullptr, 1024, 3072);

    qa_sim_softmax_kernel<<<dim3(32, 64), 256, SIM_SMEM>>>(agent);
    ak_sim_kernel<<<dim3(32, 64), 256, SIM_SMEM>>>(agent);
    ak_stats_kernel<<<BHN * MAG, 256>>>();
    mix_heads_kernel<<<8192, 256>>>(Wqa);
    mix_ak_exp_kernel<<<8192, 256>>>(Wak);
    agent_out_kernel<<<dim3(8, 64), 256>>>();
    reduce_agent_kernel<<<(BHN * MAG * DHEAD) / 256, 256>>>();
    out_mid_kernel<<<dim3(32, 64), 256>>>();

    gemm_mma_kernel<0><<<dim3(8, 128), 512, GT_SMEM>>>(mh, ml, woh, wol, out, 1024, 1024);
}

// round 10
// speedup vs baseline: 1.7493x; 1.1905x over previous
#include <cuda_runtime.h>
#include <cuda_bf16.h>
#include <stdint.h>
#include <float.h>

// ---------------- problem constants ----------------
#define NB    4
#define NSEQ  4096
#define DIMX  1024
#define HEADS 16
#define DHEAD 64
#define MAG   128
#define BHN   (NB * HEADS)
#define SCALE 0.125f

// ---------------- scratch (device globals; no allocation) ----------------
__device__ float g_qa[NB * HEADS * NSEQ * MAG];        // fp32 qa attn (softmaxed)
__device__ float g_ak[NB * HEADS * MAG * NSEQ];        // fp32 ak logits (masked)
__device__ float g_agent_part[4 * BHN * MAG * DHEAD];  // split-K partials
__device__ float g_maskf[NB * NSEQ];
__device__ float2 g_akstat[BHN * MAG];

// bf16 hi/lo operands
__device__ __nv_bfloat16 g_xh[NB * NSEQ * DIMX];
__device__ __nv_bfloat16 g_xl[NB * NSEQ * DIMX];
__device__ __nv_bfloat16 g_wqkvh[3 * DIMX * DIMX];
__device__ __nv_bfloat16 g_wqkvl[3 * DIMX * DIMX];
__device__ __nv_bfloat16 g_wouth[DIMX * DIMX];
__device__ __nv_bfloat16 g_woutl[DIMX * DIMX];
__device__ __nv_bfloat16 g_qh[BHN * NSEQ * DHEAD];     // q [bh,n,d]
__device__ __nv_bfloat16 g_ql[BHN * NSEQ * DHEAD];
__device__ __nv_bfloat16 g_kh[BHN * NSEQ * DHEAD];     // k [bh,n,d]
__device__ __nv_bfloat16 g_kl[BHN * NSEQ * DHEAD];
__device__ __nv_bfloat16 g_vth[BHN * DHEAD * NSEQ];    // v^T [bh,d,n]
__device__ __nv_bfloat16 g_vtl[BHN * DHEAD * NSEQ];
__device__ __nv_bfloat16 g_ah[HEADS * MAG * DHEAD];    // agent*SCALE [h,m,d]
__device__ __nv_bfloat16 g_al[HEADS * MAG * DHEAD];
__device__ __nv_bfloat16 g_qamh[NB * HEADS * NSEQ * MAG];  // mixed qa [bh,n,m]
__device__ __nv_bfloat16 g_qaml[NB * HEADS * NSEQ * MAG];
__device__ __nv_bfloat16 g_akmh[NB * HEADS * MAG * NSEQ];  // mixed ak attn [bh,m,n]
__device__ __nv_bfloat16 g_akml[NB * HEADS * MAG * NSEQ];
__device__ __nv_bfloat16 g_agth[BHN * DHEAD * MAG];    // agent^T [bh,d,m]
__device__ __nv_bfloat16 g_agtl[BHN * DHEAD * MAG];
__device__ __nv_bfloat16 g_midh[NB * NSEQ * DIMX];
__device__ __nv_bfloat16 g_midl[NB * NSEQ * DIMX];

// ---------------- PTX helpers ----------------
__device__ __forceinline__ uint32_t smem_u32(const void* p) {
    uint32_t a;
    asm("{ .reg .u64 t; cvta.to.shared.u64 t, %1; cvt.u32.u64 %0, t; }" : "=r"(a) : "l"(p));
    return a;
}
#define SMEM_SWIZZLE_128B(o) ((o) ^ (((o) >> 3) & 0x70))

__device__ __forceinline__ void cp_async16(uint32_t sa, const void* g) {
    asm volatile("cp.async.cg.shared.global [%0], [%1], 16;" :: "r"(sa), "l"(g));
}
#define CP_COMMIT() asm volatile("cp.async.commit_group;" ::: "memory")
#define CP_WAIT(n)  asm volatile("cp.async.wait_group %0;" :: "n"(n) : "memory")

__device__ __forceinline__ void ldsm_x4(uint32_t* r, uint32_t a) {
    asm volatile("ldmatrix.sync.aligned.m8n8.x4.shared.b16 {%0,%1,%2,%3}, [%4];"
                 : "=r"(r[0]), "=r"(r[1]), "=r"(r[2]), "=r"(r[3]) : "r"(a));
}
__device__ __forceinline__ void mma16816(float* c, const uint32_t* a, const uint32_t* b) {
    asm volatile("mma.sync.aligned.m16n8k16.row.col.f32.bf16.bf16.f32 "
                 "{%0,%1,%2,%3}, {%4,%5,%6,%7}, {%8,%9}, {%0,%1,%2,%3};"
                 : "+f"(c[0]), "+f"(c[1]), "+f"(c[2]), "+f"(c[3])
                 : "r"(a[0]), "r"(a[1]), "r"(a[2]), "r"(a[3]), "r"(b[0]), "r"(b[1]));
}

__device__ __forceinline__ float warp_max(float v) {
#pragma unroll
    for (int o = 16; o > 0; o >>= 1) v = fmaxf(v, __shfl_xor_sync(0xffffffffu, v, o));
    return v;
}
__device__ __forceinline__ float warp_sum(float v) {
#pragma unroll
    for (int o = 16; o > 0; o >>= 1) v += __shfl_xor_sync(0xffffffffu, v, o);
    return v;
}
__device__ __forceinline__ void split_hl(float v, __nv_bfloat16& h, __nv_bfloat16& l) {
    h = __float2bfloat16(v);
    l = __float2bfloat16(v - __bfloat162float(h));
}

// ---------------- mask dtype detection + expansion ----------------
__global__ void mask_expand_kernel(const void* __restrict__ mraw) {
    __shared__ int s_weird, s_off;
    const unsigned char* mb = (const unsigned char*)mraw;
    if (threadIdx.x == 0) { s_weird = 0; s_off = 0; }
    __syncthreads();
    int weird = 0, off = 0;
    for (int i = threadIdx.x; i < NB * NSEQ; i += blockDim.x) {
        unsigned char c = mb[i];
        if (c > 1) weird = 1;
        if (c != 0 && (i & 3)) off = 1;
    }
    if (weird) atomicOr(&s_weird, 1);
    if (off)   atomicOr(&s_off, 1);
    __syncthreads();
    int mode = s_weird ? 2 : (s_off ? 0 : 1);
    for (int i = threadIdx.x; i < NB * NSEQ; i += blockDim.x) {
        float v;
        if (mode == 0)      v = mb[i] ? 1.f : 0.f;
        else if (mode == 1) v = ((const int*)mraw)[i] ? 1.f : 0.f;
        else                v = (((const float*)mraw)[i] != 0.f) ? 1.f : 0.f;
        g_maskf[i] = v;
    }
}

// ---------------- fp32 -> bf16 hi/lo split ----------------
__global__ __launch_bounds__(256) void conv_split_kernel(const float* __restrict__ src,
                                                         __nv_bfloat16* __restrict__ h,
                                                         __nv_bfloat16* __restrict__ l, int n4) {
    int i = blockIdx.x * 256 + threadIdx.x;
    if (i >= n4) return;
    float4 v = reinterpret_cast<const float4*>(src)[i];
    __nv_bfloat16 h0, h1, h2, h3, l0, l1, l2, l3;
    split_hl(v.x, h0, l0); split_hl(v.y, h1, l1);
    split_hl(v.z, h2, l2); split_hl(v.w, h3, l3);
    reinterpret_cast<__nv_bfloat162*>(h)[i * 2]     = __nv_bfloat162(h0, h1);
    reinterpret_cast<__nv_bfloat162*>(h)[i * 2 + 1] = __nv_bfloat162(h2, h3);
    reinterpret_cast<__nv_bfloat162*>(l)[i * 2]     = __nv_bfloat162(l0, l1);
    reinterpret_cast<__nv_bfloat162*>(l)[i * 2 + 1] = __nv_bfloat162(l2, l3);
}

// ---------------- agent tokens: scale + bf16 split ----------------
__global__ __launch_bounds__(256) void conv_agent_kernel(const float* __restrict__ src) {
    int i = blockIdx.x * 256 + threadIdx.x;
    if (i >= HEADS * MAG * DHEAD / 4) return;
    float4 v = reinterpret_cast<const float4*>(src)[i];
    __nv_bfloat16 h0, h1, h2, h3, l0, l1, l2, l3;
    split_hl(v.x * SCALE, h0, l0); split_hl(v.y * SCALE, h1, l1);
    split_hl(v.z * SCALE, h2, l2); split_hl(v.w * SCALE, h3, l3);
    reinterpret_cast<__nv_bfloat162*>(g_ah)[i * 2]     = __nv_bfloat162(h0, h1);
    reinterpret_cast<__nv_bfloat162*>(g_ah)[i * 2 + 1] = __nv_bfloat162(h2, h3);
    reinterpret_cast<__nv_bfloat162*>(g_al)[i * 2]     = __nv_bfloat162(l0, l1);
    reinterpret_cast<__nv_bfloat162*>(g_al)[i * 2 + 1] = __nv_bfloat162(l2, l3);
}

// ---------------- W[K,N] -> W^T[N,K] bf16 hi/lo ----------------
__global__ __launch_bounds__(256) void conv_wt_kernel(const float* __restrict__ W,
                                                      __nv_bfloat16* __restrict__ Th,
                                                      __nv_bfloat16* __restrict__ Tl,
                                                      int K, int N) {
    __shared__ float t[32][33];
    int bx = blockIdx.x * 32;
    int by = blockIdx.y * 32;
    int x = threadIdx.x & 31, y0 = threadIdx.x >> 5;
#pragma unroll
    for (int y = y0; y < 32; y += 8) t[y][x] = W[(size_t)(by + y) * N + bx + x];
    __syncthreads();
#pragma unroll
    for (int y = y0; y < 32; y += 8) {
        float v = t[x][y];
        __nv_bfloat16 h, l;
        split_hl(v, h, l);
        size_t o = (size_t)(bx + y) * K + by + x;
        Th[o] = h; Tl[o] = l;
    }
}

// ---------------- big mma GEMM: 128x128 tile, BK=64, 2-stage, 512 threads ----------------
#define GT_TILE  16384
#define GT_STAGE (4 * GT_TILE)
#define GT_SMEM  (1024 + 2 * GT_STAGE)

template <int MODE>   // 0: fp32 out ; 1: qkv scatter (bf16 q/k + v^T)
__global__ __launch_bounds__(512, 1) void gemm_mma_kernel(
    const __nv_bfloat16* __restrict__ Ah, const __nv_bfloat16* __restrict__ Al,
    const __nv_bfloat16* __restrict__ Bh, const __nv_bfloat16* __restrict__ Bl,
    float* __restrict__ out, int Kdim, int Nout) {
    extern __shared__ char dsm[];
    uint32_t sraw = smem_u32(dsm);
    uint32_t sbase = (sraw + 1023u) & ~1023u;

    const int tid = threadIdx.x;
    const int lane = tid & 31;
    const int wid = tid >> 5;
    const int wm = wid >> 2;
    const int wn = wid & 3;
    const int bm = blockIdx.y * 128;
    const int bn = blockIdx.x * 128;

    float acc[2][4][4];
#pragma unroll
    for (int i = 0; i < 2; i++)
#pragma unroll
        for (int j = 0; j < 4; j++)
#pragma unroll
            for (int v = 0; v < 4; v++) acc[i][j][v] = 0.f;

    const int nchunk = Kdim >> 6;
    const int lr  = tid >> 3;
    const int lc  = (tid & 7) << 4;

    auto load_chunk = [&](int c) {
        const int buf = c & 1;
        const int k0 = c << 6;
        const uint32_t sb = sbase + buf * GT_STAGE;
#pragma unroll
        for (int i = 0; i < 2; i++) {
            int r = lr + i * 64;
            uint32_t so = SMEM_SWIZZLE_128B(r * 128 + lc);
            size_t go = (size_t)(bm + r) * Kdim + k0 + (lc >> 1);
            size_t gb = (size_t)(bn + r) * Kdim + k0 + (lc >> 1);
            cp_async16(sb + 0 * GT_TILE + so, Ah + go);
            cp_async16(sb + 1 * GT_TILE + so, Al + go);
            cp_async16(sb + 2 * GT_TILE + so, Bh + gb);
            cp_async16(sb + 3 * GT_TILE + so, Bl + gb);
        }
        CP_COMMIT();
    };

    load_chunk(0);
    if (nchunk > 1) load_chunk(1);

    const int lrow = lane & 15;
    const int lksel = (lane >> 4) << 4;

    for (int c = 0; c < nchunk; c++) {
        if (c + 1 < nchunk) { CP_WAIT(1); } else { CP_WAIT(0); }
        __syncthreads();
        const uint32_t sb = sbase + (c & 1) * GT_STAGE;
        const uint32_t a_h = sb, a_l = sb + GT_TILE;
        const uint32_t b_h = sb + 2 * GT_TILE, b_l = sb + 3 * GT_TILE;
#pragma unroll
        for (int ks = 0; ks < 4; ks++) {
            const int kb = ks * 32 + lksel;
            uint32_t ah[2][4], al[2][4], bh[4][2], bl[4][2];
#pragma unroll
            for (int mf = 0; mf < 2; mf++) {
                int row = wm * 32 + mf * 16 + lrow;
                uint32_t so = SMEM_SWIZZLE_128B(row * 128 + kb);
                ldsm_x4(ah[mf], a_h + so);
                ldsm_x4(al[mf], a_l + so);
            }
#pragma unroll
            for (int g = 0; g < 2; g++) {
                int row = wn * 32 + g * 16 + lrow;
                uint32_t so = SMEM_SWIZZLE_128B(row * 128 + kb);
                uint32_t r[4];
                ldsm_x4(r, b_h + so);
                bh[g * 2][0] = r[0]; bh[g * 2][1] = r[2];
                bh[g * 2 + 1][0] = r[1]; bh[g * 2 + 1][1] = r[3];
                ldsm_x4(r, b_l + so);
                bl[g * 2][0] = r[0]; bl[g * 2][1] = r[2];
                bl[g * 2 + 1][0] = r[1]; bl[g * 2 + 1][1] = r[3];
            }
#pragma unroll
            for (int mf = 0; mf < 2; mf++)
#pragma unroll
                for (int nf = 0; nf < 4; nf++) mma16816(acc[mf][nf], ah[mf], bh[nf]);
#pragma unroll
            for (int mf = 0; mf < 2; mf++)
#pragma unroll
                for (int nf = 0; nf < 4; nf++) mma16816(acc[mf][nf], ah[mf], bl[nf]);
#pragma unroll
            for (int mf = 0; mf < 2; mf++)
#pragma unroll
                for (int nf = 0; nf < 4; nf++) mma16816(acc[mf][nf], al[mf], bh[nf]);
        }
        __syncthreads();
        if (c + 2 < nchunk) load_chunk(c + 2);
    }

#pragma unroll
    for (int mf = 0; mf < 2; mf++) {
        int r0 = bm + wm * 32 + mf * 16 + (lane >> 2);
#pragma unroll
        for (int nf = 0; nf < 4; nf++) {
            int col = bn + wn * 32 + nf * 8 + ((lane & 3) << 1);
            if (MODE == 0) {
                float* p0 = &out[(size_t)r0 * Nout + col];
                float* p1 = &out[(size_t)(r0 + 8) * Nout + col];
                *reinterpret_cast<float2*>(p0) = make_float2(acc[mf][nf][0], acc[mf][nf][1]);
                *reinterpret_cast<float2*>(p1) = make_float2(acc[mf][nf][2], acc[mf][nf][3]);
            } else {
                const int which = col >> 10;
                const int hh = (col >> 6) & 15;
                const int d0 = col & 63;
#pragma unroll
                for (int rr = 0; rr < 2; rr++) {
                    int r = r0 + rr * 8;
                    float v0 = acc[mf][nf][rr * 2], v1 = acc[mf][nf][rr * 2 + 1];
                    int b = r >> 12, n = r & 4095;
                    int bhn = b * 16 + hh;
                    __nv_bfloat16 h0, l0, h1, l1;
                    split_hl(v0, h0, l0); split_hl(v1, h1, l1);
                    if (which == 0) {
                        size_t o = ((size_t)bhn * 4096 + n) * 64 + d0;
                        *reinterpret_cast<__nv_bfloat162*>(&g_qh[o]) = __nv_bfloat162(h0, h1);
                        *reinterpret_cast<__nv_bfloat162*>(&g_ql[o]) = __nv_bfloat162(l0, l1);
                    } else if (which == 1) {
                        size_t o = ((size_t)bhn * 4096 + n) * 64 + d0;
                        *reinterpret_cast<__nv_bfloat162*>(&g_kh[o]) = __nv_bfloat162(h0, h1);
                        *reinterpret_cast<__nv_bfloat162*>(&g_kl[o]) = __nv_bfloat162(l0, l1);
                    } else {
                        size_t o0 = ((size_t)bhn * 64 + d0) * 4096 + n;
                        size_t o1 = ((size_t)bhn * 64 + d0 + 1) * 4096 + n;
                        g_vth[o0] = h0; g_vtl[o0] = l0;
                        g_vth[o1] = h1; g_vtl[o1] = l1;
                    }
                }
            }
        }
    }
}

// ================= mid-section tensor kernels =================
// Shared geometry (256 thr, 8 warps): M=128. For N=128: wm=wid>>2 (64 rows), wn=wid&3 (32 cols),
// mf<4, nf<4. For N=64: wm=wid>>1 (32 rows), wn=wid&1 (32 cols), mf<2, nf<4.

// ---------------- qa_sim + fused softmax over m ----------------
// C[n=128, m=128] = q[128,64] @ a[128,64]^T ; bf16x3; softmax over cols via smem C.
#define QSIM_SMEM (1024 + 68608)
__global__ __launch_bounds__(256) void qa_sim_tc_kernel() {
    extern __shared__ char dsm[];
    uint32_t sraw = smem_u32(dsm);
    uint32_t sbase = (sraw + 1023u) & ~1023u;
    float* Cs = reinterpret_cast<float*>(dsm + (sbase - sraw));

    const int tid = threadIdx.x;
    const int lane = tid & 31;
    const int wid = tid >> 5;
    const int wm = wid >> 2, wn = wid & 3;
    const int bh = blockIdx.y;
    const int h = bh & 15;
    const int bm = blockIdx.x * 128;

    const __nv_bfloat16* Ahp = g_qh + (size_t)bh * NSEQ * DHEAD;
    const __nv_bfloat16* Alp = g_ql + (size_t)bh * NSEQ * DHEAD;
    const __nv_bfloat16* Bhp = g_ah + (size_t)h * MAG * DHEAD;
    const __nv_bfloat16* Blp = g_al + (size_t)h * MAG * DHEAD;

#pragma unroll
    for (int i = 0; i < 4; i++) {
        int u = tid + i * 256;
        int r = u >> 3, cb = (u & 7) << 4;
        uint32_t so = SMEM_SWIZZLE_128B(r * 128 + cb);
        cp_async16(sbase + 0 * 16384 + so, Ahp + (size_t)(bm + r) * 64 + (cb >> 1));
        cp_async16(sbase + 1 * 16384 + so, Alp + (size_t)(bm + r) * 64 + (cb >> 1));
        cp_async16(sbase + 2 * 16384 + so, Bhp + (size_t)r * 64 + (cb >> 1));
        cp_async16(sbase + 3 * 16384 + so, Blp + (size_t)r * 64 + (cb >> 1));
    }
    CP_COMMIT(); CP_WAIT(0);
    __syncthreads();

    float acc[4][4][4];
#pragma unroll
    for (int i = 0; i < 4; i++)
#pragma unroll
        for (int j = 0; j < 4; j++)
#pragma unroll
            for (int v = 0; v < 4; v++) acc[i][j][v] = 0.f;

    const int lrow = lane & 15;
    const int lksel = (lane >> 4) << 4;
    const uint32_t a_h = sbase, a_l = sbase + 16384;
    const uint32_t b_h = sbase + 32768, b_l = sbase + 49152;
#pragma unroll
    for (int ks = 0; ks < 4; ks++) {
        const int kb = ks * 32 + lksel;
        uint32_t ah[4][4], al[4][4], bh2[4][2], bl2[4][2];
#pragma unroll
        for (int mf = 0; mf < 4; mf++) {
            int row = wm * 64 + mf * 16 + lrow;
            uint32_t so = SMEM_SWIZZLE_128B(row * 128 + kb);
            ldsm_x4(ah[mf], a_h + so);
            ldsm_x4(al[mf], a_l + so);
        }
#pragma unroll
        for (int g = 0; g < 2; g++) {
            int row = wn * 32 + g * 16 + lrow;
            uint32_t so = SMEM_SWIZZLE_128B(row * 128 + kb);
            uint32_t r[4];
            ldsm_x4(r, b_h + so);
            bh2[g * 2][0] = r[0]; bh2[g * 2][1] = r[2];
            bh2[g * 2 + 1][0] = r[1]; bh2[g * 2 + 1][1] = r[3];
            ldsm_x4(r, b_l + so);
            bl2[g * 2][0] = r[0]; bl2[g * 2][1] = r[2];
            bl2[g * 2 + 1][0] = r[1]; bl2[g * 2 + 1][1] = r[3];
        }
#pragma unroll
        for (int mf = 0; mf < 4; mf++)
#pragma unroll
            for (int nf = 0; nf < 4; nf++) mma16816(acc[mf][nf], ah[mf], bh2[nf]);
#pragma unroll
        for (int mf = 0; mf < 4; mf++)
#pragma unroll
            for (int nf = 0; nf < 4; nf++) mma16816(acc[mf][nf], ah[mf], bl2[nf]);
#pragma unroll
        for (int mf = 0; mf < 4; mf++)
#pragma unroll
            for (int nf = 0; nf < 4; nf++) mma16816(acc[mf][nf], al[mf], bh2[nf]);
    }
    __syncthreads();   // done reading operand smem; reuse as C

#pragma unroll
    for (int mf = 0; mf < 4; mf++) {
        int rl = wm * 64 + mf * 16 + (lane >> 2);
#pragma unroll
        for (int nf = 0; nf < 4; nf++) {
            int col = wn * 32 + nf * 8 + ((lane & 3) << 1);
            Cs[rl * 132 + col] = acc[mf][nf][0];
            Cs[rl * 132 + col + 1] = acc[mf][nf][1];
            Cs[(rl + 8) * 132 + col] = acc[mf][nf][2];
            Cs[(rl + 8) * 132 + col + 1] = acc[mf][nf][3];
        }
    }
    __syncthreads();

    // softmax over m (row-wise, 128 per row); warp wid handles rows wid*16..+15
#pragma unroll
    for (int i = 0; i < 16; i++) {
        int row = wid * 16 + i;
        float4 v = *reinterpret_cast<float4*>(&Cs[row * 132 + lane * 4]);
        float mx = warp_max(fmaxf(fmaxf(v.x, v.y), fmaxf(v.z, v.w)));
        v.x = __expf(v.x - mx); v.y = __expf(v.y - mx);
        v.z = __expf(v.z - mx); v.w = __expf(v.w - mx);
        float sm = warp_sum(v.x + v.y + v.z + v.w);
        float inv = 1.f / sm;
        v.x *= inv; v.y *= inv; v.z *= inv; v.w *= inv;
        *reinterpret_cast<float4*>(&g_qa[((size_t)bh * NSEQ + bm + row) * MAG + lane * 4]) = v;
    }
}

// ---------------- ak_sim: C[m=128, n-tile=128] = a[128,64] @ k[128,64]^T + mask ----------------
#define AKSIM_SMEM (1024 + 65536)
__global__ __launch_bounds__(256) void ak_sim_tc_kernel() {
    extern __shared__ char dsm[];
    uint32_t sraw = smem_u32(dsm);
    uint32_t sbase = (sraw + 1023u) & ~1023u;

    const int tid = threadIdx.x;
    const int lane = tid & 31;
    const int wid = tid >> 5;
    const int wm = wid >> 2, wn = wid & 3;
    const int bh = blockIdx.y;
    const int b = bh >> 4, h = bh & 15;
    const int bn = blockIdx.x * 128;

    const __nv_bfloat16* Ahp = g_ah + (size_t)h * MAG * DHEAD;
    const __nv_bfloat16* Alp = g_al + (size_t)h * MAG * DHEAD;
    const __nv_bfloat16* Bhp = g_kh + (size_t)bh * NSEQ * DHEAD;
    const __nv_bfloat16* Blp = g_kl + (size_t)bh * NSEQ * DHEAD;

#pragma unroll
    for (int i = 0; i < 4; i++) {
        int u = tid + i * 256;
        int r = u >> 3, cb = (u & 7) << 4;
        uint32_t so = SMEM_SWIZZLE_128B(r * 128 + cb);
        cp_async16(sbase + 0 * 16384 + so, Ahp + (size_t)r * 64 + (cb >> 1));
        cp_async16(sbase + 1 * 16384 + so, Alp + (size_t)r * 64 + (cb >> 1));
        cp_async16(sbase + 2 * 16384 + so, Bhp + (size_t)(bn + r) * 64 + (cb >> 1));
        cp_async16(sbase + 3 * 16384 + so, Blp + (size_t)(bn + r) * 64 + (cb >> 1));
    }
    CP_COMMIT(); CP_WAIT(0);
    __syncthreads();

    float acc[4][4][4];
#pragma unroll
    for (int i = 0; i < 4; i++)
#pragma unroll
        for (int j = 0; j < 4; j++)
#pragma unroll
            for (int v = 0; v < 4; v++) acc[i][j][v] = 0.f;

    const int lrow = lane & 15;
    const int lksel = (lane >> 4) << 4;
    const uint32_t a_h = sbase, a_l = sbase + 16384;
    const uint32_t b_h = sbase + 32768, b_l = sbase + 49152;
#pragma unroll
    for (int ks = 0; ks < 4; ks++) {
        const int kb = ks * 32 + lksel;
        uint32_t ah[4][4], al[4][4], bh2[4][2], bl2[4][2];
#pragma unroll
        for (int mf = 0; mf < 4; mf++) {
            int row = wm * 64 + mf * 16 + lrow;
            uint32_t so = SMEM_SWIZZLE_128B(row * 128 + kb);
            ldsm_x4(ah[mf], a_h + so);
            ldsm_x4(al[mf], a_l + so);
        }
#pragma unroll
        for (int g = 0; g < 2; g++) {
            int row = wn * 32 + g * 16 + lrow;
            uint32_t so = SMEM_SWIZZLE_128B(row * 128 + kb);
            uint32_t r[4];
            ldsm_x4(r, b_h + so);
            bh2[g * 2][0] = r[0]; bh2[g * 2][1] = r[2];
            bh2[g * 2 + 1][0] = r[1]; bh2[g * 2 + 1][1] = r[3];
            ldsm_x4(r, b_l + so);
            bl2[g * 2][0] = r[0]; bl2[g * 2][1] = r[2];
            bl2[g * 2 + 1][0] = r[1]; bl2[g * 2 + 1][1] = r[3];
        }
#pragma unroll
        for (int mf = 0; mf < 4; mf++)
#pragma unroll
            for (int nf = 0; nf < 4; nf++) mma16816(acc[mf][nf], ah[mf], bh2[nf]);
#pragma unroll
        for (int mf = 0; mf < 4; mf++)
#pragma unroll
            for (int nf = 0; nf < 4; nf++) mma16816(acc[mf][nf], ah[mf], bl2[nf]);
#pragma unroll
        for (int mf = 0; mf < 4; mf++)
#pragma unroll
            for (int nf = 0; nf < 4; nf++) mma16816(acc[mf][nf], al[mf], bh2[nf]);
    }

#pragma unroll
    for (int mf = 0; mf < 4; mf++) {
        int r0 = wm * 64 + mf * 16 + (lane >> 2);   // m index
#pragma unroll
        for (int nf = 0; nf < 4; nf++) {
            int col = bn + wn * 32 + nf * 8 + ((lane & 3) << 1);   // n index
            float mv0 = g_maskf[b * NSEQ + col];
            float mv1 = g_maskf[b * NSEQ + col + 1];
            float* p0 = &g_ak[((size_t)bh * MAG + r0) * NSEQ + col];
            float* p1 = &g_ak[((size_t)bh * MAG + r0 + 8) * NSEQ + col];
            *reinterpret_cast<float2*>(p0) = make_float2(
                mv0 != 0.f ? acc[mf][nf][0] : -FLT_MAX, mv1 != 0.f ? acc[mf][nf][1] : -FLT_MAX);
            *reinterpret_cast<float2*>(p1) = make_float2(
                mv0 != 0.f ? acc[mf][nf][2] : -FLT_MAX, mv1 != 0.f ? acc[mf][nf][3] : -FLT_MAX);
        }
    }
}

// ---------------- ak row stats ----------------
__global__ __launch_bounds__(256) void ak_stats_kernel() {
    const int row = blockIdx.x;
    const int t = threadIdx.x;
    const float* p = g_ak + (size_t)row * NSEQ;
    float4 v[4];
    float mx = -FLT_MAX;
#pragma unroll
    for (int i = 0; i < 4; i++) {
        v[i] = *reinterpret_cast<const float4*>(&p[t * 16 + i * 4]);
        mx = fmaxf(mx, fmaxf(fmaxf(v[i].x, v[i].y), fmaxf(v[i].z, v[i].w)));
    }
    __shared__ float red[8];
    int wid = t >> 5, lane = t & 31;
    float wm = warp_max(mx);
    if (lane == 0) red[wid] = wm;
    __syncthreads();
    float m = red[0];
#pragma unroll
    for (int i = 1; i < 8; i++) m = fmaxf(m, red[i]);
    float sacc = 0.f;
#pragma unroll
    for (int i = 0; i < 4; i++)
        sacc += __expf(v[i].x - m) + __expf(v[i].y - m) + __expf(v[i].z - m) + __expf(v[i].w - m);
    float ws = warp_sum(sacc);
    __syncthreads();
    if (lane == 0) red[wid] = ws;
    __syncthreads();
    if (t == 0) {
        float tot = 0.f;
#pragma unroll
        for (int i = 0; i < 8; i++) tot += red[i];
        g_akstat[row] = make_float2(m, 1.f / tot);
    }
}

// ---------------- fused exp-normalize + head mix (ak) -> bf16 h/l ----------------
__global__ __launch_bounds__(256) void mix_ak_exp_kernel(const float* __restrict__ Wm) {
    __shared__ float Ws[256];
    if (threadIdx.x < 256) Ws[threadIdx.x] = Wm[threadIdx.x];
    __syncthreads();
    const size_t R = (size_t)MAG * NSEQ;
    size_t pos = (size_t)blockIdx.x * blockDim.x + threadIdx.x;
    if (pos >= (size_t)NB * R) return;
    size_t b = pos / R, r = pos % R;
    int m = (int)(r >> 12);
    const float* p = g_ak + b * 16 * R + r;
    float x[16];
#pragma unroll
    for (int h = 0; h < 16; h++) {
        float2 st = g_akstat[(b * 16 + h) * MAG + m];
        x[h] = __expf(p[h * R] - st.x) * st.y;
    }
#pragma unroll
    for (int g = 0; g < 16; g++) {
        float sacc = 0.f;
#pragma unroll
        for (int h = 0; h < 16; h++) sacc = fmaf(Ws[g * 16 + h], x[h], sacc);
        __nv_bfloat16 hh, ll;
        split_hl(sacc, hh, ll);
        size_t o = b * 16 * R + g * R + r;
        g_akmh[o] = hh; g_akml[o] = ll;
    }
}

// ---------------- talking heads (qa) -> bf16 h/l ----------------
__global__ __launch_bounds__(256) void mix_heads_kernel(const float* __restrict__ Wm) {
    __shared__ float Ws[256];
    if (threadIdx.x < 256) Ws[threadIdx.x] = Wm[threadIdx.x];
    __syncthreads();
    const size_t R = (size_t)NSEQ * MAG;
    size_t pos = (size_t)blockIdx.x * blockDim.x + threadIdx.x;
    if (pos >= (size_t)NB * R) return;
    size_t b = pos / R, r = pos % R;
    const float* p = g_qa + b * 16 * R + r;
    float x[16];
#pragma unroll
    for (int h = 0; h < 16; h++) x[h] = p[h * R];
#pragma unroll
    for (int g = 0; g < 16; g++) {
        float sacc = 0.f;
#pragma unroll
        for (int h = 0; h < 16; h++) sacc = fmaf(Ws[g * 16 + h], x[h], sacc);
        __nv_bfloat16 hh, ll;
        split_hl(sacc, hh, ll);
        size_t o = b * 16 * R + g * R + r;
        g_qamh[o] = hh; g_qaml[o] = ll;
    }
}

// ---------------- agent_out: C[m=128, d=64] = akm[128,4096] @ vT[64,4096]^T, split-K=4 ----------------
// 256 thr: wm=wid>>1 (0..3), wn=wid&1; mf<2, nf<4. BK=64, 2-stage.
#define AO_STAGE 49152   // Ah 16K | Al 16K | Bh 8K | Bl 8K
#define AO_SMEM  (1024 + 2 * AO_STAGE)
__global__ __launch_bounds__(256) void agent_out_tc_kernel() {
    extern __shared__ char dsm[];
    uint32_t sraw = smem_u32(dsm);
    uint32_t sbase = (sraw + 1023u) & ~1023u;

    const int tid = threadIdx.x;
    const int lane = tid & 31;
    const int wid = tid >> 5;
    const int wm = wid >> 1, wn = wid & 1;
    const int sp = blockIdx.x;     // 0..3
    const int bh = blockIdx.y;

    const __nv_bfloat16* Ahp = g_akmh + (size_t)bh * MAG * NSEQ;
    const __nv_bfloat16* Alp = g_akml + (size_t)bh * MAG * NSEQ;
    const __nv_bfloat16* Bhp = g_vth + (size_t)bh * DHEAD * NSEQ;
    const __nv_bfloat16* Blp = g_vtl + (size_t)bh * DHEAD * NSEQ;

    float acc[2][4][4];
#pragma unroll
    for (int i = 0; i < 2; i++)
#pragma unroll
        for (int j = 0; j < 4; j++)
#pragma unroll
            for (int v = 0; v < 4; v++) acc[i][j][v] = 0.f;

    const int kbase = sp * 1024;
    const int nchunk = 16;

    auto load_chunk = [&](int c) {
        const uint32_t sb = sbase + (c & 1) * AO_STAGE;
        const int k0 = kbase + (c << 6);
#pragma unroll
        for (int i = 0; i < 4; i++) {
            int u = tid + i * 256;
            int r = u >> 3, cb = (u & 7) << 4;
            uint32_t so = SMEM_SWIZZLE_128B(r * 128 + cb);
            cp_async16(sb + so,         Ahp + (size_t)r * 4096 + k0 + (cb >> 1));
            cp_async16(sb + 16384 + so, Alp + (size_t)r * 4096 + k0 + (cb >> 1));
        }
#pragma unroll
        for (int i = 0; i < 2; i++) {
            int u = tid + i * 256;
            int r = u >> 3, cb = (u & 7) << 4;
            uint32_t so = SMEM_SWIZZLE_128B(r * 128 + cb);
            cp_async16(sb + 32768 + so, Bhp + (size_t)r * 4096 + k0 + (cb >> 1));
            cp_async16(sb + 40960 + so, Blp + (size_t)r * 4096 + k0 + (cb >> 1));
        }
        CP_COMMIT();
    };

    load_chunk(0);
    load_chunk(1);

    const int lrow = lane & 15;
    const int lksel = (lane >> 4) << 4;

    for (int c = 0; c < nchunk; c++) {
        if (c + 1 < nchunk) { CP_WAIT(1); } else { CP_WAIT(0); }
        __syncthreads();
        const uint32_t sb = sbase + (c & 1) * AO_STAGE;
        const uint32_t a_h = sb, a_l = sb + 16384;
        const uint32_t b_h = sb + 32768, b_l = sb + 40960;
#pragma unroll
        for (int ks = 0; ks < 4; ks++) {
            const int kb = ks * 32 + lksel;
            uint32_t ah[2][4], al[2][4], bh2[4][2], bl2[4][2];
#pragma unroll
            for (int mf = 0; mf < 2; mf++) {
                int row = wm * 32 + mf * 16 + lrow;
                uint32_t so = SMEM_SWIZZLE_128B(row * 128 + kb);
                ldsm_x4(ah[mf], a_h + so);
                ldsm_x4(al[mf], a_l + so);
            }
#pragma unroll
            for (int g = 0; g < 2; g++) {
                int row = wn * 32 + g * 16 + lrow;
                uint32_t so = SMEM_SWIZZLE_128B(row * 128 + kb);
                uint32_t r[4];
                ldsm_x4(r, b_h + so);
                bh2[g * 2][0] = r[0]; bh2[g * 2][1] = r[2];
                bh2[g * 2 + 1][0] = r[1]; bh2[g * 2 + 1][1] = r[3];
                ldsm_x4(r, b_l + so);
                bl2[g * 2][0] = r[0]; bl2[g * 2][1] = r[2];
                bl2[g * 2 + 1][0] = r[1]; bl2[g * 2 + 1][1] = r[3];
            }
#pragma unroll
            for (int mf = 0; mf < 2; mf++)
#pragma unroll
                for (int nf = 0; nf < 4; nf++) mma16816(acc[mf][nf], ah[mf], bh2[nf]);
#pragma unroll
            for (int mf = 0; mf < 2; mf++)
#pragma unroll
                for (int nf = 0; nf < 4; nf++) mma16816(acc[mf][nf], ah[mf], bl2[nf]);
#pragma unroll
            for (int mf = 0; mf < 2; mf++)
#pragma unroll
                for (int nf = 0; nf < 4; nf++) mma16816(acc[mf][nf], al[mf], bh2[nf]);
        }
        __syncthreads();
        if (c + 2 < nchunk) load_chunk(c + 2);
    }

    float* P = g_agent_part + ((size_t)sp * BHN + bh) * (MAG * DHEAD);
#pragma unroll
    for (int mf = 0; mf < 2; mf++) {
        int r0 = wm * 32 + mf * 16 + (lane >> 2);
#pragma unroll
        for (int nf = 0; nf < 4; nf++) {
            int col = wn * 32 + nf * 8 + ((lane & 3) << 1);
            *reinterpret_cast<float2*>(&P[(size_t)r0 * 64 + col]) =
                make_float2(acc[mf][nf][0], acc[mf][nf][1]);
            *reinterpret_cast<float2*>(&P[(size_t)(r0 + 8) * 64 + col]) =
                make_float2(acc[mf][nf][2], acc[mf][nf][3]);
        }
    }
}

// ---------------- reduce split-K, emit agent^T bf16 h/l [bh,d,m] ----------------
__global__ __launch_bounds__(256) void reduce_agent_kernel() {
    int i = blockIdx.x * 256 + threadIdx.x;    // < 524288
    float sacc = 0.f;
#pragma unroll
    for (int k = 0; k < 4; k++) sacc += g_agent_part[(size_t)k * (BHN * MAG * DHEAD) + i];
    int bh = i >> 13;
    int rem = i & 8191;
    int m = rem >> 6, d = rem & 63;
    __nv_bfloat16 hh, ll;
    split_hl(sacc, hh, ll);
    size_t o = ((size_t)bh * 64 + d) * 128 + m;
    g_agth[o] = hh; g_agtl[o] = ll;
}

// ---------------- out_mid: C[n=128, d=64] = qam[128,128] @ agtT[64,128]^T, mask, bf16 out ----------------
__global__ __launch_bounds__(256) void out_mid_tc_kernel() {
    extern __shared__ char dsm[];
    uint32_t sraw = smem_u32(dsm);
    uint32_t sbase = (sraw + 1023u) & ~1023u;

    const int tid = threadIdx.x;
    const int lane = tid & 31;
    const int wid = tid >> 5;
    const int wm = wid >> 1, wn = wid & 1;
    const int bh = blockIdx.y;
    const int b = bh >> 4, h = bh & 15;
    const int bm = blockIdx.x * 128;

    const __nv_bfloat16* Ahp = g_qamh + (size_t)bh * NSEQ * MAG;
    const __nv_bfloat16* Alp = g_qaml + (size_t)bh * NSEQ * MAG;
    const __nv_bfloat16* Bhp = g_agth + (size_t)bh * DHEAD * MAG;
    const __nv_bfloat16* Blp = g_agtl + (size_t)bh * DHEAD * MAG;

    // load both K-chunks (K=128 -> 2 x BK=64)
#pragma unroll
    for (int c = 0; c < 2; c++) {
        const uint32_t sb = sbase + c * AO_STAGE;
        const int k0 = c << 6;
#pragma unroll
        for (int i = 0; i < 4; i++) {
            int u = tid + i * 256;
            int r = u >> 3, cb = (u & 7) << 4;
            uint32_t so = SMEM_SWIZZLE_128B(r * 128 + cb);
            cp_async16(sb + so,         Ahp + (size_t)(bm + r) * 128 + k0 + (cb >> 1));
            cp_async16(sb + 16384 + so, Alp + (size_t)(bm + r) * 128 + k0 + (cb >> 1));
        }
#pragma unroll
        for (int i = 0; i < 2; i++) {
            int u = tid + i * 256;
            int r = u >> 3, cb = (u & 7) << 4;
            uint32_t so = SMEM_SWIZZLE_128B(r * 128 + cb);
            cp_async16(sb + 32768 + so, Bhp + (size_t)r * 128 + k0 + (cb >> 1));
            cp_async16(sb + 40960 + so, Blp + (size_t)r * 128 + k0 + (cb >> 1));
        }
        CP_COMMIT();
    }
    CP_WAIT(0);
    __syncthreads();

    float acc[2][4][4];
#pragma unroll
    for (int i = 0; i < 2; i++)
#pragma unroll
        for (int j = 0; j < 4; j++)
#pragma unroll
            for (int v = 0; v < 4; v++) acc[i][j][v] = 0.f;

    const int lrow = lane & 15;
    const int lksel = (lane >> 4) << 4;
#pragma unroll
    for (int c = 0; c < 2; c++) {
        const uint32_t sb = sbase + c * AO_STAGE;
        const uint32_t a_h = sb, a_l = sb + 16384;
        const uint32_t b_h = sb + 32768, b_l = sb + 40960;
#pragma unroll
        for (int ks = 0; ks < 4; ks++) {
            const int kb = ks * 32 + lksel;
            uint32_t ah[2][4], al[2][4], bh2[4][2], bl2[4][2];
#pragma unroll
            for (int mf = 0; mf < 2; mf++) {
                int row = wm * 32 + mf * 16 + lrow;
                uint32_t so = SMEM_SWIZZLE_128B(row * 128 + kb);
                ldsm_x4(ah[mf], a_h + so);
                ldsm_x4(al[mf], a_l + so);
            }
#pragma unroll
            for (int g = 0; g < 2; g++) {
                int row = wn * 32 + g * 16 + lrow;
                uint32_t so = SMEM_SWIZZLE_128B(row * 128 + kb);
                uint32_t r[4];
                ldsm_x4(r, b_h + so);
                bh2[g * 2][0] = r[0]; bh2[g * 2][1] = r[2];
                bh2[g * 2 + 1][0] = r[1]; bh2[g * 2 + 1][1] = r[3];
                ldsm_x4(r, b_l + so);
                bl2[g * 2][0] = r[0]; bl2[g * 2][1] = r[2];
                bl2[g * 2 + 1][0] = r[1]; bl2[g * 2 + 1][1] = r[3];
            }
#pragma unroll
            for (int mf = 0; mf < 2; mf++)
#pragma unroll
                for (int nf = 0; nf < 4; nf++) mma16816(acc[mf][nf], ah[mf], bh2[nf]);
#pragma unroll
            for (int mf = 0; mf < 2; mf++)
#pragma unroll
                for (int nf = 0; nf < 4; nf++) mma16816(acc[mf][nf], ah[mf], bl2[nf]);
#pragma unroll
            for (int mf = 0; mf < 2; mf++)
#pragma unroll
                for (int nf = 0; nf < 4; nf++) mma16816(acc[mf][nf], al[mf], bh2[nf]);
        }
    }

#pragma unroll
    for (int mf = 0; mf < 2; mf++) {
        int r0 = wm * 32 + mf * 16 + (lane >> 2);
#pragma unroll
        for (int nf = 0; nf < 4; nf++) {
            int col = wn * 32 + nf * 8 + ((lane & 3) << 1);   // d pair
#pragma unroll
            for (int rr = 0; rr < 2; rr++) {
                int rn = bm + r0 + rr * 8;
                float mv = g_maskf[b * NSEQ + rn];
                float v0 = acc[mf][nf][rr * 2] * mv, v1 = acc[mf][nf][rr * 2 + 1] * mv;
                __nv_bfloat16 h0, l0, h1, l1;
                split_hl(v0, h0, l0); split_hl(v1, h1, l1);
                size_t o = ((size_t)b * NSEQ + rn) * DIMX + h * 64 + col;
                *reinterpret_cast<__nv_bfloat162*>(&g_midh[o]) = __nv_bfloat162(h0, h1);
                *reinterpret_cast<__nv_bfloat162*>(&g_midl[o]) = __nv_bfloat162(l0, l1);
            }
        }
    }
}

// ---------------- launcher ----------------
extern "C" void kernel_launch(void* const* d_in, const int* in_sizes, int n_in,
                              void* d_out, int out_size) {
    const float* x     = (const float*)d_in[0];
    const void*  mask  = d_in[1];
    const float* Wqkv  = (const float*)d_in[2];
    const float* agent = (const float*)d_in[3];
    const float* Wqa   = (const float*)d_in[4];
    const float* Wak   = (const float*)d_in[5];
    const float* Wout  = (const float*)d_in[6];
    float* out = (float*)d_out;
    (void)in_sizes; (void)n_in; (void)out_size;

    cudaFuncSetAttribute(gemm_mma_kernel<0>, cudaFuncAttributeMaxDynamicSharedMemorySize, GT_SMEM);
    cudaFuncSetAttribute(gemm_mma_kernel<1>, cudaFuncAttributeMaxDynamicSharedMemorySize, GT_SMEM);
    cudaFuncSetAttribute(qa_sim_tc_kernel, cudaFuncAttributeMaxDynamicSharedMemorySize, QSIM_SMEM);
    cudaFuncSetAttribute(ak_sim_tc_kernel, cudaFuncAttributeMaxDynamicSharedMemorySize, AKSIM_SMEM);
    cudaFuncSetAttribute(agent_out_tc_kernel, cudaFuncAttributeMaxDynamicSharedMemorySize, AO_SMEM);
    cudaFuncSetAttribute(out_mid_tc_kernel, cudaFuncAttributeMaxDynamicSharedMemorySize, AO_SMEM);

    __nv_bfloat16 *xh, *xl, *wqh, *wql, *woh, *wol, *mh, *ml;
    cudaGetSymbolAddress((void**)&xh,  g_xh);
    cudaGetSymbolAddress((void**)&xl,  g_xl);
    cudaGetSymbolAddress((void**)&wqh, g_wqkvh);
    cudaGetSymbolAddress((void**)&wql, g_wqkvl);
    cudaGetSymbolAddress((void**)&woh, g_wouth);
    cudaGetSymbolAddress((void**)&wol, g_woutl);
    cudaGetSymbolAddress((void**)&mh,  g_midh);
    cudaGetSymbolAddress((void**)&ml,  g_midl);

    mask_expand_kernel<<<1, 1024>>>(mask);
    conv_split_kernel<<<(NB * NSEQ * DIMX / 4 + 255) / 256, 256>>>(x, xh, xl, NB * NSEQ * DIMX / 4);
    conv_wt_kernel<<<dim3(96, 32), 256>>>(Wqkv, wqh, wql, 1024, 3072);
    conv_wt_kernel<<<dim3(32, 32), 256>>>(Wout, woh, wol, 1024, 1024);
    conv_agent_kernel<<<(HEADS * MAG * DHEAD / 4 + 255) / 256, 256>>>(agent);

    gemm_mma_kernel<1><<<dim3(24, 128), 512, GT_SMEM>>>(xh, xl, wqh, wql, nullptr, 1024, 3072);

    qa_sim_tc_kernel<<<dim3(32, 64), 256, QSIM_SMEM>>>();
    ak_sim_tc_kernel<<<dim3(32, 64), 256, AKSIM_SMEM>>>();
    ak_stats_kernel<<<BHN * MAG, 256>>>();
    mix_heads_kernel<<<8192, 256>>>(Wqa);
    mix_ak_exp_kernel<<<8192, 256>>>(Wak);
    agent_out_tc_kernel<<<dim3(4, 64), 256, AO_SMEM>>>();
    reduce_agent_kernel<<<(BHN * MAG * DHEAD) / 256, 256>>>();
    out_mid_tc_kernel<<<dim3(32, 64), 256, AO_SMEM>>>();

    gemm_mma_kernel<0><<<dim3(8, 128), 512, GT_SMEM>>>(mh, ml, woh, wol, out, 1024, 1024);
}

// round 11
// speedup vs baseline: 2.2994x; 1.3144x over previous
#include <cuda_runtime.h>
#include <cuda_fp16.h>
#include <stdint.h>
#include <float.h>

// ---------------- problem constants ----------------
#define NB    4
#define NSEQ  4096
#define DIMX  1024
#define HEADS 16
#define DHEAD 64
#define MAG   128
#define BHN   (NB * HEADS)
#define SCALE 0.125f

// ---------------- scratch (device globals; no allocation) ----------------
__device__ float g_qa[NB * HEADS * NSEQ * MAG];        // fp32 qa attn (softmaxed)
__device__ float g_ak[NB * HEADS * MAG * NSEQ];        // fp32 ak logits (masked)
__device__ float g_agent_part[4 * BHN * MAG * DHEAD];  // split-K partials
__device__ float g_maskf[NB * NSEQ];
__device__ float2 g_akstat[BHN * MAG];

// fp16 operands. A-side operands are hi/lo split; B-side operands are single fp16.
__device__ __half g_xh[NB * NSEQ * DIMX];
__device__ __half g_xl[NB * NSEQ * DIMX];
__device__ __half g_wqkv[3 * DIMX * DIMX];             // Wqkv^T [3072,1024] single
__device__ __half g_wout[DIMX * DIMX];                 // Wout^T single
__device__ __half g_qh[BHN * NSEQ * DHEAD];            // q hi [bh,n,d]
__device__ __half g_ql[BHN * NSEQ * DHEAD];            // q lo
__device__ __half g_k1[BHN * NSEQ * DHEAD];            // k single [bh,n,d]
__device__ __half g_vt[BHN * DHEAD * NSEQ];            // v^T single [bh,d,n]
__device__ __half g_ah[HEADS * MAG * DHEAD];           // agent*SCALE hi (also B-single)
__device__ __half g_al[HEADS * MAG * DHEAD];           // agent*SCALE lo
__device__ __half g_qamh[NB * HEADS * NSEQ * MAG];     // mixed qa hi [bh,n,m]
__device__ __half g_qaml[NB * HEADS * NSEQ * MAG];
__device__ __half g_akmh[NB * HEADS * MAG * NSEQ];     // mixed ak attn hi [bh,m,n]
__device__ __half g_akml[NB * HEADS * MAG * NSEQ];
__device__ __half g_agt[BHN * DHEAD * MAG];            // agent_out^T single [bh,d,m]
__device__ __half g_midh[NB * NSEQ * DIMX];
__device__ __half g_midl[NB * NSEQ * DIMX];

// ---------------- PTX helpers ----------------
__device__ __forceinline__ uint32_t smem_u32(const void* p) {
    uint32_t a;
    asm("{ .reg .u64 t; cvta.to.shared.u64 t, %1; cvt.u32.u64 %0, t; }" : "=r"(a) : "l"(p));
    return a;
}
#define SMEM_SWIZZLE_128B(o) ((o) ^ (((o) >> 3) & 0x70))

__device__ __forceinline__ void cp_async16(uint32_t sa, const void* g) {
    asm volatile("cp.async.cg.shared.global [%0], [%1], 16;" :: "r"(sa), "l"(g));
}
#define CP_COMMIT() asm volatile("cp.async.commit_group;" ::: "memory")
#define CP_WAIT(n)  asm volatile("cp.async.wait_group %0;" :: "n"(n) : "memory")

__device__ __forceinline__ void ldsm_x4(uint32_t* r, uint32_t a) {
    asm volatile("ldmatrix.sync.aligned.m8n8.x4.shared.b16 {%0,%1,%2,%3}, [%4];"
                 : "=r"(r[0]), "=r"(r[1]), "=r"(r[2]), "=r"(r[3]) : "r"(a));
}
__device__ __forceinline__ void mma16816(float* c, const uint32_t* a, const uint32_t* b) {
    asm volatile("mma.sync.aligned.m16n8k16.row.col.f32.f16.f16.f32 "
                 "{%0,%1,%2,%3}, {%4,%5,%6,%7}, {%8,%9}, {%0,%1,%2,%3};"
                 : "+f"(c[0]), "+f"(c[1]), "+f"(c[2]), "+f"(c[3])
                 : "r"(a[0]), "r"(a[1]), "r"(a[2]), "r"(a[3]), "r"(b[0]), "r"(b[1]));
}

__device__ __forceinline__ float warp_max(float v) {
#pragma unroll
    for (int o = 16; o > 0; o >>= 1) v = fmaxf(v, __shfl_xor_sync(0xffffffffu, v, o));
    return v;
}
__device__ __forceinline__ float warp_sum(float v) {
#pragma unroll
    for (int o = 16; o > 0; o >>= 1) v += __shfl_xor_sync(0xffffffffu, v, o);
    return v;
}
__device__ __forceinline__ void split_hl(float v, __half& h, __half& l) {
    h = __float2half_rn(v);
    l = __float2half_rn(v - __half2float(h));
}

// ---------------- mask dtype detection + expansion ----------------
__global__ void mask_expand_kernel(const void* __restrict__ mraw) {
    __shared__ int s_weird, s_off;
    const unsigned char* mb = (const unsigned char*)mraw;
    if (threadIdx.x == 0) { s_weird = 0; s_off = 0; }
    __syncthreads();
    int weird = 0, off = 0;
    for (int i = threadIdx.x; i < NB * NSEQ; i += blockDim.x) {
        unsigned char c = mb[i];
        if (c > 1) weird = 1;
        if (c != 0 && (i & 3)) off = 1;
    }
    if (weird) atomicOr(&s_weird, 1);
    if (off)   atomicOr(&s_off, 1);
    __syncthreads();
    int mode = s_weird ? 2 : (s_off ? 0 : 1);
    for (int i = threadIdx.x; i < NB * NSEQ; i += blockDim.x) {
        float v;
        if (mode == 0)      v = mb[i] ? 1.f : 0.f;
        else if (mode == 1) v = ((const int*)mraw)[i] ? 1.f : 0.f;
        else                v = (((const float*)mraw)[i] != 0.f) ? 1.f : 0.f;
        g_maskf[i] = v;
    }
}

// ---------------- fp32 -> fp16 hi/lo split ----------------
__global__ __launch_bounds__(256) void conv_split_kernel(const float* __restrict__ src,
                                                         __half* __restrict__ h,
                                                         __half* __restrict__ l, int n4) {
    int i = blockIdx.x * 256 + threadIdx.x;
    if (i >= n4) return;
    float4 v = reinterpret_cast<const float4*>(src)[i];
    __half h0, h1, h2, h3, l0, l1, l2, l3;
    split_hl(v.x, h0, l0); split_hl(v.y, h1, l1);
    split_hl(v.z, h2, l2); split_hl(v.w, h3, l3);
    reinterpret_cast<__half2*>(h)[i * 2]     = __halves2half2(h0, h1);
    reinterpret_cast<__half2*>(h)[i * 2 + 1] = __halves2half2(h2, h3);
    reinterpret_cast<__half2*>(l)[i * 2]     = __halves2half2(l0, l1);
    reinterpret_cast<__half2*>(l)[i * 2 + 1] = __halves2half2(l2, l3);
}

// ---------------- agent tokens: scale + fp16 hi/lo ----------------
__global__ __launch_bounds__(256) void conv_agent_kernel(const float* __restrict__ src) {
    int i = blockIdx.x * 256 + threadIdx.x;
    if (i >= HEADS * MAG * DHEAD / 4) return;
    float4 v = reinterpret_cast<const float4*>(src)[i];
    __half h0, h1, h2, h3, l0, l1, l2, l3;
    split_hl(v.x * SCALE, h0, l0); split_hl(v.y * SCALE, h1, l1);
    split_hl(v.z * SCALE, h2, l2); split_hl(v.w * SCALE, h3, l3);
    reinterpret_cast<__half2*>(g_ah)[i * 2]     = __halves2half2(h0, h1);
    reinterpret_cast<__half2*>(g_ah)[i * 2 + 1] = __halves2half2(h2, h3);
    reinterpret_cast<__half2*>(g_al)[i * 2]     = __halves2half2(l0, l1);
    reinterpret_cast<__half2*>(g_al)[i * 2 + 1] = __halves2half2(l2, l3);
}

// ---------------- W[K,N] -> W^T[N,K] single fp16 ----------------
__global__ __launch_bounds__(256) void conv_wt_kernel(const float* __restrict__ W,
                                                      __half* __restrict__ T,
                                                      int K, int N) {
    __shared__ float t[32][33];
    int bx = blockIdx.x * 32;
    int by = blockIdx.y * 32;
    int x = threadIdx.x & 31, y0 = threadIdx.x >> 5;
#pragma unroll
    for (int y = y0; y < 32; y += 8) t[y][x] = W[(size_t)(by + y) * N + bx + x];
    __syncthreads();
#pragma unroll
    for (int y = y0; y < 32; y += 8) {
        T[(size_t)(bx + y) * K + by + x] = __float2half_rn(t[x][y]);
    }
}

// ---------------- big mma GEMM: fp16x2, 128x128 tile, BK=64, 2-stage, 512 threads ----------------
// Stage: Ah 16K | Al 16K | B 16K = 49152
#define GT_TILE  16384
#define GT_STAGE (3 * GT_TILE)
#define GT_SMEM  (1024 + 2 * GT_STAGE)   // 99328

template <int MODE>   // 0: fp32 out ; 1: qkv scatter (q hi/lo, k single, v^T single)
__global__ __launch_bounds__(512, 1) void gemm_mma_kernel(
    const __half* __restrict__ Ah, const __half* __restrict__ Al,
    const __half* __restrict__ B,
    float* __restrict__ out, int Kdim, int Nout) {
    extern __shared__ char dsm[];
    uint32_t sraw = smem_u32(dsm);
    uint32_t sbase = (sraw + 1023u) & ~1023u;

    const int tid = threadIdx.x;
    const int lane = tid & 31;
    const int wid = tid >> 5;
    const int wm = wid >> 2;
    const int wn = wid & 3;
    const int bm = blockIdx.y * 128;
    const int bn = blockIdx.x * 128;

    float acc[2][4][4];
#pragma unroll
    for (int i = 0; i < 2; i++)
#pragma unroll
        for (int j = 0; j < 4; j++)
#pragma unroll
            for (int v = 0; v < 4; v++) acc[i][j][v] = 0.f;

    const int nchunk = Kdim >> 6;
    const int lr  = tid >> 3;
    const int lc  = (tid & 7) << 4;

    auto load_chunk = [&](int c) {
        const int buf = c & 1;
        const int k0 = c << 6;
        const uint32_t sb = sbase + buf * GT_STAGE;
#pragma unroll
        for (int i = 0; i < 2; i++) {
            int r = lr + i * 64;
            uint32_t so = SMEM_SWIZZLE_128B(r * 128 + lc);
            size_t go = (size_t)(bm + r) * Kdim + k0 + (lc >> 1);
            size_t gb = (size_t)(bn + r) * Kdim + k0 + (lc >> 1);
            cp_async16(sb + 0 * GT_TILE + so, Ah + go);
            cp_async16(sb + 1 * GT_TILE + so, Al + go);
            cp_async16(sb + 2 * GT_TILE + so, B + gb);
        }
        CP_COMMIT();
    };

    load_chunk(0);
    if (nchunk > 1) load_chunk(1);

    const int lrow = lane & 15;
    const int lksel = (lane >> 4) << 4;

    for (int c = 0; c < nchunk; c++) {
        if (c + 1 < nchunk) { CP_WAIT(1); } else { CP_WAIT(0); }
        __syncthreads();
        const uint32_t sb = sbase + (c & 1) * GT_STAGE;
        const uint32_t a_h = sb, a_l = sb + GT_TILE;
        const uint32_t b_s = sb + 2 * GT_TILE;
#pragma unroll
        for (int ks = 0; ks < 4; ks++) {
            const int kb = ks * 32 + lksel;
            uint32_t ah[2][4], al[2][4], bf[4][2];
#pragma unroll
            for (int mf = 0; mf < 2; mf++) {
                int row = wm * 32 + mf * 16 + lrow;
                uint32_t so = SMEM_SWIZZLE_128B(row * 128 + kb);
                ldsm_x4(ah[mf], a_h + so);
                ldsm_x4(al[mf], a_l + so);
            }
#pragma unroll
            for (int g = 0; g < 2; g++) {
                int row = wn * 32 + g * 16 + lrow;
                uint32_t so = SMEM_SWIZZLE_128B(row * 128 + kb);
                uint32_t r[4];
                ldsm_x4(r, b_s + so);
                bf[g * 2][0] = r[0]; bf[g * 2][1] = r[2];
                bf[g * 2 + 1][0] = r[1]; bf[g * 2 + 1][1] = r[3];
            }
#pragma unroll
            for (int mf = 0; mf < 2; mf++)
#pragma unroll
                for (int nf = 0; nf < 4; nf++) mma16816(acc[mf][nf], ah[mf], bf[nf]);
#pragma unroll
            for (int mf = 0; mf < 2; mf++)
#pragma unroll
                for (int nf = 0; nf < 4; nf++) mma16816(acc[mf][nf], al[mf], bf[nf]);
        }
        __syncthreads();
        if (c + 2 < nchunk) load_chunk(c + 2);
    }

#pragma unroll
    for (int mf = 0; mf < 2; mf++) {
        int r0 = bm + wm * 32 + mf * 16 + (lane >> 2);
#pragma unroll
        for (int nf = 0; nf < 4; nf++) {
            int col = bn + wn * 32 + nf * 8 + ((lane & 3) << 1);
            if (MODE == 0) {
                float* p0 = &out[(size_t)r0 * Nout + col];
                float* p1 = &out[(size_t)(r0 + 8) * Nout + col];
                *reinterpret_cast<float2*>(p0) = make_float2(acc[mf][nf][0], acc[mf][nf][1]);
                *reinterpret_cast<float2*>(p1) = make_float2(acc[mf][nf][2], acc[mf][nf][3]);
            } else {
                const int which = col >> 10;
                const int hh = (col >> 6) & 15;
                const int d0 = col & 63;
#pragma unroll
                for (int rr = 0; rr < 2; rr++) {
                    int r = r0 + rr * 8;
                    float v0 = acc[mf][nf][rr * 2], v1 = acc[mf][nf][rr * 2 + 1];
                    int b = r >> 12, n = r & 4095;
                    int bhn = b * 16 + hh;
                    if (which == 0) {
                        __half h0, l0, h1, l1;
                        split_hl(v0, h0, l0); split_hl(v1, h1, l1);
                        size_t o = ((size_t)bhn * 4096 + n) * 64 + d0;
                        *reinterpret_cast<__half2*>(&g_qh[o]) = __halves2half2(h0, h1);
                        *reinterpret_cast<__half2*>(&g_ql[o]) = __halves2half2(l0, l1);
                    } else if (which == 1) {
                        size_t o = ((size_t)bhn * 4096 + n) * 64 + d0;
                        *reinterpret_cast<__half2*>(&g_k1[o]) =
                            __halves2half2(__float2half_rn(v0), __float2half_rn(v1));
                    } else {
                        size_t o0 = ((size_t)bhn * 64 + d0) * 4096 + n;
                        size_t o1 = ((size_t)bhn * 64 + d0 + 1) * 4096 + n;
                        g_vt[o0] = __float2half_rn(v0);
                        g_vt[o1] = __float2half_rn(v1);
                    }
                }
            }
        }
    }
}

// ================= mid-section tensor kernels (fp16x2) =================

// ---------------- qa_sim + fused softmax over m ----------------
// C[n=128, m=128] = q(h/l)[128,64] @ a(single)[128,64]^T
#define QSIM_SMEM (1024 + 68608)
__global__ __launch_bounds__(256) void qa_sim_tc_kernel() {
    extern __shared__ char dsm[];
    uint32_t sraw = smem_u32(dsm);
    uint32_t sbase = (sraw + 1023u) & ~1023u;
    float* Cs = reinterpret_cast<float*>(dsm + (sbase - sraw));

    const int tid = threadIdx.x;
    const int lane = tid & 31;
    const int wid = tid >> 5;
    const int wm = wid >> 2, wn = wid & 3;
    const int bh = blockIdx.y;
    const int h = bh & 15;
    const int bm = blockIdx.x * 128;

    const __half* Ahp = g_qh + (size_t)bh * NSEQ * DHEAD;
    const __half* Alp = g_ql + (size_t)bh * NSEQ * DHEAD;
    const __half* Bp  = g_ah + (size_t)h * MAG * DHEAD;

#pragma unroll
    for (int i = 0; i < 4; i++) {
        int u = tid + i * 256;
        int r = u >> 3, cb = (u & 7) << 4;
        uint32_t so = SMEM_SWIZZLE_128B(r * 128 + cb);
        cp_async16(sbase + 0 * 16384 + so, Ahp + (size_t)(bm + r) * 64 + (cb >> 1));
        cp_async16(sbase + 1 * 16384 + so, Alp + (size_t)(bm + r) * 64 + (cb >> 1));
        cp_async16(sbase + 2 * 16384 + so, Bp + (size_t)r * 64 + (cb >> 1));
    }
    CP_COMMIT(); CP_WAIT(0);
    __syncthreads();

    float acc[4][4][4];
#pragma unroll
    for (int i = 0; i < 4; i++)
#pragma unroll
        for (int j = 0; j < 4; j++)
#pragma unroll
            for (int v = 0; v < 4; v++) acc[i][j][v] = 0.f;

    const int lrow = lane & 15;
    const int lksel = (lane >> 4) << 4;
    const uint32_t a_h = sbase, a_l = sbase + 16384, b_s = sbase + 32768;
#pragma unroll
    for (int ks = 0; ks < 4; ks++) {
        const int kb = ks * 32 + lksel;
        uint32_t ah[4][4], al[4][4], bf[4][2];
#pragma unroll
        for (int mf = 0; mf < 4; mf++) {
            int row = wm * 64 + mf * 16 + lrow;
            uint32_t so = SMEM_SWIZZLE_128B(row * 128 + kb);
            ldsm_x4(ah[mf], a_h + so);
            ldsm_x4(al[mf], a_l + so);
        }
#pragma unroll
        for (int g = 0; g < 2; g++) {
            int row = wn * 32 + g * 16 + lrow;
            uint32_t so = SMEM_SWIZZLE_128B(row * 128 + kb);
            uint32_t r[4];
            ldsm_x4(r, b_s + so);
            bf[g * 2][0] = r[0]; bf[g * 2][1] = r[2];
            bf[g * 2 + 1][0] = r[1]; bf[g * 2 + 1][1] = r[3];
        }
#pragma unroll
        for (int mf = 0; mf < 4; mf++)
#pragma unroll
            for (int nf = 0; nf < 4; nf++) mma16816(acc[mf][nf], ah[mf], bf[nf]);
#pragma unroll
        for (int mf = 0; mf < 4; mf++)
#pragma unroll
            for (int nf = 0; nf < 4; nf++) mma16816(acc[mf][nf], al[mf], bf[nf]);
    }
    __syncthreads();

#pragma unroll
    for (int mf = 0; mf < 4; mf++) {
        int rl = wm * 64 + mf * 16 + (lane >> 2);
#pragma unroll
        for (int nf = 0; nf < 4; nf++) {
            int col = wn * 32 + nf * 8 + ((lane & 3) << 1);
            Cs[rl * 132 + col] = acc[mf][nf][0];
            Cs[rl * 132 + col + 1] = acc[mf][nf][1];
            Cs[(rl + 8) * 132 + col] = acc[mf][nf][2];
            Cs[(rl + 8) * 132 + col + 1] = acc[mf][nf][3];
        }
    }
    __syncthreads();

#pragma unroll
    for (int i = 0; i < 16; i++) {
        int row = wid * 16 + i;
        float4 v = *reinterpret_cast<float4*>(&Cs[row * 132 + lane * 4]);
        float mx = warp_max(fmaxf(fmaxf(v.x, v.y), fmaxf(v.z, v.w)));
        v.x = __expf(v.x - mx); v.y = __expf(v.y - mx);
        v.z = __expf(v.z - mx); v.w = __expf(v.w - mx);
        float sm = warp_sum(v.x + v.y + v.z + v.w);
        float inv = 1.f / sm;
        v.x *= inv; v.y *= inv; v.z *= inv; v.w *= inv;
        *reinterpret_cast<float4*>(&g_qa[((size_t)bh * NSEQ + bm + row) * MAG + lane * 4]) = v;
    }
}

// ---------------- ak_sim: C[m=128, n-tile=128] = a(h/l) @ k(single)^T + mask ----------------
#define AKSIM_SMEM (1024 + 49152)
__global__ __launch_bounds__(256) void ak_sim_tc_kernel() {
    extern __shared__ char dsm[];
    uint32_t sraw = smem_u32(dsm);
    uint32_t sbase = (sraw + 1023u) & ~1023u;

    const int tid = threadIdx.x;
    const int lane = tid & 31;
    const int wid = tid >> 5;
    const int wm = wid >> 2, wn = wid & 3;
    const int bh = blockIdx.y;
    const int b = bh >> 4, h = bh & 15;
    const int bn = blockIdx.x * 128;

    const __half* Ahp = g_ah + (size_t)h * MAG * DHEAD;
    const __half* Alp = g_al + (size_t)h * MAG * DHEAD;
    const __half* Bp  = g_k1 + (size_t)bh * NSEQ * DHEAD;

#pragma unroll
    for (int i = 0; i < 4; i++) {
        int u = tid + i * 256;
        int r = u >> 3, cb = (u & 7) << 4;
        uint32_t so = SMEM_SWIZZLE_128B(r * 128 + cb);
        cp_async16(sbase + 0 * 16384 + so, Ahp + (size_t)r * 64 + (cb >> 1));
        cp_async16(sbase + 1 * 16384 + so, Alp + (size_t)r * 64 + (cb >> 1));
        cp_async16(sbase + 2 * 16384 + so, Bp + (size_t)(bn + r) * 64 + (cb >> 1));
    }
    CP_COMMIT(); CP_WAIT(0);
    __syncthreads();

    float acc[4][4][4];
#pragma unroll
    for (int i = 0; i < 4; i++)
#pragma unroll
        for (int j = 0; j < 4; j++)
#pragma unroll
            for (int v = 0; v < 4; v++) acc[i][j][v] = 0.f;

    const int lrow = lane & 15;
    const int lksel = (lane >> 4) << 4;
    const uint32_t a_h = sbase, a_l = sbase + 16384, b_s = sbase + 32768;
#pragma unroll
    for (int ks = 0; ks < 4; ks++) {
        const int kb = ks * 32 + lksel;
        uint32_t ah[4][4], al[4][4], bf[4][2];
#pragma unroll
        for (int mf = 0; mf < 4; mf++) {
            int row = wm * 64 + mf * 16 + lrow;
            uint32_t so = SMEM_SWIZZLE_128B(row * 128 + kb);
            ldsm_x4(ah[mf], a_h + so);
            ldsm_x4(al[mf], a_l + so);
        }
#pragma unroll
        for (int g = 0; g < 2; g++) {
            int row = wn * 32 + g * 16 + lrow;
            uint32_t so = SMEM_SWIZZLE_128B(row * 128 + kb);
            uint32_t r[4];
            ldsm_x4(r, b_s + so);
            bf[g * 2][0] = r[0]; bf[g * 2][1] = r[2];
            bf[g * 2 + 1][0] = r[1]; bf[g * 2 + 1][1] = r[3];
        }
#pragma unroll
        for (int mf = 0; mf < 4; mf++)
#pragma unroll
            for (int nf = 0; nf < 4; nf++) mma16816(acc[mf][nf], ah[mf], bf[nf]);
#pragma unroll
        for (int mf = 0; mf < 4; mf++)
#pragma unroll
            for (int nf = 0; nf < 4; nf++) mma16816(acc[mf][nf], al[mf], bf[nf]);
    }

#pragma unroll
    for (int mf = 0; mf < 4; mf++) {
        int r0 = wm * 64 + mf * 16 + (lane >> 2);
#pragma unroll
        for (int nf = 0; nf < 4; nf++) {
            int col = bn + wn * 32 + nf * 8 + ((lane & 3) << 1);
            float mv0 = g_maskf[b * NSEQ + col];
            float mv1 = g_maskf[b * NSEQ + col + 1];
            float* p0 = &g_ak[((size_t)bh * MAG + r0) * NSEQ + col];
            float* p1 = &g_ak[((size_t)bh * MAG + r0 + 8) * NSEQ + col];
            *reinterpret_cast<float2*>(p0) = make_float2(
                mv0 != 0.f ? acc[mf][nf][0] : -FLT_MAX, mv1 != 0.f ? acc[mf][nf][1] : -FLT_MAX);
            *reinterpret_cast<float2*>(p1) = make_float2(
                mv0 != 0.f ? acc[mf][nf][2] : -FLT_MAX, mv1 != 0.f ? acc[mf][nf][3] : -FLT_MAX);
        }
    }
}

// ---------------- ak row stats ----------------
__global__ __launch_bounds__(256) void ak_stats_kernel() {
    const int row = blockIdx.x;
    const int t = threadIdx.x;
    const float* p = g_ak + (size_t)row * NSEQ;
    float4 v[4];
    float mx = -FLT_MAX;
#pragma unroll
    for (int i = 0; i < 4; i++) {
        v[i] = *reinterpret_cast<const float4*>(&p[t * 16 + i * 4]);
        mx = fmaxf(mx, fmaxf(fmaxf(v[i].x, v[i].y), fmaxf(v[i].z, v[i].w)));
    }
    __shared__ float red[8];
    int wid = t >> 5, lane = t & 31;
    float wm = warp_max(mx);
    if (lane == 0) red[wid] = wm;
    __syncthreads();
    float m = red[0];
#pragma unroll
    for (int i = 1; i < 8; i++) m = fmaxf(m, red[i]);
    float sacc = 0.f;
#pragma unroll
    for (int i = 0; i < 4; i++)
        sacc += __expf(v[i].x - m) + __expf(v[i].y - m) + __expf(v[i].z - m) + __expf(v[i].w - m);
    float ws = warp_sum(sacc);
    __syncthreads();
    if (lane == 0) red[wid] = ws;
    __syncthreads();
    if (t == 0) {
        float tot = 0.f;
#pragma unroll
        for (int i = 0; i < 8; i++) tot += red[i];
        g_akstat[row] = make_float2(m, 1.f / tot);
    }
}

// ---------------- fused exp-normalize + head mix (ak) -> fp16 h/l ----------------
__global__ __launch_bounds__(256) void mix_ak_exp_kernel(const float* __restrict__ Wm) {
    __shared__ float Ws[256];
    if (threadIdx.x < 256) Ws[threadIdx.x] = Wm[threadIdx.x];
    __syncthreads();
    const size_t R = (size_t)MAG * NSEQ;
    size_t pos = (size_t)blockIdx.x * blockDim.x + threadIdx.x;
    if (pos >= (size_t)NB * R) return;
    size_t b = pos / R, r = pos % R;
    int m = (int)(r >> 12);
    const float* p = g_ak + b * 16 * R + r;
    float x[16];
#pragma unroll
    for (int h = 0; h < 16; h++) {
        float2 st = g_akstat[(b * 16 + h) * MAG + m];
        x[h] = __expf(p[h * R] - st.x) * st.y;
    }
#pragma unroll
    for (int g = 0; g < 16; g++) {
        float sacc = 0.f;
#pragma unroll
        for (int h = 0; h < 16; h++) sacc = fmaf(Ws[g * 16 + h], x[h], sacc);
        __half hh, ll;
        split_hl(sacc, hh, ll);
        size_t o = b * 16 * R + g * R + r;
        g_akmh[o] = hh; g_akml[o] = ll;
    }
}

// ---------------- talking heads (qa) -> fp16 h/l ----------------
__global__ __launch_bounds__(256) void mix_heads_kernel(const float* __restrict__ Wm) {
    __shared__ float Ws[256];
    if (threadIdx.x < 256) Ws[threadIdx.x] = Wm[threadIdx.x];
    __syncthreads();
    const size_t R = (size_t)NSEQ * MAG;
    size_t pos = (size_t)blockIdx.x * blockDim.x + threadIdx.x;
    if (pos >= (size_t)NB * R) return;
    size_t b = pos / R, r = pos % R;
    const float* p = g_qa + b * 16 * R + r;
    float x[16];
#pragma unroll
    for (int h = 0; h < 16; h++) x[h] = p[h * R];
#pragma unroll
    for (int g = 0; g < 16; g++) {
        float sacc = 0.f;
#pragma unroll
        for (int h = 0; h < 16; h++) sacc = fmaf(Ws[g * 16 + h], x[h], sacc);
        __half hh, ll;
        split_hl(sacc, hh, ll);
        size_t o = b * 16 * R + g * R + r;
        g_qamh[o] = hh; g_qaml[o] = ll;
    }
}

// ---------------- agent_out: C[m=128, d=64] = akm(h/l) @ vT(single)^T, split-K=4 ----------------
#define AO_STAGE 40960   // Ah 16K | Al 16K | B 8K
#define AO_SMEM  (1024 + 2 * AO_STAGE)
__global__ __launch_bounds__(256) void agent_out_tc_kernel() {
    extern __shared__ char dsm[];
    uint32_t sraw = smem_u32(dsm);
    uint32_t sbase = (sraw + 1023u) & ~1023u;

    const int tid = threadIdx.x;
    const int lane = tid & 31;
    const int wid = tid >> 5;
    const int wm = wid >> 1, wn = wid & 1;
    const int sp = blockIdx.x;
    const int bh = blockIdx.y;

    const __half* Ahp = g_akmh + (size_t)bh * MAG * NSEQ;
    const __half* Alp = g_akml + (size_t)bh * MAG * NSEQ;
    const __half* Bp  = g_vt + (size_t)bh * DHEAD * NSEQ;

    float acc[2][4][4];
#pragma unroll
    for (int i = 0; i < 2; i++)
#pragma unroll
        for (int j = 0; j < 4; j++)
#pragma unroll
            for (int v = 0; v < 4; v++) acc[i][j][v] = 0.f;

    const int kbase = sp * 1024;
    const int nchunk = 16;

    auto load_chunk = [&](int c) {
        const uint32_t sb = sbase + (c & 1) * AO_STAGE;
        const int k0 = kbase + (c << 6);
#pragma unroll
        for (int i = 0; i < 4; i++) {
            int u = tid + i * 256;
            int r = u >> 3, cb = (u & 7) << 4;
            uint32_t so = SMEM_SWIZZLE_128B(r * 128 + cb);
            cp_async16(sb + so,         Ahp + (size_t)r * 4096 + k0 + (cb >> 1));
            cp_async16(sb + 16384 + so, Alp + (size_t)r * 4096 + k0 + (cb >> 1));
        }
#pragma unroll
        for (int i = 0; i < 2; i++) {
            int u = tid + i * 256;
            int r = u >> 3, cb = (u & 7) << 4;
            uint32_t so = SMEM_SWIZZLE_128B(r * 128 + cb);
            cp_async16(sb + 32768 + so, Bp + (size_t)r * 4096 + k0 + (cb >> 1));
        }
        CP_COMMIT();
    };

    load_chunk(0);
    load_chunk(1);

    const int lrow = lane & 15;
    const int lksel = (lane >> 4) << 4;

    for (int c = 0; c < nchunk; c++) {
        if (c + 1 < nchunk) { CP_WAIT(1); } else { CP_WAIT(0); }
        __syncthreads();
        const uint32_t sb = sbase + (c & 1) * AO_STAGE;
        const uint32_t a_h = sb, a_l = sb + 16384, b_s = sb + 32768;
#pragma unroll
        for (int ks = 0; ks < 4; ks++) {
            const int kb = ks * 32 + lksel;
            uint32_t ah[2][4], al[2][4], bf[4][2];
#pragma unroll
            for (int mf = 0; mf < 2; mf++) {
                int row = wm * 32 + mf * 16 + lrow;
                uint32_t so = SMEM_SWIZZLE_128B(row * 128 + kb);
                ldsm_x4(ah[mf], a_h + so);
                ldsm_x4(al[mf], a_l + so);
            }
#pragma unroll
            for (int g = 0; g < 2; g++) {
                int row = wn * 32 + g * 16 + lrow;
                uint32_t so = SMEM_SWIZZLE_128B(row * 128 + kb);
                uint32_t r[4];
                ldsm_x4(r, b_s + so);
                bf[g * 2][0] = r[0]; bf[g * 2][1] = r[2];
                bf[g * 2 + 1][0] = r[1]; bf[g * 2 + 1][1] = r[3];
            }
#pragma unroll
            for (int mf = 0; mf < 2; mf++)
#pragma unroll
                for (int nf = 0; nf < 4; nf++) mma16816(acc[mf][nf], ah[mf], bf[nf]);
#pragma unroll
            for (int mf = 0; mf < 2; mf++)
#pragma unroll
                for (int nf = 0; nf < 4; nf++) mma16816(acc[mf][nf], al[mf], bf[nf]);
        }
        __syncthreads();
        if (c + 2 < nchunk) load_chunk(c + 2);
    }

    float* P = g_agent_part + ((size_t)sp * BHN + bh) * (MAG * DHEAD);
#pragma unroll
    for (int mf = 0; mf < 2; mf++) {
        int r0 = wm * 32 + mf * 16 + (lane >> 2);
#pragma unroll
        for (int nf = 0; nf < 4; nf++) {
            int col = wn * 32 + nf * 8 + ((lane & 3) << 1);
            *reinterpret_cast<float2*>(&P[(size_t)r0 * 64 + col]) =
                make_float2(acc[mf][nf][0], acc[mf][nf][1]);
            *reinterpret_cast<float2*>(&P[(size_t)(r0 + 8) * 64 + col]) =
                make_float2(acc[mf][nf][2], acc[mf][nf][3]);
        }
    }
}

// ---------------- reduce split-K, emit agent^T single fp16 [bh,d,m] ----------------
__global__ __launch_bounds__(256) void reduce_agent_kernel() {
    int i = blockIdx.x * 256 + threadIdx.x;
    float sacc = 0.f;
#pragma unroll
    for (int k = 0; k < 4; k++) sacc += g_agent_part[(size_t)k * (BHN * MAG * DHEAD) + i];
    int bh = i >> 13;
    int rem = i & 8191;
    int m = rem >> 6, d = rem & 63;
    g_agt[((size_t)bh * 64 + d) * 128 + m] = __float2half_rn(sacc);
}

// ---------------- out_mid: C[n=128, d=64] = qam(h/l) @ agt(single)^T, mask, fp16 h/l out ----------------
__global__ __launch_bounds__(256) void out_mid_tc_kernel() {
    extern __shared__ char dsm[];
    uint32_t sraw = smem_u32(dsm);
    uint32_t sbase = (sraw + 1023u) & ~1023u;

    const int tid = threadIdx.x;
    const int lane = tid & 31;
    const int wid = tid >> 5;
    const int wm = wid >> 1, wn = wid & 1;
    const int bh = blockIdx.y;
    const int b = bh >> 4, h = bh & 15;
    const int bm = blockIdx.x * 128;

    const __half* Ahp = g_qamh + (size_t)bh * NSEQ * MAG;
    const __half* Alp = g_qaml + (size_t)bh * NSEQ * MAG;
    const __half* Bp  = g_agt + (size_t)bh * DHEAD * MAG;

#pragma unroll
    for (int c = 0; c < 2; c++) {
        const uint32_t sb = sbase + c * AO_STAGE;
        const int k0 = c << 6;
#pragma unroll
        for (int i = 0; i < 4; i++) {
            int u = tid + i * 256;
            int r = u >> 3, cb = (u & 7) << 4;
            uint32_t so = SMEM_SWIZZLE_128B(r * 128 + cb);
            cp_async16(sb + so,         Ahp + (size_t)(bm + r) * 128 + k0 + (cb >> 1));
            cp_async16(sb + 16384 + so, Alp + (size_t)(bm + r) * 128 + k0 + (cb >> 1));
        }
#pragma unroll
        for (int i = 0; i < 2; i++) {
            int u = tid + i * 256;
            int r = u >> 3, cb = (u & 7) << 4;
            uint32_t so = SMEM_SWIZZLE_128B(r * 128 + cb);
            cp_async16(sb + 32768 + so, Bp + (size_t)r * 128 + k0 + (cb >> 1));
        }
        CP_COMMIT();
    }
    CP_WAIT(0);
    __syncthreads();

    float acc[2][4][4];
#pragma unroll
    for (int i = 0; i < 2; i++)
#pragma unroll
        for (int j = 0; j < 4; j++)
#pragma unroll
            for (int v = 0; v < 4; v++) acc[i][j][v] = 0.f;

    const int lrow = lane & 15;
    const int lksel = (lane >> 4) << 4;
#pragma unroll
    for (int c = 0; c < 2; c++) {
        const uint32_t sb = sbase + c * AO_STAGE;
        const uint32_t a_h = sb, a_l = sb + 16384, b_s = sb + 32768;
#pragma unroll
        for (int ks = 0; ks < 4; ks++) {
            const int kb = ks * 32 + lksel;
            uint32_t ah[2][4], al[2][4], bf[4][2];
#pragma unroll
            for (int mf = 0; mf < 2; mf++) {
                int row = wm * 32 + mf * 16 + lrow;
                uint32_t so = SMEM_SWIZZLE_128B(row * 128 + kb);
                ldsm_x4(ah[mf], a_h + so);
                ldsm_x4(al[mf], a_l + so);
            }
#pragma unroll
            for (int g = 0; g < 2; g++) {
                int row = wn * 32 + g * 16 + lrow;
                uint32_t so = SMEM_SWIZZLE_128B(row * 128 + kb);
                uint32_t r[4];
                ldsm_x4(r, b_s + so);
                bf[g * 2][0] = r[0]; bf[g * 2][1] = r[2];
                bf[g * 2 + 1][0] = r[1]; bf[g * 2 + 1][1] = r[3];
            }
#pragma unroll
            for (int mf = 0; mf < 2; mf++)
#pragma unroll
                for (int nf = 0; nf < 4; nf++) mma16816(acc[mf][nf], ah[mf], bf[nf]);
#pragma unroll
            for (int mf = 0; mf < 2; mf++)
#pragma unroll
                for (int nf = 0; nf < 4; nf++) mma16816(acc[mf][nf], al[mf], bf[nf]);
        }
    }

#pragma unroll
    for (int mf = 0; mf < 2; mf++) {
        int r0 = wm * 32 + mf * 16 + (lane >> 2);
#pragma unroll
        for (int nf = 0; nf < 4; nf++) {
            int col = wn * 32 + nf * 8 + ((lane & 3) << 1);
#pragma unroll
            for (int rr = 0; rr < 2; rr++) {
                int rn = bm + r0 + rr * 8;
                float mv = g_maskf[b * NSEQ + rn];
                float v0 = acc[mf][nf][rr * 2] * mv, v1 = acc[mf][nf][rr * 2 + 1] * mv;
                __half h0, l0, h1, l1;
                split_hl(v0, h0, l0); split_hl(v1, h1, l1);
                size_t o = ((size_t)b * NSEQ + rn) * DIMX + h * 64 + col;
                *reinterpret_cast<__half2*>(&g_midh[o]) = __halves2half2(h0, h1);
                *reinterpret_cast<__half2*>(&g_midl[o]) = __halves2half2(l0, l1);
            }
        }
    }
}

// ---------------- launcher ----------------
extern "C" void kernel_launch(void* const* d_in, const int* in_sizes, int n_in,
                              void* d_out, int out_size) {
    const float* x     = (const float*)d_in[0];
    const void*  mask  = d_in[1];
    const float* Wqkv  = (const float*)d_in[2];
    const float* agent = (const float*)d_in[3];
    const float* Wqa   = (const float*)d_in[4];
    const float* Wak   = (const float*)d_in[5];
    const float* Wout  = (const float*)d_in[6];
    float* out = (float*)d_out;
    (void)in_sizes; (void)n_in; (void)out_size;

    cudaFuncSetAttribute(gemm_mma_kernel<0>, cudaFuncAttributeMaxDynamicSharedMemorySize, GT_SMEM);
    cudaFuncSetAttribute(gemm_mma_kernel<1>, cudaFuncAttributeMaxDynamicSharedMemorySize, GT_SMEM);
    cudaFuncSetAttribute(qa_sim_tc_kernel, cudaFuncAttributeMaxDynamicSharedMemorySize, QSIM_SMEM);
    cudaFuncSetAttribute(ak_sim_tc_kernel, cudaFuncAttributeMaxDynamicSharedMemorySize, AKSIM_SMEM);
    cudaFuncSetAttribute(agent_out_tc_kernel, cudaFuncAttributeMaxDynamicSharedMemorySize, AO_SMEM);
    cudaFuncSetAttribute(out_mid_tc_kernel, cudaFuncAttributeMaxDynamicSharedMemorySize, AO_SMEM);

    __half *xh, *xl, *wq, *wo, *mh, *ml;
    cudaGetSymbolAddress((void**)&xh, g_xh);
    cudaGetSymbolAddress((void**)&xl, g_xl);
    cudaGetSymbolAddress((void**)&wq, g_wqkv);
    cudaGetSymbolAddress((void**)&wo, g_wout);
    cudaGetSymbolAddress((void**)&mh, g_midh);
    cudaGetSymbolAddress((void**)&ml, g_midl);

    mask_expand_kernel<<<1, 1024>>>(mask);
    conv_split_kernel<<<(NB * NSEQ * DIMX / 4 + 255) / 256, 256>>>(x, xh, xl, NB * NSEQ * DIMX / 4);
    conv_wt_kernel<<<dim3(96, 32), 256>>>(Wqkv, wq, 1024, 3072);
    conv_wt_kernel<<<dim3(32, 32), 256>>>(Wout, wo, 1024, 1024);
    conv_agent_kernel<<<(HEADS * MAG * DHEAD / 4 + 255) / 256, 256>>>(agent);

    gemm_mma_kernel<1><<<dim3(24, 128), 512, GT_SMEM>>>(xh, xl, wq, nullptr, 1024, 3072);

    qa_sim_tc_kernel<<<dim3(32, 64), 256, QSIM_SMEM>>>();
    ak_sim_tc_kernel<<<dim3(32, 64), 256, AKSIM_SMEM>>>();
    ak_stats_kernel<<<BHN * MAG, 256>>>();
    mix_heads_kernel<<<8192, 256>>>(Wqa);
    mix_ak_exp_kernel<<<8192, 256>>>(Wak);
    agent_out_tc_kernel<<<dim3(4, 64), 256, AO_SMEM>>>();
    reduce_agent_kernel<<<(BHN * MAG * DHEAD) / 256, 256>>>();
    out_mid_tc_kernel<<<dim3(32, 64), 256, AO_SMEM>>>();

    gemm_mma_kernel<0><<<dim3(8, 128), 512, GT_SMEM>>>(mh, ml, wo, out, 1024, 1024);
}

// round 14
// speedup vs baseline: 3.3028x; 1.4364x over previous
#include <cuda_runtime.h>
#include <cuda_fp16.h>
#include <stdint.h>
#include <float.h>

// ---------------- problem constants ----------------
#define NB    4
#define NSEQ  4096
#define DIMX  1024
#define HEADS 16
#define DHEAD 64
#define MAG   128
#define BHN   (NB * HEADS)
#define SCALE 0.125f

// ---------------- scratch (device globals; no allocation) ----------------
__device__ float g_qa[NB * HEADS * NSEQ * MAG];        // fp32 qa attn (softmaxed)
__device__ float g_ak[NB * HEADS * MAG * NSEQ];        // fp32 ak logits (masked)
__device__ float g_agent_part[4 * BHN * MAG * DHEAD];  // split-K partials
__device__ float g_maskf[NB * NSEQ];
__device__ float2 g_akstat[BHN * MAG];

// fp16 operands
__device__ __half g_x16[NB * NSEQ * DIMX];             // x single fp16
__device__ __half g_wqkv[3 * DIMX * DIMX];             // Wqkv^T single
__device__ __half g_wout[DIMX * DIMX];                 // Wout^T single
__device__ __half g_qh[BHN * NSEQ * DHEAD];            // q hi [bh,n,d]
__device__ __half g_ql[BHN * NSEQ * DHEAD];            // q lo
__device__ __half g_k1[BHN * NSEQ * DHEAD];            // k single [bh,n,d]
__device__ __half g_vt[BHN * DHEAD * NSEQ];            // v^T single [bh,d,n]
__device__ __half g_ah[HEADS * MAG * DHEAD];           // agent*SCALE hi
__device__ __half g_al[HEADS * MAG * DHEAD];           // agent*SCALE lo
__device__ __half g_qamh[NB * HEADS * NSEQ * MAG];     // mixed qa hi [bh,n,m]
__device__ __half g_qaml[NB * HEADS * NSEQ * MAG];
__device__ __half g_akmh[NB * HEADS * MAG * NSEQ];     // mixed ak attn hi [bh,m,n]
__device__ __half g_akml[NB * HEADS * MAG * NSEQ];
__device__ __half g_agt[BHN * DHEAD * MAG];            // agent_out^T single [bh,d,m]
__device__ __half g_mid[NB * NSEQ * DIMX];             // mid single fp16

// ---------------- PTX helpers ----------------
__device__ __forceinline__ uint32_t smem_u32(const void* p) {
    uint32_t a;
    asm("{ .reg .u64 t; cvta.to.shared.u64 t, %1; cvt.u32.u64 %0, t; }" : "=r"(a) : "l"(p));
    return a;
}
#define SMEM_SWIZZLE_128B(o) ((o) ^ (((o) >> 3) & 0x70))

__device__ __forceinline__ void cp_async16(uint32_t sa, const void* g) {
    asm volatile("cp.async.cg.shared.global [%0], [%1], 16;" :: "r"(sa), "l"(g));
}
#define CP_COMMIT() asm volatile("cp.async.commit_group;" ::: "memory")
#define CP_WAIT(n)  asm volatile("cp.async.wait_group %0;" :: "n"(n) : "memory")

__device__ __forceinline__ void ldsm_x4(uint32_t* r, uint32_t a) {
    asm volatile("ldmatrix.sync.aligned.m8n8.x4.shared.b16 {%0,%1,%2,%3}, [%4];"
                 : "=r"(r[0]), "=r"(r[1]), "=r"(r[2]), "=r"(r[3]) : "r"(a));
}
__device__ __forceinline__ void mma16816(float* c, const uint32_t* a, const uint32_t* b) {
    asm volatile("mma.sync.aligned.m16n8k16.row.col.f32.f16.f16.f32 "
                 "{%0,%1,%2,%3}, {%4,%5,%6,%7}, {%8,%9}, {%0,%1,%2,%3};"
                 : "+f"(c[0]), "+f"(c[1]), "+f"(c[2]), "+f"(c[3])
                 : "r"(a[0]), "r"(a[1]), "r"(a[2]), "r"(a[3]), "r"(b[0]), "r"(b[1]));
}

__device__ __forceinline__ float warp_max(float v) {
#pragma unroll
    for (int o = 16; o > 0; o >>= 1) v = fmaxf(v, __shfl_xor_sync(0xffffffffu, v, o));
    return v;
}
__device__ __forceinline__ float warp_sum(float v) {
#pragma unroll
    for (int o = 16; o > 0; o >>= 1) v += __shfl_xor_sync(0xffffffffu, v, o);
    return v;
}
__device__ __forceinline__ void split_hl(float v, __half& h, __half& l) {
    h = __float2half_rn(v);
    l = __float2half_rn(v - __half2float(h));
}

// ---------------- mask dtype detection + expansion ----------------
__global__ void mask_expand_kernel(const void* __restrict__ mraw) {
    __shared__ int s_weird, s_off;
    const unsigned char* mb = (const unsigned char*)mraw;
    if (threadIdx.x == 0) { s_weird = 0; s_off = 0; }
    __syncthreads();
    int weird = 0, off = 0;
    for (int i = threadIdx.x; i < NB * NSEQ; i += blockDim.x) {
        unsigned char c = mb[i];
        if (c > 1) weird = 1;
        if (c != 0 && (i & 3)) off = 1;
    }
    if (weird) atomicOr(&s_weird, 1);
    if (off)   atomicOr(&s_off, 1);
    __syncthreads();
    int mode = s_weird ? 2 : (s_off ? 0 : 1);
    for (int i = threadIdx.x; i < NB * NSEQ; i += blockDim.x) {
        float v;
        if (mode == 0)      v = mb[i] ? 1.f : 0.f;
        else if (mode == 1) v = ((const int*)mraw)[i] ? 1.f : 0.f;
        else                v = (((const float*)mraw)[i] != 0.f) ? 1.f : 0.f;
        g_maskf[i] = v;
    }
}

// ---------------- fp32 -> fp16 single (elementwise) ----------------
__global__ __launch_bounds__(256) void conv_x_kernel(const float* __restrict__ src,
                                                     __half* __restrict__ dst, int n4) {
    int i = blockIdx.x * 256 + threadIdx.x;
    if (i >= n4) return;
    float4 v = reinterpret_cast<const float4*>(src)[i];
    reinterpret_cast<__half2*>(dst)[i * 2] =
        __halves2half2(__float2half_rn(v.x), __float2half_rn(v.y));
    reinterpret_cast<__half2*>(dst)[i * 2 + 1] =
        __halves2half2(__float2half_rn(v.z), __float2half_rn(v.w));
}

// ---------------- agent tokens: scale + fp16 hi/lo ----------------
__global__ __launch_bounds__(256) void conv_agent_kernel(const float* __restrict__ src) {
    int i = blockIdx.x * 256 + threadIdx.x;
    if (i >= HEADS * MAG * DHEAD / 4) return;
    float4 v = reinterpret_cast<const float4*>(src)[i];
    __half h0, h1, h2, h3, l0, l1, l2, l3;
    split_hl(v.x * SCALE, h0, l0); split_hl(v.y * SCALE, h1, l1);
    split_hl(v.z * SCALE, h2, l2); split_hl(v.w * SCALE, h3, l3);
    reinterpret_cast<__half2*>(g_ah)[i * 2]     = __halves2half2(h0, h1);
    reinterpret_cast<__half2*>(g_ah)[i * 2 + 1] = __halves2half2(h2, h3);
    reinterpret_cast<__half2*>(g_al)[i * 2]     = __halves2half2(l0, l1);
    reinterpret_cast<__half2*>(g_al)[i * 2 + 1] = __halves2half2(l2, l3);
}

// ---------------- W[K,N] -> W^T[N,K] single fp16 ----------------
__global__ __launch_bounds__(256) void conv_wt_kernel(const float* __restrict__ W,
                                                      __half* __restrict__ T,
                                                      int K, int N) {
    __shared__ float t[32][33];
    int bx = blockIdx.x * 32;
    int by = blockIdx.y * 32;
    int x = threadIdx.x & 31, y0 = threadIdx.x >> 5;
#pragma unroll
    for (int y = y0; y < 32; y += 8) t[y][x] = W[(size_t)(by + y) * N + bx + x];
    __syncthreads();
#pragma unroll
    for (int y = y0; y < 32; y += 8) {
        T[(size_t)(bx + y) * K + by + x] = __float2half_rn(t[x][y]);
    }
}

// ---------------- big mma GEMM: single fp16, 128x128 tile, BK=64, 2-stage, 512 threads ----------------
#define GT_TILE  16384
#define GT_STAGE (2 * GT_TILE)
#define GT_SMEM  (1024 + 2 * GT_STAGE)   // 66560

template <int MODE>   // 0: fp32 out ; 1: qkv scatter (q hi/lo, k single, v^T single)
__global__ __launch_bounds__(512, 1) void gemm_mma_kernel(
    const __half* __restrict__ A, const __half* __restrict__ B,
    float* __restrict__ out, int Kdim, int Nout) {
    extern __shared__ char dsm[];
    uint32_t sraw = smem_u32(dsm);
    uint32_t sbase = (sraw + 1023u) & ~1023u;

    const int tid = threadIdx.x;
    const int lane = tid & 31;
    const int wid = tid >> 5;
    const int wm = wid >> 2;
    const int wn = wid & 3;
    const int bm = blockIdx.y * 128;
    const int bn = blockIdx.x * 128;

    float acc[2][4][4];
#pragma unroll
    for (int i = 0; i < 2; i++)
#pragma unroll
        for (int j = 0; j < 4; j++)
#pragma unroll
            for (int v = 0; v < 4; v++) acc[i][j][v] = 0.f;

    const int nchunk = Kdim >> 6;
    const int lr  = tid >> 3;
    const int lc  = (tid & 7) << 4;

    auto load_chunk = [&](int c) {
        const int buf = c & 1;
        const int k0 = c << 6;
        const uint32_t sb = sbase + buf * GT_STAGE;
#pragma unroll
        for (int i = 0; i < 2; i++) {
            int r = lr + i * 64;
            uint32_t so = SMEM_SWIZZLE_128B(r * 128 + lc);
            cp_async16(sb + so,           A + (size_t)(bm + r) * Kdim + k0 + (lc >> 1));
            cp_async16(sb + GT_TILE + so, B + (size_t)(bn + r) * Kdim + k0 + (lc >> 1));
        }
        CP_COMMIT();
    };

    load_chunk(0);
    if (nchunk > 1) load_chunk(1);

    const int lrow = lane & 15;
    const int lksel = (lane >> 4) << 4;

    for (int c = 0; c < nchunk; c++) {
        if (c + 1 < nchunk) { CP_WAIT(1); } else { CP_WAIT(0); }
        __syncthreads();
        const uint32_t sb = sbase + (c & 1) * GT_STAGE;
        const uint32_t a_s = sb, b_s = sb + GT_TILE;
#pragma unroll
        for (int ks = 0; ks < 4; ks++) {
            const int kb = ks * 32 + lksel;
            uint32_t af[2][4], bf[4][2];
#pragma unroll
            for (int mf = 0; mf < 2; mf++) {
                int row = wm * 32 + mf * 16 + lrow;
                ldsm_x4(af[mf], a_s + SMEM_SWIZZLE_128B(row * 128 + kb));
            }
#pragma unroll
            for (int g = 0; g < 2; g++) {
                int row = wn * 32 + g * 16 + lrow;
                uint32_t r[4];
                ldsm_x4(r, b_s + SMEM_SWIZZLE_128B(row * 128 + kb));
                bf[g * 2][0] = r[0]; bf[g * 2][1] = r[2];
                bf[g * 2 + 1][0] = r[1]; bf[g * 2 + 1][1] = r[3];
            }
#pragma unroll
            for (int mf = 0; mf < 2; mf++)
#pragma unroll
                for (int nf = 0; nf < 4; nf++) mma16816(acc[mf][nf], af[mf], bf[nf]);
        }
        __syncthreads();
        if (c + 2 < nchunk) load_chunk(c + 2);
    }

#pragma unroll
    for (int mf = 0; mf < 2; mf++) {
        int r0 = bm + wm * 32 + mf * 16 + (lane >> 2);
#pragma unroll
        for (int nf = 0; nf < 4; nf++) {
            int col = bn + wn * 32 + nf * 8 + ((lane & 3) << 1);
            if (MODE == 0) {
                float* p0 = &out[(size_t)r0 * Nout + col];
                float* p1 = &out[(size_t)(r0 + 8) * Nout + col];
                *reinterpret_cast<float2*>(p0) = make_float2(acc[mf][nf][0], acc[mf][nf][1]);
                *reinterpret_cast<float2*>(p1) = make_float2(acc[mf][nf][2], acc[mf][nf][3]);
            } else {
                const int which = col >> 10;
                const int hh = (col >> 6) & 15;
                const int d0 = col & 63;
#pragma unroll
                for (int rr = 0; rr < 2; rr++) {
                    int r = r0 + rr * 8;
                    float v0 = acc[mf][nf][rr * 2], v1 = acc[mf][nf][rr * 2 + 1];
                    int b = r >> 12, n = r & 4095;
                    int bhn = b * 16 + hh;
                    if (which == 0) {
                        __half h0, l0, h1, l1;
                        split_hl(v0, h0, l0); split_hl(v1, h1, l1);
                        size_t o = ((size_t)bhn * 4096 + n) * 64 + d0;
                        *reinterpret_cast<__half2*>(&g_qh[o]) = __halves2half2(h0, h1);
                        *reinterpret_cast<__half2*>(&g_ql[o]) = __halves2half2(l0, l1);
                    } else if (which == 1) {
                        size_t o = ((size_t)bhn * 4096 + n) * 64 + d0;
                        *reinterpret_cast<__half2*>(&g_k1[o]) =
                            __halves2half2(__float2half_rn(v0), __float2half_rn(v1));
                    } else {
                        size_t o0 = ((size_t)bhn * 64 + d0) * 4096 + n;
                        size_t o1 = ((size_t)bhn * 64 + d0 + 1) * 4096 + n;
                        g_vt[o0] = __float2half_rn(v0);
                        g_vt[o1] = __float2half_rn(v1);
                    }
                }
            }
        }
    }
}

// ================= mid-section tensor kernels (fp16x2, unchanged from R10) =================

// ---------------- qa_sim + fused softmax over m ----------------
#define QSIM_SMEM (1024 + 68608)
__global__ __launch_bounds__(256) void qa_sim_tc_kernel() {
    extern __shared__ char dsm[];
    uint32_t sraw = smem_u32(dsm);
    uint32_t sbase = (sraw + 1023u) & ~1023u;
    float* Cs = reinterpret_cast<float*>(dsm + (sbase - sraw));

    const int tid = threadIdx.x;
    const int lane = tid & 31;
    const int wid = tid >> 5;
    const int wm = wid >> 2, wn = wid & 3;
    const int bh = blockIdx.y;
    const int h = bh & 15;
    const int bm = blockIdx.x * 128;

    const __half* Ahp = g_qh + (size_t)bh * NSEQ * DHEAD;
    const __half* Alp = g_ql + (size_t)bh * NSEQ * DHEAD;
    const __half* Bp  = g_ah + (size_t)h * MAG * DHEAD;

#pragma unroll
    for (int i = 0; i < 4; i++) {
        int u = tid + i * 256;
        int r = u >> 3, cb = (u & 7) << 4;
        uint32_t so = SMEM_SWIZZLE_128B(r * 128 + cb);
        cp_async16(sbase + 0 * 16384 + so, Ahp + (size_t)(bm + r) * 64 + (cb >> 1));
        cp_async16(sbase + 1 * 16384 + so, Alp + (size_t)(bm + r) * 64 + (cb >> 1));
        cp_async16(sbase + 2 * 16384 + so, Bp + (size_t)r * 64 + (cb >> 1));
    }
    CP_COMMIT(); CP_WAIT(0);
    __syncthreads();

    float acc[4][4][4];
#pragma unroll
    for (int i = 0; i < 4; i++)
#pragma unroll
        for (int j = 0; j < 4; j++)
#pragma unroll
            for (int v = 0; v < 4; v++) acc[i][j][v] = 0.f;

    const int lrow = lane & 15;
    const int lksel = (lane >> 4) << 4;
    const uint32_t a_h = sbase, a_l = sbase + 16384, b_s = sbase + 32768;
#pragma unroll
    for (int ks = 0; ks < 4; ks++) {
        const int kb = ks * 32 + lksel;
        uint32_t ah[4][4], al[4][4], bf[4][2];
#pragma unroll
        for (int mf = 0; mf < 4; mf++) {
            int row = wm * 64 + mf * 16 + lrow;
            uint32_t so = SMEM_SWIZZLE_128B(row * 128 + kb);
            ldsm_x4(ah[mf], a_h + so);
            ldsm_x4(al[mf], a_l + so);
        }
#pragma unroll
        for (int g = 0; g < 2; g++) {
            int row = wn * 32 + g * 16 + lrow;
            uint32_t so = SMEM_SWIZZLE_128B(row * 128 + kb);
            uint32_t r[4];
            ldsm_x4(r, b_s + so);
            bf[g * 2][0] = r[0]; bf[g * 2][1] = r[2];
            bf[g * 2 + 1][0] = r[1]; bf[g * 2 + 1][1] = r[3];
        }
#pragma unroll
        for (int mf = 0; mf < 4; mf++)
#pragma unroll
            for (int nf = 0; nf < 4; nf++) mma16816(acc[mf][nf], ah[mf], bf[nf]);
#pragma unroll
        for (int mf = 0; mf < 4; mf++)
#pragma unroll
            for (int nf = 0; nf < 4; nf++) mma16816(acc[mf][nf], al[mf], bf[nf]);
    }
    __syncthreads();

#pragma unroll
    for (int mf = 0; mf < 4; mf++) {
        int rl = wm * 64 + mf * 16 + (lane >> 2);
#pragma unroll
        for (int nf = 0; nf < 4; nf++) {
            int col = wn * 32 + nf * 8 + ((lane & 3) << 1);
            Cs[rl * 132 + col] = acc[mf][nf][0];
            Cs[rl * 132 + col + 1] = acc[mf][nf][1];
            Cs[(rl + 8) * 132 + col] = acc[mf][nf][2];
            Cs[(rl + 8) * 132 + col + 1] = acc[mf][nf][3];
        }
    }
    __syncthreads();

#pragma unroll
    for (int i = 0; i < 16; i++) {
        int row = wid * 16 + i;
        float4 v = *reinterpret_cast<float4*>(&Cs[row * 132 + lane * 4]);
        float mx = warp_max(fmaxf(fmaxf(v.x, v.y), fmaxf(v.z, v.w)));
        v.x = __expf(v.x - mx); v.y = __expf(v.y - mx);
        v.z = __expf(v.z - mx); v.w = __expf(v.w - mx);
        float sm = warp_sum(v.x + v.y + v.z + v.w);
        float inv = 1.f / sm;
        v.x *= inv; v.y *= inv; v.z *= inv; v.w *= inv;
        *reinterpret_cast<float4*>(&g_qa[((size_t)bh * NSEQ + bm + row) * MAG + lane * 4]) = v;
    }
}

// ---------------- ak_sim ----------------
#define AKSIM_SMEM (1024 + 49152)
__global__ __launch_bounds__(256) void ak_sim_tc_kernel() {
    extern __shared__ char dsm[];
    uint32_t sraw = smem_u32(dsm);
    uint32_t sbase = (sraw + 1023u) & ~1023u;

    const int tid = threadIdx.x;
    const int lane = tid & 31;
    const int wid = tid >> 5;
    const int wm = wid >> 2, wn = wid & 3;
    const int bh = blockIdx.y;
    const int b = bh >> 4, h = bh & 15;
    const int bn = blockIdx.x * 128;

    const __half* Ahp = g_ah + (size_t)h * MAG * DHEAD;
    const __half* Alp = g_al + (size_t)h * MAG * DHEAD;
    const __half* Bp  = g_k1 + (size_t)bh * NSEQ * DHEAD;

#pragma unroll
    for (int i = 0; i < 4; i++) {
        int u = tid + i * 256;
        int r = u >> 3, cb = (u & 7) << 4;
        uint32_t so = SMEM_SWIZZLE_128B(r * 128 + cb);
        cp_async16(sbase + 0 * 16384 + so, Ahp + (size_t)r * 64 + (cb >> 1));
        cp_async16(sbase + 1 * 16384 + so, Alp + (size_t)r * 64 + (cb >> 1));
        cp_async16(sbase + 2 * 16384 + so, Bp + (size_t)(bn + r) * 64 + (cb >> 1));
    }
    CP_COMMIT(); CP_WAIT(0);
    __syncthreads();

    float acc[4][4][4];
#pragma unroll
    for (int i = 0; i < 4; i++)
#pragma unroll
        for (int j = 0; j < 4; j++)
#pragma unroll
            for (int v = 0; v < 4; v++) acc[i][j][v] = 0.f;

    const int lrow = lane & 15;
    const int lksel = (lane >> 4) << 4;
    const uint32_t a_h = sbase, a_l = sbase + 16384, b_s = sbase + 32768;
#pragma unroll
    for (int ks = 0; ks < 4; ks++) {
        const int kb = ks * 32 + lksel;
        uint32_t ah[4][4], al[4][4], bf[4][2];
#pragma unroll
        for (int mf = 0; mf < 4; mf++) {
            int row = wm * 64 + mf * 16 + lrow;
            uint32_t so = SMEM_SWIZZLE_128B(row * 128 + kb);
            ldsm_x4(ah[mf], a_h + so);
            ldsm_x4(al[mf], a_l + so);
        }
#pragma unroll
        for (int g = 0; g < 2; g++) {
            int row = wn * 32 + g * 16 + lrow;
            uint32_t so = SMEM_SWIZZLE_128B(row * 128 + kb);
            uint32_t r[4];
            ldsm_x4(r, b_s + so);
            bf[g * 2][0] = r[0]; bf[g * 2][1] = r[2];
            bf[g * 2 + 1][0] = r[1]; bf[g * 2 + 1][1] = r[3];
        }
#pragma unroll
        for (int mf = 0; mf < 4; mf++)
#pragma unroll
            for (int nf = 0; nf < 4; nf++) mma16816(acc[mf][nf], ah[mf], bf[nf]);
#pragma unroll
        for (int mf = 0; mf < 4; mf++)
#pragma unroll
            for (int nf = 0; nf < 4; nf++) mma16816(acc[mf][nf], al[mf], bf[nf]);
    }

#pragma unroll
    for (int mf = 0; mf < 4; mf++) {
        int r0 = wm * 64 + mf * 16 + (lane >> 2);
#pragma unroll
        for (int nf = 0; nf < 4; nf++) {
            int col = bn + wn * 32 + nf * 8 + ((lane & 3) << 1);
            float mv0 = g_maskf[b * NSEQ + col];
            float mv1 = g_maskf[b * NSEQ + col + 1];
            float* p0 = &g_ak[((size_t)bh * MAG + r0) * NSEQ + col];
            float* p1 = &g_ak[((size_t)bh * MAG + r0 + 8) * NSEQ + col];
            *reinterpret_cast<float2*>(p0) = make_float2(
                mv0 != 0.f ? acc[mf][nf][0] : -FLT_MAX, mv1 != 0.f ? acc[mf][nf][1] : -FLT_MAX);
            *reinterpret_cast<float2*>(p1) = make_float2(
                mv0 != 0.f ? acc[mf][nf][2] : -FLT_MAX, mv1 != 0.f ? acc[mf][nf][3] : -FLT_MAX);
        }
    }
}

// ---------------- ak row stats ----------------
__global__ __launch_bounds__(256) void ak_stats_kernel() {
    const int row = blockIdx.x;
    const int t = threadIdx.x;
    const float* p = g_ak + (size_t)row * NSEQ;
    float4 v[4];
    float mx = -FLT_MAX;
#pragma unroll
    for (int i = 0; i < 4; i++) {
        v[i] = *reinterpret_cast<const float4*>(&p[t * 16 + i * 4]);
        mx = fmaxf(mx, fmaxf(fmaxf(v[i].x, v[i].y), fmaxf(v[i].z, v[i].w)));
    }
    __shared__ float red[8];
    int wid = t >> 5, lane = t & 31;
    float wm = warp_max(mx);
    if (lane == 0) red[wid] = wm;
    __syncthreads();
    float m = red[0];
#pragma unroll
    for (int i = 1; i < 8; i++) m = fmaxf(m, red[i]);
    float sacc = 0.f;
#pragma unroll
    for (int i = 0; i < 4; i++)
        sacc += __expf(v[i].x - m) + __expf(v[i].y - m) + __expf(v[i].z - m) + __expf(v[i].w - m);
    float ws = warp_sum(sacc);
    __syncthreads();
    if (lane == 0) red[wid] = ws;
    __syncthreads();
    if (t == 0) {
        float tot = 0.f;
#pragma unroll
        for (int i = 0; i < 8; i++) tot += red[i];
        g_akstat[row] = make_float2(m, 1.f / tot);
    }
}

// ---------------- fused exp-normalize + head mix (ak) -> fp16 h/l ----------------
__global__ __launch_bounds__(256) void mix_ak_exp_kernel(const float* __restrict__ Wm) {
    __shared__ float Ws[256];
    if (threadIdx.x < 256) Ws[threadIdx.x] = Wm[threadIdx.x];
    __syncthreads();
    const size_t R = (size_t)MAG * NSEQ;
    size_t pos = (size_t)blockIdx.x * blockDim.x + threadIdx.x;
    if (pos >= (size_t)NB * R) return;
    size_t b = pos / R, r = pos % R;
    int m = (int)(r >> 12);
    const float* p = g_ak + b * 16 * R + r;
    float x[16];
#pragma unroll
    for (int h = 0; h < 16; h++) {
        float2 st = g_akstat[(b * 16 + h) * MAG + m];
        x[h] = __expf(p[h * R] - st.x) * st.y;
    }
#pragma unroll
    for (int g = 0; g < 16; g++) {
        float sacc = 0.f;
#pragma unroll
        for (int h = 0; h < 16; h++) sacc = fmaf(Ws[g * 16 + h], x[h], sacc);
        __half hh, ll;
        split_hl(sacc, hh, ll);
        size_t o = b * 16 * R + g * R + r;
        g_akmh[o] = hh; g_akml[o] = ll;
    }
}

// ---------------- talking heads (qa) -> fp16 h/l ----------------
__global__ __launch_bounds__(256) void mix_heads_kernel(const float* __restrict__ Wm) {
    __shared__ float Ws[256];
    if (threadIdx.x < 256) Ws[threadIdx.x] = Wm[threadIdx.x];
    __syncthreads();
    const size_t R = (size_t)NSEQ * MAG;
    size_t pos = (size_t)blockIdx.x * blockDim.x + threadIdx.x;
    if (pos >= (size_t)NB * R) return;
    size_t b = pos / R, r = pos % R;
    const float* p = g_qa + b * 16 * R + r;
    float x[16];
#pragma unroll
    for (int h = 0; h < 16; h++) x[h] = p[h * R];
#pragma unroll
    for (int g = 0; g < 16; g++) {
        float sacc = 0.f;
#pragma unroll
        for (int h = 0; h < 16; h++) sacc = fmaf(Ws[g * 16 + h], x[h], sacc);
        __half hh, ll;
        split_hl(sacc, hh, ll);
        size_t o = b * 16 * R + g * R + r;
        g_qamh[o] = hh; g_qaml[o] = ll;
    }
}

// ---------------- agent_out: C[m=128, d=64] = akm(h/l) @ vT(single)^T, split-K=4 ----------------
#define AO_STAGE 40960   // Ah 16K | Al 16K | B 8K
#define AO_SMEM  (1024 + 2 * AO_STAGE)
__global__ __launch_bounds__(256) void agent_out_tc_kernel() {
    extern __shared__ char dsm[];
    uint32_t sraw = smem_u32(dsm);
    uint32_t sbase = (sraw + 1023u) & ~1023u;

    const int tid = threadIdx.x;
    const int lane = tid & 31;
    const int wid = tid >> 5;
    const int wm = wid >> 1, wn = wid & 1;
    const int sp = blockIdx.x;
    const int bh = blockIdx.y;

    const __half* Ahp = g_akmh + (size_t)bh * MAG * NSEQ;
    const __half* Alp = g_akml + (size_t)bh * MAG * NSEQ;
    const __half* Bp  = g_vt + (size_t)bh * DHEAD * NSEQ;

    float acc[2][4][4];
#pragma unroll
    for (int i = 0; i < 2; i++)
#pragma unroll
        for (int j = 0; j < 4; j++)
#pragma unroll
            for (int v = 0; v < 4; v++) acc[i][j][v] = 0.f;

    const int kbase = sp * 1024;
    const int nchunk = 16;

    auto load_chunk = [&](int c) {
        const uint32_t sb = sbase + (c & 1) * AO_STAGE;
        const int k0 = kbase + (c << 6);
#pragma unroll
        for (int i = 0; i < 4; i++) {
            int u = tid + i * 256;
            int r = u >> 3, cb = (u & 7) << 4;
            uint32_t so = SMEM_SWIZZLE_128B(r * 128 + cb);
            cp_async16(sb + so,         Ahp + (size_t)r * 4096 + k0 + (cb >> 1));
            cp_async16(sb + 16384 + so, Alp + (size_t)r * 4096 + k0 + (cb >> 1));
        }
#pragma unroll
        for (int i = 0; i < 2; i++) {
            int u = tid + i * 256;
            int r = u >> 3, cb = (u & 7) << 4;
            uint32_t so = SMEM_SWIZZLE_128B(r * 128 + cb);
            cp_async16(sb + 32768 + so, Bp + (size_t)r * 4096 + k0 + (cb >> 1));
        }
        CP_COMMIT();
    };

    load_chunk(0);
    load_chunk(1);

    const int lrow = lane & 15;
    const int lksel = (lane >> 4) << 4;

    for (int c = 0; c < nchunk; c++) {
        if (c + 1 < nchunk) { CP_WAIT(1); } else { CP_WAIT(0); }
        __syncthreads();
        const uint32_t sb = sbase + (c & 1) * AO_STAGE;
        const uint32_t a_h = sb, a_l = sb + 16384, b_s = sb + 32768;
#pragma unroll
        for (int ks = 0; ks < 4; ks++) {
            const int kb = ks * 32 + lksel;
            uint32_t ah[2][4], al[2][4], bf[4][2];
#pragma unroll
            for (int mf = 0; mf < 2; mf++) {
                int row = wm * 32 + mf * 16 + lrow;
                uint32_t so = SMEM_SWIZZLE_128B(row * 128 + kb);
                ldsm_x4(ah[mf], a_h + so);
                ldsm_x4(al[mf], a_l + so);
            }
#pragma unroll
            for (int g = 0; g < 2; g++) {
                int row = wn * 32 + g * 16 + lrow;
                uint32_t so = SMEM_SWIZZLE_128B(row * 128 + kb);
                uint32_t r[4];
                ldsm_x4(r, b_s + so);
                bf[g * 2][0] = r[0]; bf[g * 2][1] = r[2];
                bf[g * 2 + 1][0] = r[1]; bf[g * 2 + 1][1] = r[3];
            }
#pragma unroll
            for (int mf = 0; mf < 2; mf++)
#pragma unroll
                for (int nf = 0; nf < 4; nf++) mma16816(acc[mf][nf], ah[mf], bf[nf]);
#pragma unroll
            for (int mf = 0; mf < 2; mf++)
#pragma unroll
                for (int nf = 0; nf < 4; nf++) mma16816(acc[mf][nf], al[mf], bf[nf]);
        }
        __syncthreads();
        if (c + 2 < nchunk) load_chunk(c + 2);
    }

    float* P = g_agent_part + ((size_t)sp * BHN + bh) * (MAG * DHEAD);
#pragma unroll
    for (int mf = 0; mf < 2; mf++) {
        int r0 = wm * 32 + mf * 16 + (lane >> 2);
#pragma unroll
        for (int nf = 0; nf < 4; nf++) {
            int col = wn * 32 + nf * 8 + ((lane & 3) << 1);
            *reinterpret_cast<float2*>(&P[(size_t)r0 * 64 + col]) =
                make_float2(acc[mf][nf][0], acc[mf][nf][1]);
            *reinterpret_cast<float2*>(&P[(size_t)(r0 + 8) * 64 + col]) =
                make_float2(acc[mf][nf][2], acc[mf][nf][3]);
        }
    }
}

// ---------------- reduce split-K, emit agent^T single fp16 [bh,d,m] ----------------
__global__ __launch_bounds__(256) void reduce_agent_kernel() {
    int i = blockIdx.x * 256 + threadIdx.x;
    float sacc = 0.f;
#pragma unroll
    for (int k = 0; k < 4; k++) sacc += g_agent_part[(size_t)k * (BHN * MAG * DHEAD) + i];
    int bh = i >> 13;
    int rem = i & 8191;
    int m = rem >> 6, d = rem & 63;
    g_agt[((size_t)bh * 64 + d) * 128 + m] = __float2half_rn(sacc);
}

// ---------------- out_mid: C[n=128, d=64] = qam(h/l) @ agt(single)^T, mask, single fp16 mid ----------------
__global__ __launch_bounds__(256) void out_mid_tc_kernel() {
    extern __shared__ char dsm[];
    uint32_t sraw = smem_u32(dsm);
    uint32_t sbase = (sraw + 1023u) & ~1023u;

    const int tid = threadIdx.x;
    const int lane = tid & 31;
    const int wid = tid >> 5;
    const int wm = wid >> 1, wn = wid & 1;
    const int bh = blockIdx.y;
    const int b = bh >> 4, h = bh & 15;
    const int bm = blockIdx.x * 128;

    const __half* Ahp = g_qamh + (size_t)bh * NSEQ * MAG;
    const __half* Alp = g_qaml + (size_t)bh * NSEQ * MAG;
    const __half* Bp  = g_agt + (size_t)bh * DHEAD * MAG;

#pragma unroll
    for (int c = 0; c < 2; c++) {
        const uint32_t sb = sbase + c * AO_STAGE;
        const int k0 = c << 6;
#pragma unroll
        for (int i = 0; i < 4; i++) {
            int u = tid + i * 256;
            int r = u >> 3, cb = (u & 7) << 4;
            uint32_t so = SMEM_SWIZZLE_128B(r * 128 + cb);
            cp_async16(sb + so,         Ahp + (size_t)(bm + r) * 128 + k0 + (cb >> 1));
            cp_async16(sb + 16384 + so, Alp + (size_t)(bm + r) * 128 + k0 + (cb >> 1));
        }
#pragma unroll
        for (int i = 0; i < 2; i++) {
            int u = tid + i * 256;
            int r = u >> 3, cb = (u & 7) << 4;
            uint32_t so = SMEM_SWIZZLE_128B(r * 128 + cb);
            cp_async16(sb + 32768 + so, Bp + (size_t)r * 128 + k0 + (cb >> 1));
        }
        CP_COMMIT();
    }
    CP_WAIT(0);
    __syncthreads();

    float acc[2][4][4];
#pragma unroll
    for (int i = 0; i < 2; i++)
#pragma unroll
        for (int j = 0; j < 4; j++)
#pragma unroll
            for (int v = 0; v < 4; v++) acc[i][j][v] = 0.f;

    const int lrow = lane & 15;
    const int lksel = (lane >> 4) << 4;
#pragma unroll
    for (int c = 0; c < 2; c++) {
        const uint32_t sb = sbase + c * AO_STAGE;
        const uint32_t a_h = sb, a_l = sb + 16384, b_s = sb + 32768;
#pragma unroll
        for (int ks = 0; ks < 4; ks++) {
            const int kb = ks * 32 + lksel;
            uint32_t ah[2][4], al[2][4], bf[4][2];
#pragma unroll
            for (int mf = 0; mf < 2; mf++) {
                int row = wm * 32 + mf * 16 + lrow;
                uint32_t so = SMEM_SWIZZLE_128B(row * 128 + kb);
                ldsm_x4(ah[mf], a_h + so);
                ldsm_x4(al[mf], a_l + so);
            }
#pragma unroll
            for (int g = 0; g < 2; g++) {
                int row = wn * 32 + g * 16 + lrow;
                uint32_t so = SMEM_SWIZZLE_128B(row * 128 + kb);
                uint32_t r[4];
                ldsm_x4(r, b_s + so);
                bf[g * 2][0] = r[0]; bf[g * 2][1] = r[2];
                bf[g * 2 + 1][0] = r[1]; bf[g * 2 + 1][1] = r[3];
            }
#pragma unroll
            for (int mf = 0; mf < 2; mf++)
#pragma unroll
                for (int nf = 0; nf < 4; nf++) mma16816(acc[mf][nf], ah[mf], bf[nf]);
#pragma unroll
            for (int mf = 0; mf < 2; mf++)
#pragma unroll
                for (int nf = 0; nf < 4; nf++) mma16816(acc[mf][nf], al[mf], bf[nf]);
        }
    }

#pragma unroll
    for (int mf = 0; mf < 2; mf++) {
        int r0 = wm * 32 + mf * 16 + (lane >> 2);
#pragma unroll
        for (int nf = 0; nf < 4; nf++) {
            int col = wn * 32 + nf * 8 + ((lane & 3) << 1);
#pragma unroll
            for (int rr = 0; rr < 2; rr++) {
                int rn = bm + r0 + rr * 8;
                float mv = g_maskf[b * NSEQ + rn];
                float v0 = acc[mf][nf][rr * 2] * mv, v1 = acc[mf][nf][rr * 2 + 1] * mv;
                size_t o = ((size_t)b * NSEQ + rn) * DIMX + h * 64 + col;
                *reinterpret_cast<__half2*>(&g_mid[o]) =
                    __halves2half2(__float2half_rn(v0), __float2half_rn(v1));
            }
        }
    }
}

// ---------------- launcher ----------------
extern "C" void kernel_launch(void* const* d_in, const int* in_sizes, int n_in,
                              void* d_out, int out_size) {
    const float* x     = (const float*)d_in[0];
    const void*  mask  = d_in[1];
    const float* Wqkv  = (const float*)d_in[2];
    const float* agent = (const float*)d_in[3];
    const float* Wqa   = (const float*)d_in[4];
    const float* Wak   = (const float*)d_in[5];
    const float* Wout  = (const float*)d_in[6];
    float* out = (float*)d_out;
    (void)in_sizes; (void)n_in; (void)out_size;

    cudaFuncSetAttribute(gemm_mma_kernel<0>, cudaFuncAttributeMaxDynamicSharedMemorySize, GT_SMEM);
    cudaFuncSetAttribute(gemm_mma_kernel<1>, cudaFuncAttributeMaxDynamicSharedMemorySize, GT_SMEM);
    cudaFuncSetAttribute(qa_sim_tc_kernel, cudaFuncAttributeMaxDynamicSharedMemorySize, QSIM_SMEM);
    cudaFuncSetAttribute(ak_sim_tc_kernel, cudaFuncAttributeMaxDynamicSharedMemorySize, AKSIM_SMEM);
    cudaFuncSetAttribute(agent_out_tc_kernel, cudaFuncAttributeMaxDynamicSharedMemorySize, AO_SMEM);
    cudaFuncSetAttribute(out_mid_tc_kernel, cudaFuncAttributeMaxDynamicSharedMemorySize, AO_SMEM);

    __half *x16, *wq, *wo, *mid;
    cudaGetSymbolAddress((void**)&x16, g_x16);
    cudaGetSymbolAddress((void**)&wq,  g_wqkv);
    cudaGetSymbolAddress((void**)&wo,  g_wout);
    cudaGetSymbolAddress((void**)&mid, g_mid);

    mask_expand_kernel<<<1, 1024>>>(mask);
    conv_x_kernel<<<(NB * NSEQ * DIMX / 4 + 255) / 256, 256>>>(x, x16, NB * NSEQ * DIMX / 4);
    conv_wt_kernel<<<dim3(96, 32), 256>>>(Wqkv, wq, 1024, 3072);
    conv_wt_kernel<<<dim3(32, 32), 256>>>(Wout, wo, 1024, 1024);
    conv_agent_kernel<<<(HEADS * MAG * DHEAD / 4 + 255) / 256, 256>>>(agent);

    gemm_mma_kernel<1><<<dim3(24, 128), 512, GT_SMEM>>>(x16, wq, nullptr, 1024, 3072);

    qa_sim_tc_kernel<<<dim3(32, 64), 256, QSIM_SMEM>>>();
    ak_sim_tc_kernel<<<dim3(32, 64), 256, AKSIM_SMEM>>>();
    ak_stats_kernel<<<BHN * MAG, 256>>>();
    mix_heads_kernel<<<8192, 256>>>(Wqa);
    mix_ak_exp_kernel<<<8192, 256>>>(Wak);
    agent_out_tc_kernel<<<dim3(4, 64), 256, AO_SMEM>>>();
    reduce_agent_kernel<<<(BHN * MAG * DHEAD) / 256, 256>>>();
    out_mid_tc_kernel<<<dim3(32, 64), 256, AO_SMEM>>>();

    gemm_mma_kernel<0><<<dim3(8, 128), 512, GT_SMEM>>>(mid, wo, out, 1024, 1024);
}

// round 15
// speedup vs baseline: 3.6546x; 1.1065x over previous
#include <cuda_runtime.h>
#include <cuda_fp16.h>
#include <stdint.h>
#include <float.h>

// ---------------- problem constants ----------------
#define NB    4
#define NSEQ  4096
#define DIMX  1024
#define HEADS 16
#define DHEAD 64
#define MAG   128
#define BHN   (NB * HEADS)
#define SCALE 0.125f
#define HNEG  -65504.f

// ---------------- scratch (device globals; no allocation) ----------------
__device__ float g_agent_part[4 * BHN * MAG * DHEAD];  // split-K partials
__device__ float g_maskf[NB * NSEQ];
__device__ float2 g_akstat[BHN * MAG];

// fp16 operands / intermediates (all single precision fp16)
__device__ __half g_x16[NB * NSEQ * DIMX];
__device__ __half g_wqkv[3 * DIMX * DIMX];             // Wqkv^T
__device__ __half g_wout[DIMX * DIMX];                 // Wout^T
__device__ __half g_q1[BHN * NSEQ * DHEAD];            // q [bh,n,d]
__device__ __half g_k1[BHN * NSEQ * DHEAD];            // k [bh,n,d]
__device__ __half g_vt[BHN * DHEAD * NSEQ];            // v^T [bh,d,n]
__device__ __half g_a1[HEADS * MAG * DHEAD];           // agent*SCALE [h,m,d]
__device__ __half g_qa16[NB * HEADS * NSEQ * MAG];     // qa attn (softmaxed) [bh,n,m]
__device__ __half g_ak16[NB * HEADS * MAG * NSEQ];     // ak logits (masked) [bh,m,n]
__device__ __half g_qam[NB * HEADS * NSEQ * MAG];      // mixed qa [bh,n,m]
__device__ __half g_akm[NB * HEADS * MAG * NSEQ];      // mixed ak attn [bh,m,n]
__device__ __half g_agt[BHN * DHEAD * MAG];            // agent_out^T [bh,d,m]
__device__ __half g_mid[NB * NSEQ * DIMX];             // mid

// ---------------- PTX helpers ----------------
__device__ __forceinline__ uint32_t smem_u32(const void* p) {
    uint32_t a;
    asm("{ .reg .u64 t; cvta.to.shared.u64 t, %1; cvt.u32.u64 %0, t; }" : "=r"(a) : "l"(p));
    return a;
}
#define SMEM_SWIZZLE_128B(o) ((o) ^ (((o) >> 3) & 0x70))

__device__ __forceinline__ void cp_async16(uint32_t sa, const void* g) {
    asm volatile("cp.async.cg.shared.global [%0], [%1], 16;" :: "r"(sa), "l"(g));
}
#define CP_COMMIT() asm volatile("cp.async.commit_group;" ::: "memory")
#define CP_WAIT(n)  asm volatile("cp.async.wait_group %0;" :: "n"(n) : "memory")

__device__ __forceinline__ void ldsm_x4(uint32_t* r, uint32_t a) {
    asm volatile("ldmatrix.sync.aligned.m8n8.x4.shared.b16 {%0,%1,%2,%3}, [%4];"
                 : "=r"(r[0]), "=r"(r[1]), "=r"(r[2]), "=r"(r[3]) : "r"(a));
}
__device__ __forceinline__ void mma16816(float* c, const uint32_t* a, const uint32_t* b) {
    asm volatile("mma.sync.aligned.m16n8k16.row.col.f32.f16.f16.f32 "
                 "{%0,%1,%2,%3}, {%4,%5,%6,%7}, {%8,%9}, {%0,%1,%2,%3};"
                 : "+f"(c[0]), "+f"(c[1]), "+f"(c[2]), "+f"(c[3])
                 : "r"(a[0]), "r"(a[1]), "r"(a[2]), "r"(a[3]), "r"(b[0]), "r"(b[1]));
}

__device__ __forceinline__ float warp_max(float v) {
#pragma unroll
    for (int o = 16; o > 0; o >>= 1) v = fmaxf(v, __shfl_xor_sync(0xffffffffu, v, o));
    return v;
}
__device__ __forceinline__ float warp_sum(float v) {
#pragma unroll
    for (int o = 16; o > 0; o >>= 1) v += __shfl_xor_sync(0xffffffffu, v, o);
    return v;
}

// ---------------- mask dtype detection + expansion ----------------
__global__ void mask_expand_kernel(const void* __restrict__ mraw) {
    __shared__ int s_weird, s_off;
    const unsigned char* mb = (const unsigned char*)mraw;
    if (threadIdx.x == 0) { s_weird = 0; s_off = 0; }
    __syncthreads();
    int weird = 0, off = 0;
    for (int i = threadIdx.x; i < NB * NSEQ; i += blockDim.x) {
        unsigned char c = mb[i];
        if (c > 1) weird = 1;
        if (c != 0 && (i & 3)) off = 1;
    }
    if (weird) atomicOr(&s_weird, 1);
    if (off)   atomicOr(&s_off, 1);
    __syncthreads();
    int mode = s_weird ? 2 : (s_off ? 0 : 1);
    for (int i = threadIdx.x; i < NB * NSEQ; i += blockDim.x) {
        float v;
        if (mode == 0)      v = mb[i] ? 1.f : 0.f;
        else if (mode == 1) v = ((const int*)mraw)[i] ? 1.f : 0.f;
        else                v = (((const float*)mraw)[i] != 0.f) ? 1.f : 0.f;
        g_maskf[i] = v;
    }
}

// ---------------- fp32 -> fp16 (elementwise) ----------------
__global__ __launch_bounds__(256) void conv_x_kernel(const float* __restrict__ src,
                                                     __half* __restrict__ dst, int n4) {
    int i = blockIdx.x * 256 + threadIdx.x;
    if (i >= n4) return;
    float4 v = reinterpret_cast<const float4*>(src)[i];
    reinterpret_cast<__half2*>(dst)[i * 2] =
        __halves2half2(__float2half_rn(v.x), __float2half_rn(v.y));
    reinterpret_cast<__half2*>(dst)[i * 2 + 1] =
        __halves2half2(__float2half_rn(v.z), __float2half_rn(v.w));
}

// ---------------- agent tokens: scale + fp16 ----------------
__global__ __launch_bounds__(256) void conv_agent_kernel(const float* __restrict__ src) {
    int i = blockIdx.x * 256 + threadIdx.x;
    if (i >= HEADS * MAG * DHEAD / 4) return;
    float4 v = reinterpret_cast<const float4*>(src)[i];
    reinterpret_cast<__half2*>(g_a1)[i * 2] =
        __halves2half2(__float2half_rn(v.x * SCALE), __float2half_rn(v.y * SCALE));
    reinterpret_cast<__half2*>(g_a1)[i * 2 + 1] =
        __halves2half2(__float2half_rn(v.z * SCALE), __float2half_rn(v.w * SCALE));
}

// ---------------- W[K,N] -> W^T[N,K] fp16 ----------------
__global__ __launch_bounds__(256) void conv_wt_kernel(const float* __restrict__ W,
                                                      __half* __restrict__ T,
                                                      int K, int N) {
    __shared__ float t[32][33];
    int bx = blockIdx.x * 32;
    int by = blockIdx.y * 32;
    int x = threadIdx.x & 31, y0 = threadIdx.x >> 5;
#pragma unroll
    for (int y = y0; y < 32; y += 8) t[y][x] = W[(size_t)(by + y) * N + bx + x];
    __syncthreads();
#pragma unroll
    for (int y = y0; y < 32; y += 8) {
        T[(size_t)(bx + y) * K + by + x] = __float2half_rn(t[x][y]);
    }
}

// ---------------- big mma GEMM: fp16, 128x128 tile, BK=64, 2-stage, 512 threads ----------------
#define GT_TILE  16384
#define GT_STAGE (2 * GT_TILE)
#define GT_SMEM  (1024 + 2 * GT_STAGE)   // 66560

template <int MODE>   // 0: fp32 out ; 1: qkv scatter (q, k, v^T all single fp16)
__global__ __launch_bounds__(512, 1) void gemm_mma_kernel(
    const __half* __restrict__ A, const __half* __restrict__ B,
    float* __restrict__ out, int Kdim, int Nout) {
    extern __shared__ char dsm[];
    uint32_t sraw = smem_u32(dsm);
    uint32_t sbase = (sraw + 1023u) & ~1023u;

    const int tid = threadIdx.x;
    const int lane = tid & 31;
    const int wid = tid >> 5;
    const int wm = wid >> 2;
    const int wn = wid & 3;
    const int bm = blockIdx.y * 128;
    const int bn = blockIdx.x * 128;

    float acc[2][4][4];
#pragma unroll
    for (int i = 0; i < 2; i++)
#pragma unroll
        for (int j = 0; j < 4; j++)
#pragma unroll
            for (int v = 0; v < 4; v++) acc[i][j][v] = 0.f;

    const int nchunk = Kdim >> 6;
    const int lr  = tid >> 3;
    const int lc  = (tid & 7) << 4;

    auto load_chunk = [&](int c) {
        const int buf = c & 1;
        const int k0 = c << 6;
        const uint32_t sb = sbase + buf * GT_STAGE;
#pragma unroll
        for (int i = 0; i < 2; i++) {
            int r = lr + i * 64;
            uint32_t so = SMEM_SWIZZLE_128B(r * 128 + lc);
            cp_async16(sb + so,           A + (size_t)(bm + r) * Kdim + k0 + (lc >> 1));
            cp_async16(sb + GT_TILE + so, B + (size_t)(bn + r) * Kdim + k0 + (lc >> 1));
        }
        CP_COMMIT();
    };

    load_chunk(0);
    if (nchunk > 1) load_chunk(1);

    const int lrow = lane & 15;
    const int lksel = (lane >> 4) << 4;

    for (int c = 0; c < nchunk; c++) {
        if (c + 1 < nchunk) { CP_WAIT(1); } else { CP_WAIT(0); }
        __syncthreads();
        const uint32_t sb = sbase + (c & 1) * GT_STAGE;
        const uint32_t a_s = sb, b_s = sb + GT_TILE;
#pragma unroll
        for (int ks = 0; ks < 4; ks++) {
            const int kb = ks * 32 + lksel;
            uint32_t af[2][4], bf[4][2];
#pragma unroll
            for (int mf = 0; mf < 2; mf++) {
                int row = wm * 32 + mf * 16 + lrow;
                ldsm_x4(af[mf], a_s + SMEM_SWIZZLE_128B(row * 128 + kb));
            }
#pragma unroll
            for (int g = 0; g < 2; g++) {
                int row = wn * 32 + g * 16 + lrow;
                uint32_t r[4];
                ldsm_x4(r, b_s + SMEM_SWIZZLE_128B(row * 128 + kb));
                bf[g * 2][0] = r[0]; bf[g * 2][1] = r[2];
                bf[g * 2 + 1][0] = r[1]; bf[g * 2 + 1][1] = r[3];
            }
#pragma unroll
            for (int mf = 0; mf < 2; mf++)
#pragma unroll
                for (int nf = 0; nf < 4; nf++) mma16816(acc[mf][nf], af[mf], bf[nf]);
        }
        __syncthreads();
        if (c + 2 < nchunk) load_chunk(c + 2);
    }

#pragma unroll
    for (int mf = 0; mf < 2; mf++) {
        int r0 = bm + wm * 32 + mf * 16 + (lane >> 2);
#pragma unroll
        for (int nf = 0; nf < 4; nf++) {
            int col = bn + wn * 32 + nf * 8 + ((lane & 3) << 1);
            if (MODE == 0) {
                float* p0 = &out[(size_t)r0 * Nout + col];
                float* p1 = &out[(size_t)(r0 + 8) * Nout + col];
                *reinterpret_cast<float2*>(p0) = make_float2(acc[mf][nf][0], acc[mf][nf][1]);
                *reinterpret_cast<float2*>(p1) = make_float2(acc[mf][nf][2], acc[mf][nf][3]);
            } else {
                const int which = col >> 10;
                const int hh = (col >> 6) & 15;
                const int d0 = col & 63;
#pragma unroll
                for (int rr = 0; rr < 2; rr++) {
                    int r = r0 + rr * 8;
                    float v0 = acc[mf][nf][rr * 2], v1 = acc[mf][nf][rr * 2 + 1];
                    int b = r >> 12, n = r & 4095;
                    int bhn = b * 16 + hh;
                    if (which == 0) {
                        size_t o = ((size_t)bhn * 4096 + n) * 64 + d0;
                        *reinterpret_cast<__half2*>(&g_q1[o]) =
                            __halves2half2(__float2half_rn(v0), __float2half_rn(v1));
                    } else if (which == 1) {
                        size_t o = ((size_t)bhn * 4096 + n) * 64 + d0;
                        *reinterpret_cast<__half2*>(&g_k1[o]) =
                            __halves2half2(__float2half_rn(v0), __float2half_rn(v1));
                    } else {
                        size_t o0 = ((size_t)bhn * 64 + d0) * 4096 + n;
                        size_t o1 = ((size_t)bhn * 64 + d0 + 1) * 4096 + n;
                        g_vt[o0] = __float2half_rn(v0);
                        g_vt[o1] = __float2half_rn(v1);
                    }
                }
            }
        }
    }
}

// ================= mid-section tensor kernels (single-pass fp16) =================

// ---------------- qa_sim + fused softmax over m -> fp16 qa ----------------
// C[n=128, m=128] = q[128,64] @ a[128,64]^T
#define QSIM_SMEM (1024 + 68608)
__global__ __launch_bounds__(256) void qa_sim_tc_kernel() {
    extern __shared__ char dsm[];
    uint32_t sraw = smem_u32(dsm);
    uint32_t sbase = (sraw + 1023u) & ~1023u;
    float* Cs = reinterpret_cast<float*>(dsm + (sbase - sraw));

    const int tid = threadIdx.x;
    const int lane = tid & 31;
    const int wid = tid >> 5;
    const int wm = wid >> 2, wn = wid & 3;
    const int bh = blockIdx.y;
    const int h = bh & 15;
    const int bm = blockIdx.x * 128;

    const __half* Ap = g_q1 + (size_t)bh * NSEQ * DHEAD;
    const __half* Bp = g_a1 + (size_t)h * MAG * DHEAD;

#pragma unroll
    for (int i = 0; i < 4; i++) {
        int u = tid + i * 256;
        int r = u >> 3, cb = (u & 7) << 4;
        uint32_t so = SMEM_SWIZZLE_128B(r * 128 + cb);
        cp_async16(sbase + so,         Ap + (size_t)(bm + r) * 64 + (cb >> 1));
        cp_async16(sbase + 16384 + so, Bp + (size_t)r * 64 + (cb >> 1));
    }
    CP_COMMIT(); CP_WAIT(0);
    __syncthreads();

    float acc[4][4][4];
#pragma unroll
    for (int i = 0; i < 4; i++)
#pragma unroll
        for (int j = 0; j < 4; j++)
#pragma unroll
            for (int v = 0; v < 4; v++) acc[i][j][v] = 0.f;

    const int lrow = lane & 15;
    const int lksel = (lane >> 4) << 4;
    const uint32_t a_s = sbase, b_s = sbase + 16384;
#pragma unroll
    for (int ks = 0; ks < 4; ks++) {
        const int kb = ks * 32 + lksel;
        uint32_t af[4][4], bf[4][2];
#pragma unroll
        for (int mf = 0; mf < 4; mf++) {
            int row = wm * 64 + mf * 16 + lrow;
            ldsm_x4(af[mf], a_s + SMEM_SWIZZLE_128B(row * 128 + kb));
        }
#pragma unroll
        for (int g = 0; g < 2; g++) {
            int row = wn * 32 + g * 16 + lrow;
            uint32_t r[4];
            ldsm_x4(r, b_s + SMEM_SWIZZLE_128B(row * 128 + kb));
            bf[g * 2][0] = r[0]; bf[g * 2][1] = r[2];
            bf[g * 2 + 1][0] = r[1]; bf[g * 2 + 1][1] = r[3];
        }
#pragma unroll
        for (int mf = 0; mf < 4; mf++)
#pragma unroll
            for (int nf = 0; nf < 4; nf++) mma16816(acc[mf][nf], af[mf], bf[nf]);
    }
    __syncthreads();

#pragma unroll
    for (int mf = 0; mf < 4; mf++) {
        int rl = wm * 64 + mf * 16 + (lane >> 2);
#pragma unroll
        for (int nf = 0; nf < 4; nf++) {
            int col = wn * 32 + nf * 8 + ((lane & 3) << 1);
            Cs[rl * 132 + col] = acc[mf][nf][0];
            Cs[rl * 132 + col + 1] = acc[mf][nf][1];
            Cs[(rl + 8) * 132 + col] = acc[mf][nf][2];
            Cs[(rl + 8) * 132 + col + 1] = acc[mf][nf][3];
        }
    }
    __syncthreads();

#pragma unroll
    for (int i = 0; i < 16; i++) {
        int row = wid * 16 + i;
        float4 v = *reinterpret_cast<float4*>(&Cs[row * 132 + lane * 4]);
        float mx = warp_max(fmaxf(fmaxf(v.x, v.y), fmaxf(v.z, v.w)));
        v.x = __expf(v.x - mx); v.y = __expf(v.y - mx);
        v.z = __expf(v.z - mx); v.w = __expf(v.w - mx);
        float sm = warp_sum(v.x + v.y + v.z + v.w);
        float inv = 1.f / sm;
        __half2 o0 = __halves2half2(__float2half_rn(v.x * inv), __float2half_rn(v.y * inv));
        __half2 o1 = __halves2half2(__float2half_rn(v.z * inv), __float2half_rn(v.w * inv));
        __half2* p = reinterpret_cast<__half2*>(
            &g_qa16[((size_t)bh * NSEQ + bm + row) * MAG + lane * 4]);
        p[0] = o0; p[1] = o1;
    }
}

// ---------------- ak_sim: C[m=128, n-tile=128] = a @ k^T + mask -> fp16 logits ----------------
#define AKSIM_SMEM (1024 + 32768)
__global__ __launch_bounds__(256) void ak_sim_tc_kernel() {
    extern __shared__ char dsm[];
    uint32_t sraw = smem_u32(dsm);
    uint32_t sbase = (sraw + 1023u) & ~1023u;

    const int tid = threadIdx.x;
    const int lane = tid & 31;
    const int wid = tid >> 5;
    const int wm = wid >> 2, wn = wid & 3;
    const int bh = blockIdx.y;
    const int b = bh >> 4, h = bh & 15;
    const int bn = blockIdx.x * 128;

    const __half* Ap = g_a1 + (size_t)h * MAG * DHEAD;
    const __half* Bp = g_k1 + (size_t)bh * NSEQ * DHEAD;

#pragma unroll
    for (int i = 0; i < 4; i++) {
        int u = tid + i * 256;
        int r = u >> 3, cb = (u & 7) << 4;
        uint32_t so = SMEM_SWIZZLE_128B(r * 128 + cb);
        cp_async16(sbase + so,         Ap + (size_t)r * 64 + (cb >> 1));
        cp_async16(sbase + 16384 + so, Bp + (size_t)(bn + r) * 64 + (cb >> 1));
    }
    CP_COMMIT(); CP_WAIT(0);
    __syncthreads();

    float acc[4][4][4];
#pragma unroll
    for (int i = 0; i < 4; i++)
#pragma unroll
        for (int j = 0; j < 4; j++)
#pragma unroll
            for (int v = 0; v < 4; v++) acc[i][j][v] = 0.f;

    const int lrow = lane & 15;
    const int lksel = (lane >> 4) << 4;
    const uint32_t a_s = sbase, b_s = sbase + 16384;
#pragma unroll
    for (int ks = 0; ks < 4; ks++) {
        const int kb = ks * 32 + lksel;
        uint32_t af[4][4], bf[4][2];
#pragma unroll
        for (int mf = 0; mf < 4; mf++) {
            int row = wm * 64 + mf * 16 + lrow;
            ldsm_x4(af[mf], a_s + SMEM_SWIZZLE_128B(row * 128 + kb));
        }
#pragma unroll
        for (int g = 0; g < 2; g++) {
            int row = wn * 32 + g * 16 + lrow;
            uint32_t r[4];
            ldsm_x4(r, b_s + SMEM_SWIZZLE_128B(row * 128 + kb));
            bf[g * 2][0] = r[0]; bf[g * 2][1] = r[2];
            bf[g * 2 + 1][0] = r[1]; bf[g * 2 + 1][1] = r[3];
        }
#pragma unroll
        for (int mf = 0; mf < 4; mf++)
#pragma unroll
            for (int nf = 0; nf < 4; nf++) mma16816(acc[mf][nf], af[mf], bf[nf]);
    }

#pragma unroll
    for (int mf = 0; mf < 4; mf++) {
        int r0 = wm * 64 + mf * 16 + (lane >> 2);
#pragma unroll
        for (int nf = 0; nf < 4; nf++) {
            int col = bn + wn * 32 + nf * 8 + ((lane & 3) << 1);
            float mv0 = g_maskf[b * NSEQ + col];
            float mv1 = g_maskf[b * NSEQ + col + 1];
            float a0 = mv0 != 0.f ? acc[mf][nf][0] : HNEG;
            float a1 = mv1 != 0.f ? acc[mf][nf][1] : HNEG;
            float a2 = mv0 != 0.f ? acc[mf][nf][2] : HNEG;
            float a3 = mv1 != 0.f ? acc[mf][nf][3] : HNEG;
            *reinterpret_cast<__half2*>(&g_ak16[((size_t)bh * MAG + r0) * NSEQ + col]) =
                __halves2half2(__float2half_rn(a0), __float2half_rn(a1));
            *reinterpret_cast<__half2*>(&g_ak16[((size_t)bh * MAG + r0 + 8) * NSEQ + col]) =
                __halves2half2(__float2half_rn(a2), __float2half_rn(a3));
        }
    }
}

// ---------------- ak row stats (fp16 input) ----------------
__global__ __launch_bounds__(256) void ak_stats_kernel() {
    const int row = blockIdx.x;
    const int t = threadIdx.x;
    const __half* p = g_ak16 + (size_t)row * NSEQ;
    float v[16];
    float mx = -FLT_MAX;
#pragma unroll
    for (int i = 0; i < 2; i++) {
        uint4 raw = *reinterpret_cast<const uint4*>(&p[t * 16 + i * 8]);
        const __half2* h2 = reinterpret_cast<const __half2*>(&raw);
#pragma unroll
        for (int j = 0; j < 4; j++) {
            float2 f = __half22float2(h2[j]);
            v[i * 8 + j * 2] = f.x; v[i * 8 + j * 2 + 1] = f.y;
            mx = fmaxf(mx, fmaxf(f.x, f.y));
        }
    }
    __shared__ float red[8];
    int wid = t >> 5, lane = t & 31;
    float wm = warp_max(mx);
    if (lane == 0) red[wid] = wm;
    __syncthreads();
    float m = red[0];
#pragma unroll
    for (int i = 1; i < 8; i++) m = fmaxf(m, red[i]);
    float sacc = 0.f;
#pragma unroll
    for (int i = 0; i < 16; i++) sacc += __expf(v[i] - m);
    float ws = warp_sum(sacc);
    __syncthreads();
    if (lane == 0) red[wid] = ws;
    __syncthreads();
    if (t == 0) {
        float tot = 0.f;
#pragma unroll
        for (int i = 0; i < 8; i++) tot += red[i];
        g_akstat[row] = make_float2(m, 1.f / tot);
    }
}

// ---------------- fused exp-normalize + head mix (ak) -> fp16 ----------------
__global__ __launch_bounds__(256) void mix_ak_exp_kernel(const float* __restrict__ Wm) {
    __shared__ float Ws[256];
    if (threadIdx.x < 256) Ws[threadIdx.x] = Wm[threadIdx.x];
    __syncthreads();
    const size_t R = (size_t)MAG * NSEQ;
    size_t pos = (size_t)blockIdx.x * blockDim.x + threadIdx.x;
    if (pos >= (size_t)NB * R) return;
    size_t b = pos / R, r = pos % R;
    int m = (int)(r >> 12);
    const __half* p = g_ak16 + b * 16 * R + r;
    float x[16];
#pragma unroll
    for (int h = 0; h < 16; h++) {
        float2 st = g_akstat[(b * 16 + h) * MAG + m];
        x[h] = __expf(__half2float(p[h * R]) - st.x) * st.y;
    }
#pragma unroll
    for (int g = 0; g < 16; g++) {
        float sacc = 0.f;
#pragma unroll
        for (int h = 0; h < 16; h++) sacc = fmaf(Ws[g * 16 + h], x[h], sacc);
        g_akm[b * 16 * R + g * R + r] = __float2half_rn(sacc);
    }
}

// ---------------- talking heads (qa) -> fp16 ----------------
__global__ __launch_bounds__(256) void mix_heads_kernel(const float* __restrict__ Wm) {
    __shared__ float Ws[256];
    if (threadIdx.x < 256) Ws[threadIdx.x] = Wm[threadIdx.x];
    __syncthreads();
    const size_t R = (size_t)NSEQ * MAG;
    size_t pos = (size_t)blockIdx.x * blockDim.x + threadIdx.x;
    if (pos >= (size_t)NB * R) return;
    size_t b = pos / R, r = pos % R;
    const __half* p = g_qa16 + b * 16 * R + r;
    float x[16];
#pragma unroll
    for (int h = 0; h < 16; h++) x[h] = __half2float(p[h * R]);
#pragma unroll
    for (int g = 0; g < 16; g++) {
        float sacc = 0.f;
#pragma unroll
        for (int h = 0; h < 16; h++) sacc = fmaf(Ws[g * 16 + h], x[h], sacc);
        g_qam[b * 16 * R + g * R + r] = __float2half_rn(sacc);
    }
}

// ---------------- agent_out: C[m=128, d=64] = akm @ vT^T, split-K=4 ----------------
#define AO_STAGE 24576   // A 16K | B 8K
#define AO_SMEM  (1024 + 2 * AO_STAGE)
__global__ __launch_bounds__(256) void agent_out_tc_kernel() {
    extern __shared__ char dsm[];
    uint32_t sraw = smem_u32(dsm);
    uint32_t sbase = (sraw + 1023u) & ~1023u;

    const int tid = threadIdx.x;
    const int lane = tid & 31;
    const int wid = tid >> 5;
    const int wm = wid >> 1, wn = wid & 1;
    const int sp = blockIdx.x;
    const int bh = blockIdx.y;

    const __half* Ap = g_akm + (size_t)bh * MAG * NSEQ;
    const __half* Bp = g_vt + (size_t)bh * DHEAD * NSEQ;

    float acc[2][4][4];
#pragma unroll
    for (int i = 0; i < 2; i++)
#pragma unroll
        for (int j = 0; j < 4; j++)
#pragma unroll
            for (int v = 0; v < 4; v++) acc[i][j][v] = 0.f;

    const int kbase = sp * 1024;
    const int nchunk = 16;

    auto load_chunk = [&](int c) {
        const uint32_t sb = sbase + (c & 1) * AO_STAGE;
        const int k0 = kbase + (c << 6);
#pragma unroll
        for (int i = 0; i < 4; i++) {
            int u = tid + i * 256;
            int r = u >> 3, cb = (u & 7) << 4;
            uint32_t so = SMEM_SWIZZLE_128B(r * 128 + cb);
            cp_async16(sb + so, Ap + (size_t)r * 4096 + k0 + (cb >> 1));
        }
#pragma unroll
        for (int i = 0; i < 2; i++) {
            int u = tid + i * 256;
            int r = u >> 3, cb = (u & 7) << 4;
            uint32_t so = SMEM_SWIZZLE_128B(r * 128 + cb);
            cp_async16(sb + 16384 + so, Bp + (size_t)r * 4096 + k0 + (cb >> 1));
        }
        CP_COMMIT();
    };

    load_chunk(0);
    load_chunk(1);

    const int lrow = lane & 15;
    const int lksel = (lane >> 4) << 4;

    for (int c = 0; c < nchunk; c++) {
        if (c + 1 < nchunk) { CP_WAIT(1); } else { CP_WAIT(0); }
        __syncthreads();
        const uint32_t sb = sbase + (c & 1) * AO_STAGE;
        const uint32_t a_s = sb, b_s = sb + 16384;
#pragma unroll
        for (int ks = 0; ks < 4; ks++) {
            const int kb = ks * 32 + lksel;
            uint32_t af[2][4], bf[4][2];
#pragma unroll
            for (int mf = 0; mf < 2; mf++) {
                int row = wm * 32 + mf * 16 + lrow;
                ldsm_x4(af[mf], a_s + SMEM_SWIZZLE_128B(row * 128 + kb));
            }
#pragma unroll
            for (int g = 0; g < 2; g++) {
                int row = wn * 32 + g * 16 + lrow;
                uint32_t r[4];
                ldsm_x4(r, b_s + SMEM_SWIZZLE_128B(row * 128 + kb));
                bf[g * 2][0] = r[0]; bf[g * 2][1] = r[2];
                bf[g * 2 + 1][0] = r[1]; bf[g * 2 + 1][1] = r[3];
            }
#pragma unroll
            for (int mf = 0; mf < 2; mf++)
#pragma unroll
                for (int nf = 0; nf < 4; nf++) mma16816(acc[mf][nf], af[mf], bf[nf]);
        }
        __syncthreads();
        if (c + 2 < nchunk) load_chunk(c + 2);
    }

    float* P = g_agent_part + ((size_t)sp * BHN + bh) * (MAG * DHEAD);
#pragma unroll
    for (int mf = 0; mf < 2; mf++) {
        int r0 = wm * 32 + mf * 16 + (lane >> 2);
#pragma unroll
        for (int nf = 0; nf < 4; nf++) {
            int col = wn * 32 + nf * 8 + ((lane & 3) << 1);
            *reinterpret_cast<float2*>(&P[(size_t)r0 * 64 + col]) =
                make_float2(acc[mf][nf][0], acc[mf][nf][1]);
            *reinterpret_cast<float2*>(&P[(size_t)(r0 + 8) * 64 + col]) =
                make_float2(acc[mf][nf][2], acc[mf][nf][3]);
        }
    }
}

// ---------------- reduce split-K, emit agent^T fp16 [bh,d,m] ----------------
__global__ __launch_bounds__(256) void reduce_agent_kernel() {
    int i = blockIdx.x * 256 + threadIdx.x;
    float sacc = 0.f;
#pragma unroll
    for (int k = 0; k < 4; k++) sacc += g_agent_part[(size_t)k * (BHN * MAG * DHEAD) + i];
    int bh = i >> 13;
    int rem = i & 8191;
    int m = rem >> 6, d = rem & 63;
    g_agt[((size_t)bh * 64 + d) * 128 + m] = __float2half_rn(sacc);
}

// ---------------- out_mid: C[n=128, d=64] = qam @ agt^T, mask, fp16 mid ----------------
__global__ __launch_bounds__(256) void out_mid_tc_kernel() {
    extern __shared__ char dsm[];
    uint32_t sraw = smem_u32(dsm);
    uint32_t sbase = (sraw + 1023u) & ~1023u;

    const int tid = threadIdx.x;
    const int lane = tid & 31;
    const int wid = tid >> 5;
    const int wm = wid >> 1, wn = wid & 1;
    const int bh = blockIdx.y;
    const int b = bh >> 4, h = bh & 15;
    const int bm = blockIdx.x * 128;

    const __half* Ap = g_qam + (size_t)bh * NSEQ * MAG;
    const __half* Bp = g_agt + (size_t)bh * DHEAD * MAG;

#pragma unroll
    for (int c = 0; c < 2; c++) {
        const uint32_t sb = sbase + c * AO_STAGE;
        const int k0 = c << 6;
#pragma unroll
        for (int i = 0; i < 4; i++) {
            int u = tid + i * 256;
            int r = u >> 3, cb = (u & 7) << 4;
            uint32_t so = SMEM_SWIZZLE_128B(r * 128 + cb);
            cp_async16(sb + so, Ap + (size_t)(bm + r) * 128 + k0 + (cb >> 1));
        }
#pragma unroll
        for (int i = 0; i < 2; i++) {
            int u = tid + i * 256;
            int r = u >> 3, cb = (u & 7) << 4;
            uint32_t so = SMEM_SWIZZLE_128B(r * 128 + cb);
            cp_async16(sb + 16384 + so, Bp + (size_t)r * 128 + k0 + (cb >> 1));
        }
        CP_COMMIT();
    }
    CP_WAIT(0);
    __syncthreads();

    float acc[2][4][4];
#pragma unroll
    for (int i = 0; i < 2; i++)
#pragma unroll
        for (int j = 0; j < 4; j++)
#pragma unroll
            for (int v = 0; v < 4; v++) acc[i][j][v] = 0.f;

    const int lrow = lane & 15;
    const int lksel = (lane >> 4) << 4;
#pragma unroll
    for (int c = 0; c < 2; c++) {
        const uint32_t sb = sbase + c * AO_STAGE;
        const uint32_t a_s = sb, b_s = sb + 16384;
#pragma unroll
        for (int ks = 0; ks < 4; ks++) {
            const int kb = ks * 32 + lksel;
            uint32_t af[2][4], bf[4][2];
#pragma unroll
            for (int mf = 0; mf < 2; mf++) {
                int row = wm * 32 + mf * 16 + lrow;
                ldsm_x4(af[mf], a_s + SMEM_SWIZZLE_128B(row * 128 + kb));
            }
#pragma unroll
            for (int g = 0; g < 2; g++) {
                int row = wn * 32 + g * 16 + lrow;
                uint32_t r[4];
                ldsm_x4(r, b_s + SMEM_SWIZZLE_128B(row * 128 + kb));
                bf[g * 2][0] = r[0]; bf[g * 2][1] = r[2];
                bf[g * 2 + 1][0] = r[1]; bf[g * 2 + 1][1] = r[3];
            }
#pragma unroll
            for (int mf = 0; mf < 2; mf++)
#pragma unroll
                for (int nf = 0; nf < 4; nf++) mma16816(acc[mf][nf], af[mf], bf[nf]);
        }
    }

#pragma unroll
    for (int mf = 0; mf < 2; mf++) {
        int r0 = wm * 32 + mf * 16 + (lane >> 2);
#pragma unroll
        for (int nf = 0; nf < 4; nf++) {
            int col = wn * 32 + nf * 8 + ((lane & 3) << 1);
#pragma unroll
            for (int rr = 0; rr < 2; rr++) {
                int rn = bm + r0 + rr * 8;
                float mv = g_maskf[b * NSEQ + rn];
                float v0 = acc[mf][nf][rr * 2] * mv, v1 = acc[mf][nf][rr * 2 + 1] * mv;
                size_t o = ((size_t)b * NSEQ + rn) * DIMX + h * 64 + col;
                *reinterpret_cast<__half2*>(&g_mid[o]) =
                    __halves2half2(__float2half_rn(v0), __float2half_rn(v1));
            }
        }
    }
}

// ---------------- launcher ----------------
extern "C" void kernel_launch(void* const* d_in, const int* in_sizes, int n_in,
                              void* d_out, int out_size) {
    const float* x     = (const float*)d_in[0];
    const void*  mask  = d_in[1];
    const float* Wqkv  = (const float*)d_in[2];
    const float* agent = (const float*)d_in[3];
    const float* Wqa   = (const float*)d_in[4];
    const float* Wak   = (const float*)d_in[5];
    const float* Wout  = (const float*)d_in[6];
    float* out = (float*)d_out;
    (void)in_sizes; (void)n_in; (void)out_size;

    cudaFuncSetAttribute(gemm_mma_kernel<0>, cudaFuncAttributeMaxDynamicSharedMemorySize, GT_SMEM);
    cudaFuncSetAttribute(gemm_mma_kernel<1>, cudaFuncAttributeMaxDynamicSharedMemorySize, GT_SMEM);
    cudaFuncSetAttribute(qa_sim_tc_kernel, cudaFuncAttributeMaxDynamicSharedMemorySize, QSIM_SMEM);
    cudaFuncSetAttribute(ak_sim_tc_kernel, cudaFuncAttributeMaxDynamicSharedMemorySize, AKSIM_SMEM);
    cudaFuncSetAttribute(agent_out_tc_kernel, cudaFuncAttributeMaxDynamicSharedMemorySize, AO_SMEM);
    cudaFuncSetAttribute(out_mid_tc_kernel, cudaFuncAttributeMaxDynamicSharedMemorySize, AO_SMEM);

    __half *x16, *wq, *wo, *mid;
    cudaGetSymbolAddress((void**)&x16, g_x16);
    cudaGetSymbolAddress((void**)&wq,  g_wqkv);
    cudaGetSymbolAddress((void**)&wo,  g_wout);
    cudaGetSymbolAddress((void**)&mid, g_mid);

    mask_expand_kernel<<<1, 1024>>>(mask);
    conv_x_kernel<<<(NB * NSEQ * DIMX / 4 + 255) / 256, 256>>>(x, x16, NB * NSEQ * DIMX / 4);
    conv_wt_kernel<<<dim3(96, 32), 256>>>(Wqkv, wq, 1024, 3072);
    conv_wt_kernel<<<dim3(32, 32), 256>>>(Wout, wo, 1024, 1024);
    conv_agent_kernel<<<(HEADS * MAG * DHEAD / 4 + 255) / 256, 256>>>(agent);

    gemm_mma_kernel<1><<<dim3(24, 128), 512, GT_SMEM>>>(x16, wq, nullptr, 1024, 3072);

    qa_sim_tc_kernel<<<dim3(32, 64), 256, QSIM_SMEM>>>();
    ak_sim_tc_kernel<<<dim3(32, 64), 256, AKSIM_SMEM>>>();
    ak_stats_kernel<<<BHN * MAG, 256>>>();
    mix_heads_kernel<<<8192, 256>>>(Wqa);
    mix_ak_exp_kernel<<<8192, 256>>>(Wak);
    agent_out_tc_kernel<<<dim3(4, 64), 256, AO_SMEM>>>();
    reduce_agent_kernel<<<(BHN * MAG * DHEAD) / 256, 256>>>();
    out_mid_tc_kernel<<<dim3(32, 64), 256, AO_SMEM>>>();

    gemm_mma_kernel<0><<<dim3(8, 128), 512, GT_SMEM>>>(mid, wo, out, 1024, 1024);
}